// round 1
// baseline (speedup 1.0000x reference)
#include <cuda_runtime.h>
#include <math.h>

// ---------------------------------------------------------------------------
// Problem constants
//   B=2, N=9216, C=512, HEAD=8, d=64, SR=4, H=W=96 -> Nkv = 24*24 = 576
//   LoRA rank R=32, scaling = 4/32 = 0.125
// ---------------------------------------------------------------------------
#define SCALING 0.125f

// ---------------------------------------------------------------------------
// Scratch (static device globals; allocation inside kernel_launch is banned)
// ---------------------------------------------------------------------------
__device__ float g_q    [9437184];  // (B,N,C)    18432*512
__device__ float g_t1   [589824];   // (B*N, 32)
__device__ float g_xspre[589824];   // (B*576, 512) pre-LN
__device__ float g_xs   [589824];   // (B*576, 512)
__device__ float g_kv   [1179648];  // (B*576, 1024)
__device__ float g_t2   [36864];    // (B*576, 32)
__device__ float g_lv   [589824];   // (B*576, 512)  (already * SCALING)
__device__ float g_k    [589824];   // (B*H, 576, 64)
__device__ float g_v    [589824];   // (B*H, 576, 64)
__device__ float g_ctx  [9437184];  // (B,N,C)

// ---------------------------------------------------------------------------
// Generic tiled GEMM:  C[m,n] = scale * sum_k A[m,k]*B[n,k]  (+bias[n]) (+Cin)
// A: MxK row-major (lda), B: NxK row-major (ldb)  -> computes A @ B^T
// 64x64 tile, BK=16, 256 threads, 4x4 microkernel.
// ---------------------------------------------------------------------------
__global__ void gemm_abt(int M, int N, int K,
                         const float* __restrict__ A, int lda,
                         const float* __restrict__ Bm, int ldb,
                         const float* __restrict__ bias,
                         const float* __restrict__ Cin,
                         float scale,
                         float* __restrict__ C, int ldc)
{
    __shared__ float As[16 * 64];   // [k][m]
    __shared__ float Bs[16 * 64];   // [k][n]
    const int t  = threadIdx.x;
    const int ty = t >> 4, tx = t & 15;
    const int m0 = blockIdx.y * 64, n0 = blockIdx.x * 64;
    const int lr = t >> 2;            // 0..63
    const int lk = (t & 3) << 2;      // 0,4,8,12

    float acc[4][4];
#pragma unroll
    for (int i = 0; i < 4; i++)
#pragma unroll
        for (int j = 0; j < 4; j++) acc[i][j] = 0.f;

    const int gmL = m0 + lr;
    const int gnL = n0 + lr;

    for (int k0 = 0; k0 < K; k0 += 16) {
        float4 av = make_float4(0.f, 0.f, 0.f, 0.f);
        float4 bv = make_float4(0.f, 0.f, 0.f, 0.f);
        if (gmL < M) av = *(const float4*)(A  + (long)gmL * lda + k0 + lk);
        if (gnL < N) bv = *(const float4*)(Bm + (long)gnL * ldb + k0 + lk);
        __syncthreads();
        As[(lk + 0) * 64 + lr] = av.x; As[(lk + 1) * 64 + lr] = av.y;
        As[(lk + 2) * 64 + lr] = av.z; As[(lk + 3) * 64 + lr] = av.w;
        Bs[(lk + 0) * 64 + lr] = bv.x; Bs[(lk + 1) * 64 + lr] = bv.y;
        Bs[(lk + 2) * 64 + lr] = bv.z; Bs[(lk + 3) * 64 + lr] = bv.w;
        __syncthreads();
#pragma unroll
        for (int kk = 0; kk < 16; kk++) {
            float4 a4 = *(const float4*)(As + kk * 64 + ty * 4);
            float4 b4 = *(const float4*)(Bs + kk * 64 + tx * 4);
            float ar[4] = {a4.x, a4.y, a4.z, a4.w};
            float br[4] = {b4.x, b4.y, b4.z, b4.w};
#pragma unroll
            for (int i = 0; i < 4; i++)
#pragma unroll
                for (int j = 0; j < 4; j++)
                    acc[i][j] += ar[i] * br[j];
        }
    }

#pragma unroll
    for (int i = 0; i < 4; i++) {
        int gm = m0 + ty * 4 + i;
        if (gm >= M) continue;
#pragma unroll
        for (int j = 0; j < 4; j++) {
            int gn = n0 + tx * 4 + j;
            if (gn >= N) continue;
            float r = scale * acc[i][j];
            if (bias) r += bias[gn];
            if (Cin)  r += Cin[(long)gm * ldc + gn];
            C[(long)gm * ldc + gn] = r;
        }
    }
}

// ---------------------------------------------------------------------------
// Spatial-reduction conv as gathered GEMM:
//   out[m, co] = bias[co] + sum_{k<8192} im2col(x)[m,k] * w_sr[co, k]
//   m = b*576 + py*24 + px ; k = ci*16 + i*4 + j
//   im2col(x)[m,k] = x[b, (py*4+i)*96 + px*4 + j, ci]
// M=1152, N=512, K=8192.
// ---------------------------------------------------------------------------
__global__ void convsr_gemm(const float* __restrict__ x,
                            const float* __restrict__ w,
                            const float* __restrict__ bias,
                            float* __restrict__ out)
{
    __shared__ float As[16 * 64];
    __shared__ float Bs[16 * 64];
    const int t  = threadIdx.x;
    const int ty = t >> 4, tx = t & 15;
    const int m0 = blockIdx.y * 64, n0 = blockIdx.x * 64;
    const int lr = t >> 2;
    const int lk = (t & 3) << 2;

    // invariant per-thread A-gather geometry
    const int m  = m0 + lr;              // < 1152
    const int b  = m / 576;
    const int p  = m % 576;
    const int py = p / 24, px = p % 24;
    const int i  = lk >> 2;              // kernel row (lk in {0,4,8,12})
    const long xrow = (long)b * 9216 * 512
                    + (long)((py * 4 + i) * 96 + px * 4) * 512;
    const int gnL = n0 + lr;

    float acc[4][4];
#pragma unroll
    for (int a = 0; a < 4; a++)
#pragma unroll
        for (int c = 0; c < 4; c++) acc[a][c] = 0.f;

    for (int k0 = 0; k0 < 8192; k0 += 16) {
        const int ci = k0 >> 4;
        float a0 = x[xrow + ci];
        float a1 = x[xrow + 512 + ci];
        float a2 = x[xrow + 1024 + ci];
        float a3 = x[xrow + 1536 + ci];
        float4 bv = *(const float4*)(w + (long)gnL * 8192 + k0 + lk);
        __syncthreads();
        As[(lk + 0) * 64 + lr] = a0; As[(lk + 1) * 64 + lr] = a1;
        As[(lk + 2) * 64 + lr] = a2; As[(lk + 3) * 64 + lr] = a3;
        Bs[(lk + 0) * 64 + lr] = bv.x; Bs[(lk + 1) * 64 + lr] = bv.y;
        Bs[(lk + 2) * 64 + lr] = bv.z; Bs[(lk + 3) * 64 + lr] = bv.w;
        __syncthreads();
#pragma unroll
        for (int kk = 0; kk < 16; kk++) {
            float4 a4 = *(const float4*)(As + kk * 64 + ty * 4);
            float4 b4 = *(const float4*)(Bs + kk * 64 + tx * 4);
            float ar[4] = {a4.x, a4.y, a4.z, a4.w};
            float br[4] = {b4.x, b4.y, b4.z, b4.w};
#pragma unroll
            for (int ii = 0; ii < 4; ii++)
#pragma unroll
                for (int jj = 0; jj < 4; jj++)
                    acc[ii][jj] += ar[ii] * br[jj];
        }
    }

#pragma unroll
    for (int ii = 0; ii < 4; ii++) {
        int gm = m0 + ty * 4 + ii;
#pragma unroll
        for (int jj = 0; jj < 4; jj++) {
            int gn = n0 + tx * 4 + jj;
            out[(long)gm * 512 + gn] = acc[ii][jj] + bias[gn];
        }
    }
}

// ---------------------------------------------------------------------------
// LayerNorm over C=512 (biased var, eps 1e-5). One 128-thread block per row.
// ---------------------------------------------------------------------------
__global__ void layernorm_kernel(const float* __restrict__ in,
                                 const float* __restrict__ gam,
                                 const float* __restrict__ bet,
                                 float* __restrict__ out)
{
    const int row = blockIdx.x;
    const int t   = threadIdx.x;   // 0..127
    const float* x = in + (long)row * 512;
    float v0 = x[t], v1 = x[t + 128], v2 = x[t + 256], v3 = x[t + 384];
    float s  = v0 + v1 + v2 + v3;
    float s2 = v0 * v0 + v1 * v1 + v2 * v2 + v3 * v3;
#pragma unroll
    for (int o = 16; o > 0; o >>= 1) {
        s  += __shfl_xor_sync(0xffffffffu, s,  o);
        s2 += __shfl_xor_sync(0xffffffffu, s2, o);
    }
    __shared__ float ss[4], ss2[4];
    if ((t & 31) == 0) { ss[t >> 5] = s; ss2[t >> 5] = s2; }
    __syncthreads();
    s  = ss[0]  + ss[1]  + ss[2]  + ss[3];
    s2 = ss2[0] + ss2[1] + ss2[2] + ss2[3];
    const float mean = s * (1.f / 512.f);
    const float var  = s2 * (1.f / 512.f) - mean * mean;
    const float inv  = rsqrtf(var + 1e-5f);
    float* o = out + (long)row * 512;
    o[t]       = (v0 - mean) * inv * gam[t]       + bet[t];
    o[t + 128] = (v1 - mean) * inv * gam[t + 128] + bet[t + 128];
    o[t + 256] = (v2 - mean) * inv * gam[t + 256] + bet[t + 256];
    o[t + 384] = (v3 - mean) * inv * gam[t + 384] + bet[t + 384];
}

// ---------------------------------------------------------------------------
// Split kv buffer into k/v head layout; v gets the raw-reshape LoRA fixup:
//   k[b,h,m,dd] = kv[b,m, h*64+dd]
//   v[b,h,m,dd] = kv[b,m, 512 + h*64+dd] + lv_flat[b, h*36864 + m*64 + dd]
// ---------------------------------------------------------------------------
__global__ void build_kv(const float* __restrict__ kv,
                         const float* __restrict__ lv,
                         float* __restrict__ k, float* __restrict__ v)
{
    const int idx = blockIdx.x * 256 + threadIdx.x;   // < 589824
    const int dd = idx & 63;
    const int m  = (idx >> 6) % 576;
    const int bh = idx / 36864;       // 576*64
    const int h  = bh & 7, b = bh >> 3;
    const long base = (long)(b * 576 + m) * 1024 + h * 64 + dd;
    k[idx] = kv[base];
    v[idx] = kv[base + 512] + lv[(long)b * 294912 + h * 36864 + m * 64 + dd];
}

// ---------------------------------------------------------------------------
// Fused attention. One block = 64 queries of one (b,h); full 64x576 score
// matrix lives in shared memory (single-pass softmax, no online rescale).
//   grid = (144, 16), block = 256, dyn smem = 183552 B
// ---------------------------------------------------------------------------
#define SP 580           // S row pitch (floats), mult of 4, not mult of 32
#define KVP 68           // Q/K/V tile pitch
#define ATTN_SMEM ((64 * SP + 2 * 64 * KVP + 64) * 4)

__global__ void attn_kernel(const float* __restrict__ qb,   // (B,N,512)
                            const float* __restrict__ kb,   // (B*H,576,64)
                            const float* __restrict__ vb,   // (B*H,576,64)
                            float* __restrict__ ctx)        // (B,N,512)
{
    extern __shared__ float sm[];
    float* S      = sm;                  // 64 * SP
    float* Qt     = sm + 64 * SP;        // [dd][q], pitch KVP
    float* KV     = Qt + 64 * KVP;       // K: [dd][key] ; V: [key][dd]
    float* rowinv = KV + 64 * KVP;       // 64

    const int t  = threadIdx.x;
    const int ty = t >> 4, tx = t & 15;
    const int bh = blockIdx.y, b = bh >> 3, h = bh & 7;
    const int n0 = blockIdx.x * 64;

    // Load Q tile transposed: Qt[dd][q]
#pragma unroll
    for (int r = 0; r < 16; r++) {
        int idx = r * 256 + t;
        int q = idx >> 6, dd = idx & 63;
        Qt[dd * KVP + q] = qb[(long)(b * 9216 + n0 + q) * 512 + h * 64 + dd];
    }

    // ---- Phase 1: S = (Q K^T) * d^-0.5, chunked over 9 key tiles ----
    for (int ch = 0; ch < 9; ch++) {
        const int m0c = ch * 64;
        __syncthreads();
#pragma unroll
        for (int r = 0; r < 16; r++) {
            int idx = r * 256 + t;
            int key = idx >> 6, dd = idx & 63;
            KV[dd * KVP + key] = kb[(long)(bh * 576 + m0c + key) * 64 + dd];
        }
        __syncthreads();
        float acc[4][4];
#pragma unroll
        for (int i = 0; i < 4; i++)
#pragma unroll
            for (int j = 0; j < 4; j++) acc[i][j] = 0.f;
#pragma unroll 8
        for (int dd = 0; dd < 64; dd++) {
            float4 a4 = *(const float4*)(Qt + dd * KVP + ty * 4);
            float4 k4 = *(const float4*)(KV + dd * KVP + tx * 4);
            float ar[4] = {a4.x, a4.y, a4.z, a4.w};
            float kr[4] = {k4.x, k4.y, k4.z, k4.w};
#pragma unroll
            for (int i = 0; i < 4; i++)
#pragma unroll
                for (int j = 0; j < 4; j++)
                    acc[i][j] += ar[i] * kr[j];
        }
#pragma unroll
        for (int i = 0; i < 4; i++) {
            float4 sv = make_float4(acc[i][0] * 0.125f, acc[i][1] * 0.125f,
                                    acc[i][2] * 0.125f, acc[i][3] * 0.125f);
            *(float4*)(S + (ty * 4 + i) * SP + m0c + tx * 4) = sv;
        }
    }
    __syncthreads();

    // ---- Phase 2: softmax over 576 keys (4 threads per row) ----
    {
        const int row = t >> 2, part = t & 3;
        float mx = -1e30f;
        for (int s = 0; s < 144; s++)
            mx = fmaxf(mx, S[row * SP + 4 * s + part]);
        mx = fmaxf(mx, __shfl_xor_sync(0xffffffffu, mx, 1));
        mx = fmaxf(mx, __shfl_xor_sync(0xffffffffu, mx, 2));
        float sum = 0.f;
        for (int s = 0; s < 144; s++) {
            float e = __expf(S[row * SP + 4 * s + part] - mx);
            S[row * SP + 4 * s + part] = e;
            sum += e;
        }
        sum += __shfl_xor_sync(0xffffffffu, sum, 1);
        sum += __shfl_xor_sync(0xffffffffu, sum, 2);
        if (part == 0) rowinv[row] = 1.f / sum;
    }

    // ---- Phase 3: out = (P @ V) * rowinv ----
    float acc[4][4];
#pragma unroll
    for (int i = 0; i < 4; i++)
#pragma unroll
        for (int j = 0; j < 4; j++) acc[i][j] = 0.f;

    for (int ch = 0; ch < 9; ch++) {
        const int m0c = ch * 64;
        __syncthreads();   // S + rowinv ready; previous V reads done
#pragma unroll
        for (int r = 0; r < 16; r++) {
            int idx = r * 256 + t;
            int key = idx >> 6, dd = idx & 63;
            KV[key * KVP + dd] = vb[(long)(bh * 576 + m0c + key) * 64 + dd];
        }
        __syncthreads();
#pragma unroll 8
        for (int j = 0; j < 64; j++) {
            float4 v4 = *(const float4*)(KV + j * KVP + tx * 4);
#pragma unroll
            for (int i = 0; i < 4; i++) {
                float pv = S[(ty * 4 + i) * SP + m0c + j];
                acc[i][0] += pv * v4.x;
                acc[i][1] += pv * v4.y;
                acc[i][2] += pv * v4.z;
                acc[i][3] += pv * v4.w;
            }
        }
    }

#pragma unroll
    for (int i = 0; i < 4; i++) {
        const float inv = rowinv[ty * 4 + i];
        float4 o = make_float4(acc[i][0] * inv, acc[i][1] * inv,
                               acc[i][2] * inv, acc[i][3] * inv);
        *(float4*)(ctx + (long)(b * 9216 + n0 + ty * 4 + i) * 512
                        + h * 64 + tx * 4) = o;
    }
}

// ---------------------------------------------------------------------------
// Launch pipeline
// ---------------------------------------------------------------------------
extern "C" void kernel_launch(void* const* d_in, const int* in_sizes, int n_in,
                              void* d_out, int out_size)
{
    (void)in_sizes; (void)n_in; (void)out_size;
    const float* x      = (const float*)d_in[0];
    const float* w_q    = (const float*)d_in[1];
    const float* b_q    = (const float*)d_in[2];
    const float* w_kv   = (const float*)d_in[3];
    const float* b_kv   = (const float*)d_in[4];
    const float* w_proj = (const float*)d_in[5];
    const float* b_proj = (const float*)d_in[6];
    const float* w_sr   = (const float*)d_in[7];
    const float* b_sr   = (const float*)d_in[8];
    const float* ln_g   = (const float*)d_in[9];
    const float* ln_b   = (const float*)d_in[10];
    const float* lAq    = (const float*)d_in[11];
    const float* lBq    = (const float*)d_in[12];
    const float* lAv    = (const float*)d_in[13];
    const float* lBv    = (const float*)d_in[14];

    float *q, *t1, *xspre, *xs, *kv, *t2, *lv, *k, *v, *ctx;
    cudaGetSymbolAddress((void**)&q,     g_q);
    cudaGetSymbolAddress((void**)&t1,    g_t1);
    cudaGetSymbolAddress((void**)&xspre, g_xspre);
    cudaGetSymbolAddress((void**)&xs,    g_xs);
    cudaGetSymbolAddress((void**)&kv,    g_kv);
    cudaGetSymbolAddress((void**)&t2,    g_t2);
    cudaGetSymbolAddress((void**)&lv,    g_lv);
    cudaGetSymbolAddress((void**)&k,     g_k);
    cudaGetSymbolAddress((void**)&v,     g_v);
    cudaGetSymbolAddress((void**)&ctx,   g_ctx);

    dim3 blk(256);

    // q = X Wq^T + b_q
    gemm_abt<<<dim3(8, 288), blk>>>(18432, 512, 512, x, 512, w_q, 512,
                                    b_q, nullptr, 1.f, q, 512);
    // t1 = X Aq^T
    gemm_abt<<<dim3(1, 288), blk>>>(18432, 32, 512, x, 512, lAq, 512,
                                    nullptr, nullptr, 1.f, t1, 32);
    // q += (t1 Bq^T) * SCALING
    gemm_abt<<<dim3(8, 288), blk>>>(18432, 512, 32, t1, 32, lBq, 32,
                                    nullptr, q, SCALING, q, 512);
    // spatial-reduction conv (im2col GEMM) + bias
    convsr_gemm<<<dim3(8, 18), blk>>>(x, w_sr, b_sr, xspre);
    // LayerNorm
    layernorm_kernel<<<1152, 128>>>(xspre, ln_g, ln_b, xs);
    // kv = xs Wkv^T + b_kv
    gemm_abt<<<dim3(16, 18), blk>>>(1152, 1024, 512, xs, 512, w_kv, 512,
                                    b_kv, nullptr, 1.f, kv, 1024);
    // t2 = xs Av^T ; lv = (t2 Bv^T) * SCALING
    gemm_abt<<<dim3(1, 18), blk>>>(1152, 32, 512, xs, 512, lAv, 512,
                                   nullptr, nullptr, 1.f, t2, 32);
    gemm_abt<<<dim3(8, 18), blk>>>(1152, 512, 32, t2, 32, lBv, 32,
                                   nullptr, nullptr, SCALING, lv, 512);
    // split k / v (+ raw-reshape LoRA-v fixup)
    build_kv<<<2304, 256>>>(kv, lv, k, v);
    // fused attention
    cudaFuncSetAttribute(attn_kernel,
                         cudaFuncAttributeMaxDynamicSharedMemorySize, ATTN_SMEM);
    attn_kernel<<<dim3(144, 16), 256, ATTN_SMEM>>>(q, k, v, ctx);
    // out = ctx Wp^T + b_proj
    gemm_abt<<<dim3(8, 288), blk>>>(18432, 512, 512, ctx, 512, w_proj, 512,
                                    b_proj, nullptr, 1.f, (float*)d_out, 512);
}

// round 2
// speedup vs baseline: 1.7359x; 1.7359x over previous
#include <cuda_runtime.h>
#include <math.h>

// B=2, N=9216, C=512, HEAD=8, d=64, SR=4, H=W=96 -> Nkv=576, R=32
#define SCALING 0.125f

// ---------------------------------------------------------------------------
// Scratch
// ---------------------------------------------------------------------------
__device__ float g_q    [9437184];  // (B,N,C)
__device__ float g_t1   [589824];   // (B*N, 32)
__device__ float g_xspre[589824];   // (B*576, 512)
__device__ float g_xs   [589824];
__device__ float g_kv   [1179648];  // (B*576, 1024)
__device__ float g_t2   [36864];
__device__ float g_lv   [589824];
__device__ float g_k    [589824];   // (B*H,576,64)
__device__ float g_v    [589824];
__device__ float g_ctx  [9437184];
__device__ float g_im2c [9437184];  // 1152 x 8192 im2col
__device__ float g_w2   [4194304];  // 512 x 8192 reordered conv weight
__device__ float g_part [4718592];  // split-K partials (8x589824 == 4x1179648)

// ---------------------------------------------------------------------------
// tf32 helpers
// ---------------------------------------------------------------------------
__device__ __forceinline__ unsigned f2tf(float x) {
    unsigned u;
    asm("cvt.rna.tf32.f32 %0, %1;" : "=r"(u) : "f"(x));
    return u;
}
__device__ __forceinline__ void mma8(float* c, const unsigned* a, const unsigned* b) {
    asm volatile(
        "mma.sync.aligned.m16n8k8.row.col.f32.tf32.tf32.f32 "
        "{%0,%1,%2,%3}, {%4,%5,%6,%7}, {%8,%9}, {%0,%1,%2,%3};"
        : "+f"(c[0]), "+f"(c[1]), "+f"(c[2]), "+f"(c[3])
        : "r"(a[0]), "r"(a[1]), "r"(a[2]), "r"(a[3]),
          "r"(b[0]), "r"(b[1]));
}

// ---------------------------------------------------------------------------
// tf32 tensor-core GEMM:  C = scale * (A @ B^T) (+bias) (+Cin)
// A: MxK row-major, B: NxK row-major. REQUIRES M%128==0, N%64==0, K%16==0.
// BM=128, BN=64, BK=16; 256 threads; warps 4(M)x2(N), each 32x32.
// If gridDim.z>1: write raw partials to `part` (no bias/scale/Cin).
// ---------------------------------------------------------------------------
__global__ void __launch_bounds__(256)
gemm_tf32(int M, int N, int K,
          const float* __restrict__ A, int lda,
          const float* __restrict__ B, int ldb,
          const float* __restrict__ bias,
          const float* __restrict__ Cin,
          float scale,
          float* __restrict__ C, int ldc,
          int kchunk, float* __restrict__ part)
{
    __shared__ unsigned As[128][20];
    __shared__ unsigned Bs[64][20];
    const int t    = threadIdx.x;
    const int lane = t & 31, w = t >> 5;
    const int g  = lane >> 2, tg = lane & 3;
    const int wm = w >> 1,  wn = w & 1;
    const long m0 = (long)blockIdx.y * 128;
    const int  n0 = blockIdx.x * 64;
    const int  kb = blockIdx.z * kchunk;

    const int ar  = t >> 2;            // A rows ar and ar+64
    const int kq4 = (t & 3) * 4;       // k sub-quad

    float acc[2][4][4];
#pragma unroll
    for (int mi = 0; mi < 2; mi++)
#pragma unroll
        for (int ni = 0; ni < 4; ni++)
#pragma unroll
            for (int c = 0; c < 4; c++) acc[mi][ni][c] = 0.f;

    const float* Ap0 = A + (m0 + ar) * lda + kq4;
    const float* Ap1 = A + (m0 + ar + 64) * lda + kq4;
    const float* Bp  = B + (long)(n0 + ar) * ldb + kq4;   // ar<64 valid for B rows

    for (int k0 = kb; k0 < kb + kchunk; k0 += 16) {
        float4 av0 = *(const float4*)(Ap0 + k0);
        float4 av1 = *(const float4*)(Ap1 + k0);
        float4 bv  = *(const float4*)(Bp  + k0);
        __syncthreads();
        As[ar][kq4 + 0]      = f2tf(av0.x);
        As[ar][kq4 + 1]      = f2tf(av0.y);
        As[ar][kq4 + 2]      = f2tf(av0.z);
        As[ar][kq4 + 3]      = f2tf(av0.w);
        As[ar + 64][kq4 + 0] = f2tf(av1.x);
        As[ar + 64][kq4 + 1] = f2tf(av1.y);
        As[ar + 64][kq4 + 2] = f2tf(av1.z);
        As[ar + 64][kq4 + 3] = f2tf(av1.w);
        Bs[ar][kq4 + 0]      = f2tf(bv.x);
        Bs[ar][kq4 + 1]      = f2tf(bv.y);
        Bs[ar][kq4 + 2]      = f2tf(bv.z);
        Bs[ar][kq4 + 3]      = f2tf(bv.w);
        __syncthreads();
#pragma unroll
        for (int kk = 0; kk < 16; kk += 8) {
            unsigned af[2][4], bf[4][2];
#pragma unroll
            for (int mi = 0; mi < 2; mi++) {
                const int r = wm * 32 + mi * 16 + g;
                af[mi][0] = As[r][kk + tg];
                af[mi][1] = As[r + 8][kk + tg];
                af[mi][2] = As[r][kk + tg + 4];
                af[mi][3] = As[r + 8][kk + tg + 4];
            }
#pragma unroll
            for (int ni = 0; ni < 4; ni++) {
                const int rn = wn * 32 + ni * 8 + g;
                bf[ni][0] = Bs[rn][kk + tg];
                bf[ni][1] = Bs[rn][kk + tg + 4];
            }
#pragma unroll
            for (int mi = 0; mi < 2; mi++)
#pragma unroll
                for (int ni = 0; ni < 4; ni++)
                    mma8(acc[mi][ni], af[mi], bf[ni]);
        }
    }

    if (gridDim.z == 1) {
#pragma unroll
        for (int mi = 0; mi < 2; mi++) {
            const long r0 = m0 + wm * 32 + mi * 16 + g;
            const long r1 = r0 + 8;
#pragma unroll
            for (int ni = 0; ni < 4; ni++) {
                const int c = n0 + wn * 32 + ni * 8 + 2 * tg;
                float v00 = scale * acc[mi][ni][0];
                float v01 = scale * acc[mi][ni][1];
                float v10 = scale * acc[mi][ni][2];
                float v11 = scale * acc[mi][ni][3];
                if (bias) {
                    float b0 = bias[c], b1 = bias[c + 1];
                    v00 += b0; v01 += b1; v10 += b0; v11 += b1;
                }
                if (Cin) {
                    v00 += Cin[r0 * ldc + c]; v01 += Cin[r0 * ldc + c + 1];
                    v10 += Cin[r1 * ldc + c]; v11 += Cin[r1 * ldc + c + 1];
                }
                *(float2*)(C + r0 * ldc + c) = make_float2(v00, v01);
                *(float2*)(C + r1 * ldc + c) = make_float2(v10, v11);
            }
        }
    } else {
        float* P = part + (long)blockIdx.z * M * ldc;
#pragma unroll
        for (int mi = 0; mi < 2; mi++) {
            const long r0 = m0 + wm * 32 + mi * 16 + g;
            const long r1 = r0 + 8;
#pragma unroll
            for (int ni = 0; ni < 4; ni++) {
                const int c = n0 + wn * 32 + ni * 8 + 2 * tg;
                *(float2*)(P + r0 * ldc + c) =
                    make_float2(acc[mi][ni][0], acc[mi][ni][1]);
                *(float2*)(P + r1 * ldc + c) =
                    make_float2(acc[mi][ni][2], acc[mi][ni][3]);
            }
        }
    }
}

// out[i] = bias[i % ldc] + sum_z part[z*zstride + i]
__global__ void reduce_part(const float* __restrict__ part,
                            const float* __restrict__ bias,
                            float* __restrict__ out,
                            int total, int ldc, int nz, long zstride)
{
    const int i = blockIdx.x * 256 + threadIdx.x;
    if (i >= total) return;
    float s = bias[i % ldc];
    for (int z = 0; z < nz; z++) s += part[(long)z * zstride + i];
    out[i] = s;
}

// w2[co][(i*4+j)*512 + ci] = w_sr[co][ci][i][j]
__global__ void reorder_w_kernel(const float* __restrict__ w,
                                 float* __restrict__ w2)
{
    const int tid = blockIdx.x * 256 + threadIdx.x;   // < 4194304
    const int ci = tid & 511;
    const int s  = (tid >> 9) & 15;
    const int co = tid >> 13;
    w2[tid] = w[(long)co * 8192 + ci * 16 + s];
}

// im2col: A2[m][(i*4+j)*512+ci] = x[b, (4py+i)*96+4px+j, ci]
__global__ void im2col_kernel(const float* __restrict__ x,
                              float* __restrict__ out)
{
    const long tid = (long)blockIdx.x * 256 + threadIdx.x;  // < 9437184
    const int ci = tid & 511;
    const int s  = ((int)(tid >> 9)) & 15;
    const int m  = (int)(tid >> 13);
    const int i = s >> 2, j = s & 3;
    const int b = m / 576, p = m % 576;
    const int py = p / 24, px = p % 24;
    out[tid] = x[((long)b * 9216 + (py * 4 + i) * 96 + px * 4 + j) * 512 + ci];
}

// ---------------------------------------------------------------------------
// SIMT GEMM kept for tiny-N LoRA-A (N=32)
// ---------------------------------------------------------------------------
__global__ void gemm_abt(int M, int N, int K,
                         const float* __restrict__ A, int lda,
                         const float* __restrict__ Bm, int ldb,
                         const float* __restrict__ bias,
                         const float* __restrict__ Cin,
                         float scale,
                         float* __restrict__ C, int ldc)
{
    __shared__ float As[16 * 64];
    __shared__ float Bs[16 * 64];
    const int t  = threadIdx.x;
    const int ty = t >> 4, tx = t & 15;
    const int m0 = blockIdx.y * 64, n0 = blockIdx.x * 64;
    const int lr = t >> 2;
    const int lk = (t & 3) << 2;

    float acc[4][4];
#pragma unroll
    for (int i = 0; i < 4; i++)
#pragma unroll
        for (int j = 0; j < 4; j++) acc[i][j] = 0.f;

    const int gmL = m0 + lr;
    const int gnL = n0 + lr;

    for (int k0 = 0; k0 < K; k0 += 16) {
        float4 av = make_float4(0.f, 0.f, 0.f, 0.f);
        float4 bv = make_float4(0.f, 0.f, 0.f, 0.f);
        if (gmL < M) av = *(const float4*)(A  + (long)gmL * lda + k0 + lk);
        if (gnL < N) bv = *(const float4*)(Bm + (long)gnL * ldb + k0 + lk);
        __syncthreads();
        As[(lk + 0) * 64 + lr] = av.x; As[(lk + 1) * 64 + lr] = av.y;
        As[(lk + 2) * 64 + lr] = av.z; As[(lk + 3) * 64 + lr] = av.w;
        Bs[(lk + 0) * 64 + lr] = bv.x; Bs[(lk + 1) * 64 + lr] = bv.y;
        Bs[(lk + 2) * 64 + lr] = bv.z; Bs[(lk + 3) * 64 + lr] = bv.w;
        __syncthreads();
#pragma unroll
        for (int kk = 0; kk < 16; kk++) {
            float4 a4 = *(const float4*)(As + kk * 64 + ty * 4);
            float4 b4 = *(const float4*)(Bs + kk * 64 + tx * 4);
            float ar[4] = {a4.x, a4.y, a4.z, a4.w};
            float br[4] = {b4.x, b4.y, b4.z, b4.w};
#pragma unroll
            for (int i = 0; i < 4; i++)
#pragma unroll
                for (int j = 0; j < 4; j++)
                    acc[i][j] += ar[i] * br[j];
        }
    }

#pragma unroll
    for (int i = 0; i < 4; i++) {
        int gm = m0 + ty * 4 + i;
        if (gm >= M) continue;
#pragma unroll
        for (int j = 0; j < 4; j++) {
            int gn = n0 + tx * 4 + j;
            if (gn >= N) continue;
            float r = scale * acc[i][j];
            if (bias) r += bias[gn];
            if (Cin)  r += Cin[(long)gm * ldc + gn];
            C[(long)gm * ldc + gn] = r;
        }
    }
}

// ---------------------------------------------------------------------------
// LayerNorm over C=512
// ---------------------------------------------------------------------------
__global__ void layernorm_kernel(const float* __restrict__ in,
                                 const float* __restrict__ gam,
                                 const float* __restrict__ bet,
                                 float* __restrict__ out)
{
    const int row = blockIdx.x;
    const int t   = threadIdx.x;
    const float* x = in + (long)row * 512;
    float v0 = x[t], v1 = x[t + 128], v2 = x[t + 256], v3 = x[t + 384];
    float s  = v0 + v1 + v2 + v3;
    float s2 = v0 * v0 + v1 * v1 + v2 * v2 + v3 * v3;
#pragma unroll
    for (int o = 16; o > 0; o >>= 1) {
        s  += __shfl_xor_sync(0xffffffffu, s,  o);
        s2 += __shfl_xor_sync(0xffffffffu, s2, o);
    }
    __shared__ float ss[4], ss2[4];
    if ((t & 31) == 0) { ss[t >> 5] = s; ss2[t >> 5] = s2; }
    __syncthreads();
    s  = ss[0]  + ss[1]  + ss[2]  + ss[3];
    s2 = ss2[0] + ss2[1] + ss2[2] + ss2[3];
    const float mean = s * (1.f / 512.f);
    const float var  = s2 * (1.f / 512.f) - mean * mean;
    const float inv  = rsqrtf(var + 1e-5f);
    float* o = out + (long)row * 512;
    o[t]       = (v0 - mean) * inv * gam[t]       + bet[t];
    o[t + 128] = (v1 - mean) * inv * gam[t + 128] + bet[t + 128];
    o[t + 256] = (v2 - mean) * inv * gam[t + 256] + bet[t + 256];
    o[t + 384] = (v3 - mean) * inv * gam[t + 384] + bet[t + 384];
}

// ---------------------------------------------------------------------------
// k/v head split; v gets the raw-reshape LoRA fixup
// ---------------------------------------------------------------------------
__global__ void build_kv(const float* __restrict__ kv,
                         const float* __restrict__ lv,
                         float* __restrict__ k, float* __restrict__ v)
{
    const int idx = blockIdx.x * 256 + threadIdx.x;
    const int dd = idx & 63;
    const int m  = (idx >> 6) % 576;
    const int bh = idx / 36864;
    const int h  = bh & 7, b = bh >> 3;
    const long base = (long)(b * 576 + m) * 1024 + h * 64 + dd;
    k[idx] = kv[base];
    v[idx] = kv[base + 512] + lv[(long)b * 294912 + h * 36864 + m * 64 + dd];
}

// ---------------------------------------------------------------------------
// Fused attention (fp32 SIMT), full 64x576 scores in smem
// ---------------------------------------------------------------------------
#define SP 580
#define KVP 68
#define ATTN_SMEM ((64 * SP + 2 * 64 * KVP + 64) * 4)

__global__ void attn_kernel(const float* __restrict__ qb,
                            const float* __restrict__ kb,
                            const float* __restrict__ vb,
                            float* __restrict__ ctx)
{
    extern __shared__ float sm[];
    float* S      = sm;
    float* Qt     = sm + 64 * SP;
    float* KV     = Qt + 64 * KVP;
    float* rowinv = KV + 64 * KVP;

    const int t  = threadIdx.x;
    const int ty = t >> 4, tx = t & 15;
    const int bh = blockIdx.y, b = bh >> 3, h = bh & 7;
    const int n0 = blockIdx.x * 64;

#pragma unroll
    for (int r = 0; r < 16; r++) {
        int idx = r * 256 + t;
        int q = idx >> 6, dd = idx & 63;
        Qt[dd * KVP + q] = qb[(long)(b * 9216 + n0 + q) * 512 + h * 64 + dd];
    }

    for (int ch = 0; ch < 9; ch++) {
        const int m0c = ch * 64;
        __syncthreads();
#pragma unroll
        for (int r = 0; r < 16; r++) {
            int idx = r * 256 + t;
            int key = idx >> 6, dd = idx & 63;
            KV[dd * KVP + key] = kb[(long)(bh * 576 + m0c + key) * 64 + dd];
        }
        __syncthreads();
        float acc[4][4];
#pragma unroll
        for (int i = 0; i < 4; i++)
#pragma unroll
            for (int j = 0; j < 4; j++) acc[i][j] = 0.f;
#pragma unroll 8
        for (int dd = 0; dd < 64; dd++) {
            float4 a4 = *(const float4*)(Qt + dd * KVP + ty * 4);
            float4 k4 = *(const float4*)(KV + dd * KVP + tx * 4);
            float ar[4] = {a4.x, a4.y, a4.z, a4.w};
            float kr[4] = {k4.x, k4.y, k4.z, k4.w};
#pragma unroll
            for (int i = 0; i < 4; i++)
#pragma unroll
                for (int j = 0; j < 4; j++)
                    acc[i][j] += ar[i] * kr[j];
        }
#pragma unroll
        for (int i = 0; i < 4; i++) {
            float4 sv = make_float4(acc[i][0] * 0.125f, acc[i][1] * 0.125f,
                                    acc[i][2] * 0.125f, acc[i][3] * 0.125f);
            *(float4*)(S + (ty * 4 + i) * SP + m0c + tx * 4) = sv;
        }
    }
    __syncthreads();

    {
        const int row = t >> 2, part = t & 3;
        float mx = -1e30f;
        for (int s = 0; s < 144; s++)
            mx = fmaxf(mx, S[row * SP + 4 * s + part]);
        mx = fmaxf(mx, __shfl_xor_sync(0xffffffffu, mx, 1));
        mx = fmaxf(mx, __shfl_xor_sync(0xffffffffu, mx, 2));
        float sum = 0.f;
        for (int s = 0; s < 144; s++) {
            float e = __expf(S[row * SP + 4 * s + part] - mx);
            S[row * SP + 4 * s + part] = e;
            sum += e;
        }
        sum += __shfl_xor_sync(0xffffffffu, sum, 1);
        sum += __shfl_xor_sync(0xffffffffu, sum, 2);
        if (part == 0) rowinv[row] = 1.f / sum;
    }

    float acc[4][4];
#pragma unroll
    for (int i = 0; i < 4; i++)
#pragma unroll
        for (int j = 0; j < 4; j++) acc[i][j] = 0.f;

    for (int ch = 0; ch < 9; ch++) {
        const int m0c = ch * 64;
        __syncthreads();
#pragma unroll
        for (int r = 0; r < 16; r++) {
            int idx = r * 256 + t;
            int key = idx >> 6, dd = idx & 63;
            KV[key * KVP + dd] = vb[(long)(bh * 576 + m0c + key) * 64 + dd];
        }
        __syncthreads();
#pragma unroll 8
        for (int j = 0; j < 64; j++) {
            float4 v4 = *(const float4*)(KV + j * KVP + tx * 4);
#pragma unroll
            for (int i = 0; i < 4; i++) {
                float pv = S[(ty * 4 + i) * SP + m0c + j];
                acc[i][0] += pv * v4.x;
                acc[i][1] += pv * v4.y;
                acc[i][2] += pv * v4.z;
                acc[i][3] += pv * v4.w;
            }
        }
    }

#pragma unroll
    for (int i = 0; i < 4; i++) {
        const float inv = rowinv[ty * 4 + i];
        float4 o = make_float4(acc[i][0] * inv, acc[i][1] * inv,
                               acc[i][2] * inv, acc[i][3] * inv);
        *(float4*)(ctx + (long)(b * 9216 + n0 + ty * 4 + i) * 512
                        + h * 64 + tx * 4) = o;
    }
}

// ---------------------------------------------------------------------------
// Launch pipeline
// ---------------------------------------------------------------------------
extern "C" void kernel_launch(void* const* d_in, const int* in_sizes, int n_in,
                              void* d_out, int out_size)
{
    (void)in_sizes; (void)n_in; (void)out_size;
    const float* x      = (const float*)d_in[0];
    const float* w_q    = (const float*)d_in[1];
    const float* b_q    = (const float*)d_in[2];
    const float* w_kv   = (const float*)d_in[3];
    const float* b_kv   = (const float*)d_in[4];
    const float* w_proj = (const float*)d_in[5];
    const float* b_proj = (const float*)d_in[6];
    const float* w_sr   = (const float*)d_in[7];
    const float* b_sr   = (const float*)d_in[8];
    const float* ln_g   = (const float*)d_in[9];
    const float* ln_b   = (const float*)d_in[10];
    const float* lAq    = (const float*)d_in[11];
    const float* lBq    = (const float*)d_in[12];
    const float* lAv    = (const float*)d_in[13];
    const float* lBv    = (const float*)d_in[14];

    float *q, *t1, *xspre, *xs, *kv, *t2, *lv, *k, *v, *ctx, *im2c, *w2, *part;
    cudaGetSymbolAddress((void**)&q,     g_q);
    cudaGetSymbolAddress((void**)&t1,    g_t1);
    cudaGetSymbolAddress((void**)&xspre, g_xspre);
    cudaGetSymbolAddress((void**)&xs,    g_xs);
    cudaGetSymbolAddress((void**)&kv,    g_kv);
    cudaGetSymbolAddress((void**)&t2,    g_t2);
    cudaGetSymbolAddress((void**)&lv,    g_lv);
    cudaGetSymbolAddress((void**)&k,     g_k);
    cudaGetSymbolAddress((void**)&v,     g_v);
    cudaGetSymbolAddress((void**)&ctx,   g_ctx);
    cudaGetSymbolAddress((void**)&im2c,  g_im2c);
    cudaGetSymbolAddress((void**)&w2,    g_w2);
    cudaGetSymbolAddress((void**)&part,  g_part);

    dim3 blk(256);

    // conv prep
    reorder_w_kernel<<<16384, blk>>>(w_sr, w2);
    im2col_kernel<<<36864, blk>>>(x, im2c);
    // conv GEMM, 8-way split-K (1152x512x8192)
    gemm_tf32<<<dim3(8, 9, 8), blk>>>(1152, 512, 8192, im2c, 8192, w2, 8192,
                                      nullptr, nullptr, 1.f, nullptr, 512,
                                      1024, part);
    reduce_part<<<2304, blk>>>(part, b_sr, xspre, 589824, 512, 8, 589824);
    layernorm_kernel<<<1152, 128>>>(xspre, ln_g, ln_b, xs);

    // q = X Wq^T + b_q  (18432x512x512)
    gemm_tf32<<<dim3(8, 144, 1), blk>>>(18432, 512, 512, x, 512, w_q, 512,
                                        b_q, nullptr, 1.f, q, 512, 512, nullptr);
    // t1 = X Aq^T  (N=32, SIMT)
    gemm_abt<<<dim3(1, 288), blk>>>(18432, 32, 512, x, 512, lAq, 512,
                                    nullptr, nullptr, 1.f, t1, 32);
    // q += (t1 Bq^T) * SCALING
    gemm_tf32<<<dim3(8, 144, 1), blk>>>(18432, 512, 32, t1, 32, lBq, 32,
                                        nullptr, q, SCALING, q, 512, 32, nullptr);

    // kv = xs Wkv^T + b_kv  (1152x1024x512), 4-way split-K
    gemm_tf32<<<dim3(16, 9, 4), blk>>>(1152, 1024, 512, xs, 512, w_kv, 512,
                                       nullptr, nullptr, 1.f, nullptr, 1024,
                                       128, part);
    reduce_part<<<4608, blk>>>(part, b_kv, kv, 1179648, 1024, 4, 1179648);

    // lv = (xs Av^T) Bv^T * SCALING
    gemm_abt<<<dim3(1, 18), blk>>>(1152, 32, 512, xs, 512, lAv, 512,
                                   nullptr, nullptr, 1.f, t2, 32);
    gemm_tf32<<<dim3(8, 9, 1), blk>>>(1152, 512, 32, t2, 32, lBv, 32,
                                      nullptr, nullptr, SCALING, lv, 512,
                                      32, nullptr);

    build_kv<<<2304, blk>>>(kv, lv, k, v);

    cudaFuncSetAttribute(attn_kernel,
                         cudaFuncAttributeMaxDynamicSharedMemorySize, ATTN_SMEM);
    attn_kernel<<<dim3(144, 16), blk, ATTN_SMEM>>>(q, k, v, ctx);

    // out = ctx Wp^T + b_proj
    gemm_tf32<<<dim3(8, 144, 1), blk>>>(18432, 512, 512, ctx, 512, w_proj, 512,
                                        b_proj, nullptr, 1.f, (float*)d_out,
                                        512, 512, nullptr);
}

// round 3
// speedup vs baseline: 2.1099x; 1.2154x over previous
#include <cuda_runtime.h>
#include <math.h>

// B=2, N=9216, C=512, HEAD=8, d=64, SR=4, H=W=96 -> Nkv=576, R=32
#define SCALING 0.125f

// ---------------------------------------------------------------------------
// Scratch
// ---------------------------------------------------------------------------
__device__ float g_q    [9437184];  // (B,N,C)
__device__ float g_t1   [589824];   // (B*N, 32)
__device__ float g_xspre[589824];   // (B*576, 512)
__device__ float g_xs   [589824];
__device__ float g_kv   [1179648];  // (B*576, 1024)
__device__ float g_t2   [36864];
__device__ float g_lv   [589824];
__device__ float g_k    [589824];   // (B*H,576,64)
__device__ float g_v    [589824];
__device__ float g_ctx  [9437184];
__device__ float g_im2c [9437184];  // 1152 x 8192 im2col
__device__ float g_w2   [4194304];  // 512 x 8192 reordered conv weight
__device__ float g_part [4718592];  // split-K partials

// ---------------------------------------------------------------------------
// tf32 helpers
// ---------------------------------------------------------------------------
__device__ __forceinline__ unsigned f2tf(float x) {
    unsigned u;
    asm("cvt.rna.tf32.f32 %0, %1;" : "=r"(u) : "f"(x));
    return u;
}
__device__ __forceinline__ void mma8(float* c, const unsigned* a, const unsigned* b) {
    asm volatile(
        "mma.sync.aligned.m16n8k8.row.col.f32.tf32.tf32.f32 "
        "{%0,%1,%2,%3}, {%4,%5,%6,%7}, {%8,%9}, {%0,%1,%2,%3};"
        : "+f"(c[0]), "+f"(c[1]), "+f"(c[2]), "+f"(c[3])
        : "r"(a[0]), "r"(a[1]), "r"(a[2]), "r"(a[3]),
          "r"(b[0]), "r"(b[1]));
}

// ---------------------------------------------------------------------------
// tf32 tensor-core GEMM:  C = scale * (A @ B^T) (+bias) (+Cin)
// A: MxK row-major, B: NxK row-major. REQUIRES M%128==0, N%64==0, K%16==0.
// BM=128, BN=64, BK=16; 256 threads; warps 4(M)x2(N), each 32x32.
// If gridDim.z>1: write raw partials to `part`.
// SPLIT=1: hi/lo tf32 decomposition (3 mmas) for ~fp32 accuracy.
// ---------------------------------------------------------------------------
template <int SPLIT>
__global__ void __launch_bounds__(256)
gemm_tf32(int M, int N, int K,
          const float* __restrict__ A, int lda,
          const float* __restrict__ B, int ldb,
          const float* __restrict__ bias,
          const float* __restrict__ Cin,
          float scale,
          float* __restrict__ C, int ldc,
          int kchunk, float* __restrict__ part)
{
    __shared__ unsigned As[SPLIT + 1][128][20];
    __shared__ unsigned Bs[SPLIT + 1][64][20];
    const int t    = threadIdx.x;
    const int lane = t & 31, w = t >> 5;
    const int g  = lane >> 2, tg = lane & 3;
    const int wm = w >> 1,  wn = w & 1;
    const long m0 = (long)blockIdx.y * 128;
    const int  n0 = blockIdx.x * 64;
    const int  kb = blockIdx.z * kchunk;

    const int ar  = t >> 2;
    const int kq4 = (t & 3) * 4;

    float acc[2][4][4];
#pragma unroll
    for (int mi = 0; mi < 2; mi++)
#pragma unroll
        for (int ni = 0; ni < 4; ni++)
#pragma unroll
            for (int c = 0; c < 4; c++) acc[mi][ni][c] = 0.f;

    const float* Ap0 = A + (m0 + ar) * lda + kq4;
    const float* Ap1 = A + (m0 + ar + 64) * lda + kq4;
    const float* Bp  = B + (long)(n0 + ar) * ldb + kq4;

    for (int k0 = kb; k0 < kb + kchunk; k0 += 16) {
        float4 av0 = *(const float4*)(Ap0 + k0);
        float4 av1 = *(const float4*)(Ap1 + k0);
        float4 bv  = *(const float4*)(Bp  + k0);
        __syncthreads();
        {
            float a0[4] = {av0.x, av0.y, av0.z, av0.w};
            float a1[4] = {av1.x, av1.y, av1.z, av1.w};
            float bb[4] = {bv.x,  bv.y,  bv.z,  bv.w};
#pragma unroll
            for (int c = 0; c < 4; c++) {
                unsigned h0 = f2tf(a0[c]), h1 = f2tf(a1[c]), hb = f2tf(bb[c]);
                As[0][ar][kq4 + c]      = h0;
                As[0][ar + 64][kq4 + c] = h1;
                Bs[0][ar][kq4 + c]      = hb;
                if (SPLIT) {
                    As[SPLIT][ar][kq4 + c]      = f2tf(a0[c] - __uint_as_float(h0));
                    As[SPLIT][ar + 64][kq4 + c] = f2tf(a1[c] - __uint_as_float(h1));
                    Bs[SPLIT][ar][kq4 + c]      = f2tf(bb[c] - __uint_as_float(hb));
                }
            }
        }
        __syncthreads();
#pragma unroll
        for (int kk = 0; kk < 16; kk += 8) {
            unsigned af[2][4], bf[4][2];
#pragma unroll
            for (int mi = 0; mi < 2; mi++) {
                const int r = wm * 32 + mi * 16 + g;
                af[mi][0] = As[0][r][kk + tg];
                af[mi][1] = As[0][r + 8][kk + tg];
                af[mi][2] = As[0][r][kk + tg + 4];
                af[mi][3] = As[0][r + 8][kk + tg + 4];
            }
#pragma unroll
            for (int ni = 0; ni < 4; ni++) {
                const int rn = wn * 32 + ni * 8 + g;
                bf[ni][0] = Bs[0][rn][kk + tg];
                bf[ni][1] = Bs[0][rn][kk + tg + 4];
            }
#pragma unroll
            for (int mi = 0; mi < 2; mi++)
#pragma unroll
                for (int ni = 0; ni < 4; ni++)
                    mma8(acc[mi][ni], af[mi], bf[ni]);
            if (SPLIT) {
                unsigned afl[2][4], bfl[4][2];
#pragma unroll
                for (int mi = 0; mi < 2; mi++) {
                    const int r = wm * 32 + mi * 16 + g;
                    afl[mi][0] = As[SPLIT][r][kk + tg];
                    afl[mi][1] = As[SPLIT][r + 8][kk + tg];
                    afl[mi][2] = As[SPLIT][r][kk + tg + 4];
                    afl[mi][3] = As[SPLIT][r + 8][kk + tg + 4];
                }
#pragma unroll
                for (int ni = 0; ni < 4; ni++) {
                    const int rn = wn * 32 + ni * 8 + g;
                    bfl[ni][0] = Bs[SPLIT][rn][kk + tg];
                    bfl[ni][1] = Bs[SPLIT][rn][kk + tg + 4];
                }
#pragma unroll
                for (int mi = 0; mi < 2; mi++)
#pragma unroll
                    for (int ni = 0; ni < 4; ni++) {
                        mma8(acc[mi][ni], af[mi],  bfl[ni]);
                        mma8(acc[mi][ni], afl[mi], bf[ni]);
                    }
            }
        }
    }

    if (gridDim.z == 1) {
#pragma unroll
        for (int mi = 0; mi < 2; mi++) {
            const long r0 = m0 + wm * 32 + mi * 16 + g;
            const long r1 = r0 + 8;
#pragma unroll
            for (int ni = 0; ni < 4; ni++) {
                const int c = n0 + wn * 32 + ni * 8 + 2 * tg;
                float v00 = scale * acc[mi][ni][0];
                float v01 = scale * acc[mi][ni][1];
                float v10 = scale * acc[mi][ni][2];
                float v11 = scale * acc[mi][ni][3];
                if (bias) {
                    float b0 = bias[c], b1 = bias[c + 1];
                    v00 += b0; v01 += b1; v10 += b0; v11 += b1;
                }
                if (Cin) {
                    v00 += Cin[r0 * ldc + c]; v01 += Cin[r0 * ldc + c + 1];
                    v10 += Cin[r1 * ldc + c]; v11 += Cin[r1 * ldc + c + 1];
                }
                *(float2*)(C + r0 * ldc + c) = make_float2(v00, v01);
                *(float2*)(C + r1 * ldc + c) = make_float2(v10, v11);
            }
        }
    } else {
        float* P = part + (long)blockIdx.z * M * ldc;
#pragma unroll
        for (int mi = 0; mi < 2; mi++) {
            const long r0 = m0 + wm * 32 + mi * 16 + g;
            const long r1 = r0 + 8;
#pragma unroll
            for (int ni = 0; ni < 4; ni++) {
                const int c = n0 + wn * 32 + ni * 8 + 2 * tg;
                *(float2*)(P + r0 * ldc + c) =
                    make_float2(acc[mi][ni][0], acc[mi][ni][1]);
                *(float2*)(P + r1 * ldc + c) =
                    make_float2(acc[mi][ni][2], acc[mi][ni][3]);
            }
        }
    }
}

// out[i] = bias[i % ldc] + sum_z part[z*zstride + i]
__global__ void reduce_part(const float* __restrict__ part,
                            const float* __restrict__ bias,
                            float* __restrict__ out,
                            int total, int ldc, int nz, long zstride)
{
    const int i = blockIdx.x * 256 + threadIdx.x;
    if (i >= total) return;
    float s = bias[i % ldc];
    for (int z = 0; z < nz; z++) s += part[(long)z * zstride + i];
    out[i] = s;
}

// w2[co][(i*4+j)*512 + ci] = w_sr[co][ci][i][j]
__global__ void reorder_w_kernel(const float* __restrict__ w,
                                 float* __restrict__ w2)
{
    const int tid = blockIdx.x * 256 + threadIdx.x;
    const int ci = tid & 511;
    const int s  = (tid >> 9) & 15;
    const int co = tid >> 13;
    w2[tid] = w[(long)co * 8192 + ci * 16 + s];
}

// im2col: A2[m][(i*4+j)*512+ci] = x[b, (4py+i)*96+4px+j, ci]
__global__ void im2col_kernel(const float* __restrict__ x,
                              float* __restrict__ out)
{
    const long tid = (long)blockIdx.x * 256 + threadIdx.x;
    const int ci = tid & 511;
    const int s  = ((int)(tid >> 9)) & 15;
    const int m  = (int)(tid >> 13);
    const int i = s >> 2, j = s & 3;
    const int b = m / 576, p = m % 576;
    const int py = p / 24, px = p % 24;
    out[tid] = x[((long)b * 9216 + (py * 4 + i) * 96 + px * 4 + j) * 512 + ci];
}

// ---------------------------------------------------------------------------
// SIMT GEMM kept for tiny-N LoRA-A (N=32)
// ---------------------------------------------------------------------------
__global__ void gemm_abt(int M, int N, int K,
                         const float* __restrict__ A, int lda,
                         const float* __restrict__ Bm, int ldb,
                         const float* __restrict__ bias,
                         const float* __restrict__ Cin,
                         float scale,
                         float* __restrict__ C, int ldc)
{
    __shared__ float As[16 * 64];
    __shared__ float Bs[16 * 64];
    const int t  = threadIdx.x;
    const int ty = t >> 4, tx = t & 15;
    const int m0 = blockIdx.y * 64, n0 = blockIdx.x * 64;
    const int lr = t >> 2;
    const int lk = (t & 3) << 2;

    float acc[4][4];
#pragma unroll
    for (int i = 0; i < 4; i++)
#pragma unroll
        for (int j = 0; j < 4; j++) acc[i][j] = 0.f;

    const int gmL = m0 + lr;
    const int gnL = n0 + lr;

    for (int k0 = 0; k0 < K; k0 += 16) {
        float4 av = make_float4(0.f, 0.f, 0.f, 0.f);
        float4 bv = make_float4(0.f, 0.f, 0.f, 0.f);
        if (gmL < M) av = *(const float4*)(A  + (long)gmL * lda + k0 + lk);
        if (gnL < N) bv = *(const float4*)(Bm + (long)gnL * ldb + k0 + lk);
        __syncthreads();
        As[(lk + 0) * 64 + lr] = av.x; As[(lk + 1) * 64 + lr] = av.y;
        As[(lk + 2) * 64 + lr] = av.z; As[(lk + 3) * 64 + lr] = av.w;
        Bs[(lk + 0) * 64 + lr] = bv.x; Bs[(lk + 1) * 64 + lr] = bv.y;
        Bs[(lk + 2) * 64 + lr] = bv.z; Bs[(lk + 3) * 64 + lr] = bv.w;
        __syncthreads();
#pragma unroll
        for (int kk = 0; kk < 16; kk++) {
            float4 a4 = *(const float4*)(As + kk * 64 + ty * 4);
            float4 b4 = *(const float4*)(Bs + kk * 64 + tx * 4);
            float ar[4] = {a4.x, a4.y, a4.z, a4.w};
            float br[4] = {b4.x, b4.y, b4.z, b4.w};
#pragma unroll
            for (int i = 0; i < 4; i++)
#pragma unroll
                for (int j = 0; j < 4; j++)
                    acc[i][j] += ar[i] * br[j];
        }
    }

#pragma unroll
    for (int i = 0; i < 4; i++) {
        int gm = m0 + ty * 4 + i;
        if (gm >= M) continue;
#pragma unroll
        for (int j = 0; j < 4; j++) {
            int gn = n0 + tx * 4 + j;
            if (gn >= N) continue;
            float r = scale * acc[i][j];
            if (bias) r += bias[gn];
            if (Cin)  r += Cin[(long)gm * ldc + gn];
            C[(long)gm * ldc + gn] = r;
        }
    }
}

// ---------------------------------------------------------------------------
// LayerNorm over C=512
// ---------------------------------------------------------------------------
__global__ void layernorm_kernel(const float* __restrict__ in,
                                 const float* __restrict__ gam,
                                 const float* __restrict__ bet,
                                 float* __restrict__ out)
{
    const int row = blockIdx.x;
    const int t   = threadIdx.x;
    const float* x = in + (long)row * 512;
    float v0 = x[t], v1 = x[t + 128], v2 = x[t + 256], v3 = x[t + 384];
    float s  = v0 + v1 + v2 + v3;
    float s2 = v0 * v0 + v1 * v1 + v2 * v2 + v3 * v3;
#pragma unroll
    for (int o = 16; o > 0; o >>= 1) {
        s  += __shfl_xor_sync(0xffffffffu, s,  o);
        s2 += __shfl_xor_sync(0xffffffffu, s2, o);
    }
    __shared__ float ss[4], ss2[4];
    if ((t & 31) == 0) { ss[t >> 5] = s; ss2[t >> 5] = s2; }
    __syncthreads();
    s  = ss[0]  + ss[1]  + ss[2]  + ss[3];
    s2 = ss2[0] + ss2[1] + ss2[2] + ss2[3];
    const float mean = s * (1.f / 512.f);
    const float var  = s2 * (1.f / 512.f) - mean * mean;
    const float inv  = rsqrtf(var + 1e-5f);
    float* o = out + (long)row * 512;
    o[t]       = (v0 - mean) * inv * gam[t]       + bet[t];
    o[t + 128] = (v1 - mean) * inv * gam[t + 128] + bet[t + 128];
    o[t + 256] = (v2 - mean) * inv * gam[t + 256] + bet[t + 256];
    o[t + 384] = (v3 - mean) * inv * gam[t + 384] + bet[t + 384];
}

// ---------------------------------------------------------------------------
// k/v head split; v gets the raw-reshape LoRA fixup
// ---------------------------------------------------------------------------
__global__ void build_kv(const float* __restrict__ kv,
                         const float* __restrict__ lv,
                         float* __restrict__ k, float* __restrict__ v)
{
    const int idx = blockIdx.x * 256 + threadIdx.x;
    const int dd = idx & 63;
    const int m  = (idx >> 6) % 576;
    const int bh = idx / 36864;
    const int h  = bh & 7, b = bh >> 3;
    const long base = (long)(b * 576 + m) * 1024 + h * 64 + dd;
    k[idx] = kv[base];
    v[idx] = kv[base + 512] + lv[(long)b * 294912 + h * 36864 + m * 64 + dd];
}

// ---------------------------------------------------------------------------
// Fused attention, tf32 tensor cores.
// One block = 64 queries x one (b,h). Full 64x576 score matrix in smem.
// 256 threads = 8 warps as 4(m) x 2(n).
// ---------------------------------------------------------------------------
#define SP 580   // S pitch: mod 32 == 4 -> conflict-free frag loads
#define TP 68    // tile pitch: mod 32 == 4
#define ATTN_SMEM ((64 * SP + 2 * 64 * TP + 64) * 4)

__global__ void __launch_bounds__(256)
attn_mma(const float* __restrict__ qb,   // (B,N,512)
         const float* __restrict__ kb,   // (B*H,576,64)
         const float* __restrict__ vb,   // (B*H,576,64)
         float* __restrict__ ctx)        // (B,N,512)
{
    extern __shared__ float sm[];
    float*    S      = sm;                              // 64 * SP (fp32/tf32 bits)
    unsigned* Qs     = (unsigned*)(sm + 64 * SP);       // [q][dd] 64*TP
    unsigned* KVs    = Qs + 64 * TP;                    // K: [key][dd], V: [dd][key]
    float*    rowinv = (float*)(KVs + 64 * TP);         // 64

    const int t    = threadIdx.x;
    const int lane = t & 31, w = t >> 5;
    const int g  = lane >> 2, tg = lane & 3;
    const int wm = w >> 1,  wn = w & 1;
    const int bh = blockIdx.y, b = bh >> 3, h = bh & 7;
    const int n0 = blockIdx.x * 64;

    // Q tile [q][dd] as tf32
#pragma unroll
    for (int r = 0; r < 16; r++) {
        int idx = r * 256 + t;
        int qq = idx >> 6, dd = idx & 63;
        Qs[qq * TP + dd] = f2tf(qb[(long)(b * 9216 + n0 + qq) * 512 + h * 64 + dd]);
    }

    // ---- Phase 1: S = (Q K^T) * 0.125 ----
    for (int ch = 0; ch < 9; ch++) {
        const int m0c = ch * 64;
        __syncthreads();
#pragma unroll
        for (int r = 0; r < 16; r++) {
            int idx = r * 256 + t;
            int key = idx >> 6, dd = idx & 63;
            KVs[key * TP + dd] =
                f2tf(kb[(long)(bh * 576 + m0c + key) * 64 + dd]);
        }
        __syncthreads();
        float acc[4][4];
#pragma unroll
        for (int ni = 0; ni < 4; ni++)
#pragma unroll
            for (int c = 0; c < 4; c++) acc[ni][c] = 0.f;
        const int r = wm * 16 + g;
#pragma unroll
        for (int kk = 0; kk < 64; kk += 8) {
            unsigned af[4];
            af[0] = Qs[r * TP + kk + tg];
            af[1] = Qs[(r + 8) * TP + kk + tg];
            af[2] = Qs[r * TP + kk + tg + 4];
            af[3] = Qs[(r + 8) * TP + kk + tg + 4];
#pragma unroll
            for (int ni = 0; ni < 4; ni++) {
                const int rn = wn * 32 + ni * 8 + g;
                unsigned bf[2];
                bf[0] = KVs[rn * TP + kk + tg];
                bf[1] = KVs[rn * TP + kk + tg + 4];
                mma8(acc[ni], af, bf);
            }
        }
        const int r0 = wm * 16 + g;
#pragma unroll
        for (int ni = 0; ni < 4; ni++) {
            const int c = m0c + wn * 32 + ni * 8 + 2 * tg;
            *(float2*)(S + r0 * SP + c) =
                make_float2(acc[ni][0] * 0.125f, acc[ni][1] * 0.125f);
            *(float2*)(S + (r0 + 8) * SP + c) =
                make_float2(acc[ni][2] * 0.125f, acc[ni][3] * 0.125f);
        }
    }
    __syncthreads();

    // ---- Phase 2: softmax (e rounded to tf32 so P is exact for the mma) ----
    {
        const int row = t >> 2, part = t & 3;
        float mx = -1e30f;
        for (int s = 0; s < 144; s++)
            mx = fmaxf(mx, S[row * SP + 4 * s + part]);
        mx = fmaxf(mx, __shfl_xor_sync(0xffffffffu, mx, 1));
        mx = fmaxf(mx, __shfl_xor_sync(0xffffffffu, mx, 2));
        float sum = 0.f;
        for (int s = 0; s < 144; s++) {
            float e = __expf(S[row * SP + 4 * s + part] - mx);
            float et = __uint_as_float(f2tf(e));
            S[row * SP + 4 * s + part] = et;
            sum += et;
        }
        sum += __shfl_xor_sync(0xffffffffu, sum, 1);
        sum += __shfl_xor_sync(0xffffffffu, sum, 2);
        if (part == 0) rowinv[row] = 1.f / sum;
    }
    __syncthreads();

    // ---- Phase 3: O = P @ V  (V transposed tile [dd][key]) ----
    float o[4][4];
#pragma unroll
    for (int ni = 0; ni < 4; ni++)
#pragma unroll
        for (int c = 0; c < 4; c++) o[ni][c] = 0.f;

    for (int ch = 0; ch < 9; ch++) {
        const int m0c = ch * 64;
#pragma unroll
        for (int r = 0; r < 16; r++) {
            int idx = r * 256 + t;
            int key = idx >> 6, dd = idx & 63;
            KVs[dd * TP + key] =
                f2tf(vb[(long)(bh * 576 + m0c + key) * 64 + dd]);
        }
        __syncthreads();
        const int r = wm * 16 + g;
#pragma unroll
        for (int kk = 0; kk < 64; kk += 8) {
            unsigned af[4];
            af[0] = __float_as_uint(S[r * SP + m0c + kk + tg]);
            af[1] = __float_as_uint(S[(r + 8) * SP + m0c + kk + tg]);
            af[2] = __float_as_uint(S[r * SP + m0c + kk + tg + 4]);
            af[3] = __float_as_uint(S[(r + 8) * SP + m0c + kk + tg + 4]);
#pragma unroll
            for (int ni = 0; ni < 4; ni++) {
                const int rn = wn * 32 + ni * 8 + g;
                unsigned bf[2];
                bf[0] = KVs[rn * TP + kk + tg];
                bf[1] = KVs[rn * TP + kk + tg + 4];
                mma8(o[ni], af, bf);
            }
        }
        __syncthreads();   // before next V overwrite
    }

    // epilogue: normalize by rowinv and store
    const int r0 = wm * 16 + g;
    const float inv0 = rowinv[r0], inv1 = rowinv[r0 + 8];
#pragma unroll
    for (int ni = 0; ni < 4; ni++) {
        const int c = wn * 32 + ni * 8 + 2 * tg;
        *(float2*)(ctx + (long)(b * 9216 + n0 + r0) * 512 + h * 64 + c) =
            make_float2(o[ni][0] * inv0, o[ni][1] * inv0);
        *(float2*)(ctx + (long)(b * 9216 + n0 + r0 + 8) * 512 + h * 64 + c) =
            make_float2(o[ni][2] * inv1, o[ni][3] * inv1);
    }
}

// ---------------------------------------------------------------------------
// Launch pipeline
// ---------------------------------------------------------------------------
extern "C" void kernel_launch(void* const* d_in, const int* in_sizes, int n_in,
                              void* d_out, int out_size)
{
    (void)in_sizes; (void)n_in; (void)out_size;
    const float* x      = (const float*)d_in[0];
    const float* w_q    = (const float*)d_in[1];
    const float* b_q    = (const float*)d_in[2];
    const float* w_kv   = (const float*)d_in[3];
    const float* b_kv   = (const float*)d_in[4];
    const float* w_proj = (const float*)d_in[5];
    const float* b_proj = (const float*)d_in[6];
    const float* w_sr   = (const float*)d_in[7];
    const float* b_sr   = (const float*)d_in[8];
    const float* ln_g   = (const float*)d_in[9];
    const float* ln_b   = (const float*)d_in[10];
    const float* lAq    = (const float*)d_in[11];
    const float* lBq    = (const float*)d_in[12];
    const float* lAv    = (const float*)d_in[13];
    const float* lBv    = (const float*)d_in[14];

    float *q, *t1, *xspre, *xs, *kv, *t2, *lv, *k, *v, *ctx, *im2c, *w2, *part;
    cudaGetSymbolAddress((void**)&q,     g_q);
    cudaGetSymbolAddress((void**)&t1,    g_t1);
    cudaGetSymbolAddress((void**)&xspre, g_xspre);
    cudaGetSymbolAddress((void**)&xs,    g_xs);
    cudaGetSymbolAddress((void**)&kv,    g_kv);
    cudaGetSymbolAddress((void**)&t2,    g_t2);
    cudaGetSymbolAddress((void**)&lv,    g_lv);
    cudaGetSymbolAddress((void**)&k,     g_k);
    cudaGetSymbolAddress((void**)&v,     g_v);
    cudaGetSymbolAddress((void**)&ctx,   g_ctx);
    cudaGetSymbolAddress((void**)&im2c,  g_im2c);
    cudaGetSymbolAddress((void**)&w2,    g_w2);
    cudaGetSymbolAddress((void**)&part,  g_part);

    dim3 blk(256);

    // conv prep
    reorder_w_kernel<<<16384, blk>>>(w_sr, w2);
    im2col_kernel<<<36864, blk>>>(x, im2c);
    // conv GEMM, 8-way split-K, hi/lo split-tf32 for accuracy
    gemm_tf32<1><<<dim3(8, 9, 8), blk>>>(1152, 512, 8192, im2c, 8192, w2, 8192,
                                         nullptr, nullptr, 1.f, nullptr, 512,
                                         1024, part);
    reduce_part<<<2304, blk>>>(part, b_sr, xspre, 589824, 512, 8, 589824);
    layernorm_kernel<<<1152, 128>>>(xspre, ln_g, ln_b, xs);

    // q = X Wq^T + b_q
    gemm_tf32<0><<<dim3(8, 144, 1), blk>>>(18432, 512, 512, x, 512, w_q, 512,
                                           b_q, nullptr, 1.f, q, 512, 512, nullptr);
    // t1 = X Aq^T  (N=32, SIMT)
    gemm_abt<<<dim3(1, 288), blk>>>(18432, 32, 512, x, 512, lAq, 512,
                                    nullptr, nullptr, 1.f, t1, 32);
    // q += (t1 Bq^T) * SCALING
    gemm_tf32<0><<<dim3(8, 144, 1), blk>>>(18432, 512, 32, t1, 32, lBq, 32,
                                           nullptr, q, SCALING, q, 512, 32, nullptr);

    // kv = xs Wkv^T + b_kv  (4-way split-K)
    gemm_tf32<0><<<dim3(16, 9, 4), blk>>>(1152, 1024, 512, xs, 512, w_kv, 512,
                                          nullptr, nullptr, 1.f, nullptr, 1024,
                                          128, part);
    reduce_part<<<4608, blk>>>(part, b_kv, kv, 1179648, 1024, 4, 1179648);

    // lv = (xs Av^T) Bv^T * SCALING
    gemm_abt<<<dim3(1, 18), blk>>>(1152, 32, 512, xs, 512, lAv, 512,
                                   nullptr, nullptr, 1.f, t2, 32);
    gemm_tf32<0><<<dim3(8, 9, 1), blk>>>(1152, 512, 32, t2, 32, lBv, 32,
                                         nullptr, nullptr, SCALING, lv, 512,
                                         32, nullptr);

    build_kv<<<2304, blk>>>(kv, lv, k, v);

    cudaFuncSetAttribute(attn_mma,
                         cudaFuncAttributeMaxDynamicSharedMemorySize, ATTN_SMEM);
    attn_mma<<<dim3(144, 16), blk, ATTN_SMEM>>>(q, k, v, ctx);

    // out = ctx Wp^T + b_proj
    gemm_tf32<0><<<dim3(8, 144, 1), blk>>>(18432, 512, 512, ctx, 512, w_proj, 512,
                                           b_proj, nullptr, 1.f, (float*)d_out,
                                           512, 512, nullptr);
}

// round 4
// speedup vs baseline: 2.3134x; 1.0964x over previous
#include <cuda_runtime.h>
#include <math.h>

// B=2, N=9216, C=512, HEAD=8, d=64, SR=4, H=W=96 -> Nkv=576, R=32
#define SCALING 0.125f

// ---------------------------------------------------------------------------
// Scratch
// ---------------------------------------------------------------------------
__device__ float g_q    [9437184];  // (B,N,C)
__device__ float g_xspre[589824];   // (B*576, 512)
__device__ float g_xs   [589824];
__device__ float g_kv   [1179648];  // (B*576, 1024)
__device__ float g_t2   [36864];
__device__ float g_lv   [589824];
__device__ float g_k    [589824];   // (B*H,576,64)
__device__ float g_v    [589824];
__device__ float g_ctx  [9437184];
__device__ float g_im2c [9437184];  // 1152x8192 im2col; later reused as t1p (18432x64)
__device__ float g_w2   [4194304];  // 512 x 8192 reordered conv weight
__device__ float g_part [4718592];  // split-K partials
__device__ float g_lAqp [32768];    // 64 x 512 padded lora_A_q
__device__ float g_Bq2  [16384];    // 512 x 32 prescaled lora_B_q

// ---------------------------------------------------------------------------
// tf32 helpers
// ---------------------------------------------------------------------------
__device__ __forceinline__ unsigned f2tf(float x) {
    unsigned u;
    asm("cvt.rna.tf32.f32 %0, %1;" : "=r"(u) : "f"(x));
    return u;
}
__device__ __forceinline__ void mma8(float* c, const unsigned* a, const unsigned* b) {
    asm volatile(
        "mma.sync.aligned.m16n8k8.row.col.f32.tf32.tf32.f32 "
        "{%0,%1,%2,%3}, {%4,%5,%6,%7}, {%8,%9}, {%0,%1,%2,%3};"
        : "+f"(c[0]), "+f"(c[1]), "+f"(c[2]), "+f"(c[3])
        : "r"(a[0]), "r"(a[1]), "r"(a[2]), "r"(a[3]),
          "r"(b[0]), "r"(b[1]));
}

// ---------------------------------------------------------------------------
// tf32 tensor-core GEMM:  C = scale * (A @ B^T [+ A2 @ B2^T]) (+bias) (+Cin)
// A: MxK row-major, B: NxK row-major. REQUIRES M%128==0, N%64==0, K%16==0.
// BM=128, BN=64, BK=16; 256 threads; warps 4(M)x2(N), each 32x32.
// gridDim.z>1: raw partials to `part`. SPLIT=1: hi/lo tf32 (3 mmas).
// Optional second operand pair (A2,B2,K2) appended to the K loop (SPLIT=0 path).
// ---------------------------------------------------------------------------
template <int SPLIT>
__global__ void __launch_bounds__(256)
gemm_tf32(int M, int N, int K,
          const float* __restrict__ A, int lda,
          const float* __restrict__ B, int ldb,
          const float* __restrict__ bias,
          const float* __restrict__ Cin,
          float scale,
          float* __restrict__ C, int ldc,
          int kchunk, float* __restrict__ part,
          const float* __restrict__ A2, int lda2,
          const float* __restrict__ B2, int ldb2, int K2)
{
    __shared__ unsigned As[SPLIT + 1][128][20];
    __shared__ unsigned Bs[SPLIT + 1][64][20];
    const int t    = threadIdx.x;
    const int lane = t & 31, w = t >> 5;
    const int g  = lane >> 2, tg = lane & 3;
    const int wm = w >> 1,  wn = w & 1;
    const long m0 = (long)blockIdx.y * 128;
    const int  n0 = blockIdx.x * 64;
    const int  kb = blockIdx.z * kchunk;

    const int ar  = t >> 2;
    const int kq4 = (t & 3) * 4;

    float acc[2][4][4];
#pragma unroll
    for (int mi = 0; mi < 2; mi++)
#pragma unroll
        for (int ni = 0; ni < 4; ni++)
#pragma unroll
            for (int c = 0; c < 4; c++) acc[mi][ni][c] = 0.f;

    const float* Ap0 = A + (m0 + ar) * lda + kq4;
    const float* Ap1 = A + (m0 + ar + 64) * lda + kq4;
    const float* Bp  = B + (long)(n0 + ar) * ldb + kq4;

    for (int k0 = kb; k0 < kb + kchunk; k0 += 16) {
        float4 av0 = *(const float4*)(Ap0 + k0);
        float4 av1 = *(const float4*)(Ap1 + k0);
        float4 bv  = *(const float4*)(Bp  + k0);
        __syncthreads();
        {
            float a0[4] = {av0.x, av0.y, av0.z, av0.w};
            float a1[4] = {av1.x, av1.y, av1.z, av1.w};
            float bb[4] = {bv.x,  bv.y,  bv.z,  bv.w};
#pragma unroll
            for (int c = 0; c < 4; c++) {
                unsigned h0 = f2tf(a0[c]), h1 = f2tf(a1[c]), hb = f2tf(bb[c]);
                As[0][ar][kq4 + c]      = h0;
                As[0][ar + 64][kq4 + c] = h1;
                Bs[0][ar][kq4 + c]      = hb;
                if (SPLIT) {
                    As[SPLIT][ar][kq4 + c]      = f2tf(a0[c] - __uint_as_float(h0));
                    As[SPLIT][ar + 64][kq4 + c] = f2tf(a1[c] - __uint_as_float(h1));
                    Bs[SPLIT][ar][kq4 + c]      = f2tf(bb[c] - __uint_as_float(hb));
                }
            }
        }
        __syncthreads();
#pragma unroll
        for (int kk = 0; kk < 16; kk += 8) {
            unsigned af[2][4], bf[4][2];
#pragma unroll
            for (int mi = 0; mi < 2; mi++) {
                const int r = wm * 32 + mi * 16 + g;
                af[mi][0] = As[0][r][kk + tg];
                af[mi][1] = As[0][r + 8][kk + tg];
                af[mi][2] = As[0][r][kk + tg + 4];
                af[mi][3] = As[0][r + 8][kk + tg + 4];
            }
#pragma unroll
            for (int ni = 0; ni < 4; ni++) {
                const int rn = wn * 32 + ni * 8 + g;
                bf[ni][0] = Bs[0][rn][kk + tg];
                bf[ni][1] = Bs[0][rn][kk + tg + 4];
            }
#pragma unroll
            for (int mi = 0; mi < 2; mi++)
#pragma unroll
                for (int ni = 0; ni < 4; ni++)
                    mma8(acc[mi][ni], af[mi], bf[ni]);
            if (SPLIT) {
                unsigned afl[2][4], bfl[4][2];
#pragma unroll
                for (int mi = 0; mi < 2; mi++) {
                    const int r = wm * 32 + mi * 16 + g;
                    afl[mi][0] = As[SPLIT][r][kk + tg];
                    afl[mi][1] = As[SPLIT][r + 8][kk + tg];
                    afl[mi][2] = As[SPLIT][r][kk + tg + 4];
                    afl[mi][3] = As[SPLIT][r + 8][kk + tg + 4];
                }
#pragma unroll
                for (int ni = 0; ni < 4; ni++) {
                    const int rn = wn * 32 + ni * 8 + g;
                    bfl[ni][0] = Bs[SPLIT][rn][kk + tg];
                    bfl[ni][1] = Bs[SPLIT][rn][kk + tg + 4];
                }
#pragma unroll
                for (int mi = 0; mi < 2; mi++)
#pragma unroll
                    for (int ni = 0; ni < 4; ni++) {
                        mma8(acc[mi][ni], af[mi],  bfl[ni]);
                        mma8(acc[mi][ni], afl[mi], bf[ni]);
                    }
            }
        }
    }

    // Optional fused second operand pair (LoRA tail), SPLIT=0 path only.
    if (!SPLIT && K2 > 0) {
        const float* A2p0 = A2 + (m0 + ar) * lda2 + kq4;
        const float* A2p1 = A2 + (m0 + ar + 64) * lda2 + kq4;
        const float* B2p  = B2 + (long)(n0 + ar) * ldb2 + kq4;
        for (int k0 = 0; k0 < K2; k0 += 16) {
            float4 av0 = *(const float4*)(A2p0 + k0);
            float4 av1 = *(const float4*)(A2p1 + k0);
            float4 bv  = *(const float4*)(B2p  + k0);
            __syncthreads();
            As[0][ar][kq4 + 0]      = f2tf(av0.x);
            As[0][ar][kq4 + 1]      = f2tf(av0.y);
            As[0][ar][kq4 + 2]      = f2tf(av0.z);
            As[0][ar][kq4 + 3]      = f2tf(av0.w);
            As[0][ar + 64][kq4 + 0] = f2tf(av1.x);
            As[0][ar + 64][kq4 + 1] = f2tf(av1.y);
            As[0][ar + 64][kq4 + 2] = f2tf(av1.z);
            As[0][ar + 64][kq4 + 3] = f2tf(av1.w);
            Bs[0][ar][kq4 + 0]      = f2tf(bv.x);
            Bs[0][ar][kq4 + 1]      = f2tf(bv.y);
            Bs[0][ar][kq4 + 2]      = f2tf(bv.z);
            Bs[0][ar][kq4 + 3]      = f2tf(bv.w);
            __syncthreads();
#pragma unroll
            for (int kk = 0; kk < 16; kk += 8) {
                unsigned af[2][4], bf[4][2];
#pragma unroll
                for (int mi = 0; mi < 2; mi++) {
                    const int r = wm * 32 + mi * 16 + g;
                    af[mi][0] = As[0][r][kk + tg];
                    af[mi][1] = As[0][r + 8][kk + tg];
                    af[mi][2] = As[0][r][kk + tg + 4];
                    af[mi][3] = As[0][r + 8][kk + tg + 4];
                }
#pragma unroll
                for (int ni = 0; ni < 4; ni++) {
                    const int rn = wn * 32 + ni * 8 + g;
                    bf[ni][0] = Bs[0][rn][kk + tg];
                    bf[ni][1] = Bs[0][rn][kk + tg + 4];
                }
#pragma unroll
                for (int mi = 0; mi < 2; mi++)
#pragma unroll
                    for (int ni = 0; ni < 4; ni++)
                        mma8(acc[mi][ni], af[mi], bf[ni]);
            }
        }
    }

    if (gridDim.z == 1) {
#pragma unroll
        for (int mi = 0; mi < 2; mi++) {
            const long r0 = m0 + wm * 32 + mi * 16 + g;
            const long r1 = r0 + 8;
#pragma unroll
            for (int ni = 0; ni < 4; ni++) {
                const int c = n0 + wn * 32 + ni * 8 + 2 * tg;
                float v00 = scale * acc[mi][ni][0];
                float v01 = scale * acc[mi][ni][1];
                float v10 = scale * acc[mi][ni][2];
                float v11 = scale * acc[mi][ni][3];
                if (bias) {
                    float b0 = bias[c], b1 = bias[c + 1];
                    v00 += b0; v01 += b1; v10 += b0; v11 += b1;
                }
                if (Cin) {
                    v00 += Cin[r0 * ldc + c]; v01 += Cin[r0 * ldc + c + 1];
                    v10 += Cin[r1 * ldc + c]; v11 += Cin[r1 * ldc + c + 1];
                }
                *(float2*)(C + r0 * ldc + c) = make_float2(v00, v01);
                *(float2*)(C + r1 * ldc + c) = make_float2(v10, v11);
            }
        }
    } else {
        float* P = part + (long)blockIdx.z * M * ldc;
#pragma unroll
        for (int mi = 0; mi < 2; mi++) {
            const long r0 = m0 + wm * 32 + mi * 16 + g;
            const long r1 = r0 + 8;
#pragma unroll
            for (int ni = 0; ni < 4; ni++) {
                const int c = n0 + wn * 32 + ni * 8 + 2 * tg;
                *(float2*)(P + r0 * ldc + c) =
                    make_float2(acc[mi][ni][0], acc[mi][ni][1]);
                *(float2*)(P + r1 * ldc + c) =
                    make_float2(acc[mi][ni][2], acc[mi][ni][3]);
            }
        }
    }
}

// out[i] = bias[i % ldc] + sum_z part[z*zstride + i]
__global__ void reduce_part(const float* __restrict__ part,
                            const float* __restrict__ bias,
                            float* __restrict__ out,
                            int total, int ldc, int nz, long zstride)
{
    const int i = blockIdx.x * 256 + threadIdx.x;
    if (i >= total) return;
    float s = bias[i % ldc];
    for (int z = 0; z < nz; z++) s += part[(long)z * zstride + i];
    out[i] = s;
}

// w2[co][(i*4+j)*512 + ci] = w_sr[co][ci][i][j]
__global__ void reorder_w_kernel(const float* __restrict__ w,
                                 float* __restrict__ w2)
{
    const int tid = blockIdx.x * 256 + threadIdx.x;
    const int ci = tid & 511;
    const int s  = (tid >> 9) & 15;
    const int co = tid >> 13;
    w2[tid] = w[(long)co * 8192 + ci * 16 + s];
}

// im2col: A2[m][(i*4+j)*512+ci] = x[b, (4py+i)*96+4px+j, ci]
__global__ void im2col_kernel(const float* __restrict__ x,
                              float* __restrict__ out)
{
    const long tid = (long)blockIdx.x * 256 + threadIdx.x;
    const int ci = tid & 511;
    const int s  = ((int)(tid >> 9)) & 15;
    const int m  = (int)(tid >> 13);
    const int i = s >> 2, j = s & 3;
    const int b = m / 576, p = m % 576;
    const int py = p / 24, px = p % 24;
    out[tid] = x[((long)b * 9216 + (py * 4 + i) * 96 + px * 4 + j) * 512 + ci];
}

// pad lora_A_q to 64x512 (zeros) and prescale lora_B_q by SCALING
__global__ void prep_q_lora(const float* __restrict__ lAq,
                            const float* __restrict__ lBq,
                            float* __restrict__ lAqp,
                            float* __restrict__ Bq2)
{
    const int i = blockIdx.x * 256 + threadIdx.x;
    if (i < 64 * 512) lAqp[i] = (i < 32 * 512) ? lAq[i] : 0.f;
    if (i < 512 * 32) Bq2[i] = lBq[i] * SCALING;
}

// ---------------------------------------------------------------------------
// SIMT GEMM kept for tiny LoRA-A on xs (1152 x 32 x 512)
// ---------------------------------------------------------------------------
__global__ void gemm_abt(int M, int N, int K,
                         const float* __restrict__ A, int lda,
                         const float* __restrict__ Bm, int ldb,
                         const float* __restrict__ bias,
                         const float* __restrict__ Cin,
                         float scale,
                         float* __restrict__ C, int ldc)
{
    __shared__ float As[16 * 64];
    __shared__ float Bs[16 * 64];
    const int t  = threadIdx.x;
    const int ty = t >> 4, tx = t & 15;
    const int m0 = blockIdx.y * 64, n0 = blockIdx.x * 64;
    const int lr = t >> 2;
    const int lk = (t & 3) << 2;

    float acc[4][4];
#pragma unroll
    for (int i = 0; i < 4; i++)
#pragma unroll
        for (int j = 0; j < 4; j++) acc[i][j] = 0.f;

    const int gmL = m0 + lr;
    const int gnL = n0 + lr;

    for (int k0 = 0; k0 < K; k0 += 16) {
        float4 av = make_float4(0.f, 0.f, 0.f, 0.f);
        float4 bv = make_float4(0.f, 0.f, 0.f, 0.f);
        if (gmL < M) av = *(const float4*)(A  + (long)gmL * lda + k0 + lk);
        if (gnL < N) bv = *(const float4*)(Bm + (long)gnL * ldb + k0 + lk);
        __syncthreads();
        As[(lk + 0) * 64 + lr] = av.x; As[(lk + 1) * 64 + lr] = av.y;
        As[(lk + 2) * 64 + lr] = av.z; As[(lk + 3) * 64 + lr] = av.w;
        Bs[(lk + 0) * 64 + lr] = bv.x; Bs[(lk + 1) * 64 + lr] = bv.y;
        Bs[(lk + 2) * 64 + lr] = bv.z; Bs[(lk + 3) * 64 + lr] = bv.w;
        __syncthreads();
#pragma unroll
        for (int kk = 0; kk < 16; kk++) {
            float4 a4 = *(const float4*)(As + kk * 64 + ty * 4);
            float4 b4 = *(const float4*)(Bs + kk * 64 + tx * 4);
            float ar[4] = {a4.x, a4.y, a4.z, a4.w};
            float br[4] = {b4.x, b4.y, b4.z, b4.w};
#pragma unroll
            for (int i = 0; i < 4; i++)
#pragma unroll
                for (int j = 0; j < 4; j++)
                    acc[i][j] += ar[i] * br[j];
        }
    }

#pragma unroll
    for (int i = 0; i < 4; i++) {
        int gm = m0 + ty * 4 + i;
        if (gm >= M) continue;
#pragma unroll
        for (int j = 0; j < 4; j++) {
            int gn = n0 + tx * 4 + j;
            if (gn >= N) continue;
            float r = scale * acc[i][j];
            if (bias) r += bias[gn];
            if (Cin)  r += Cin[(long)gm * ldc + gn];
            C[(long)gm * ldc + gn] = r;
        }
    }
}

// ---------------------------------------------------------------------------
// LayerNorm over C=512
// ---------------------------------------------------------------------------
__global__ void layernorm_kernel(const float* __restrict__ in,
                                 const float* __restrict__ gam,
                                 const float* __restrict__ bet,
                                 float* __restrict__ out)
{
    const int row = blockIdx.x;
    const int t   = threadIdx.x;
    const float* x = in + (long)row * 512;
    float v0 = x[t], v1 = x[t + 128], v2 = x[t + 256], v3 = x[t + 384];
    float s  = v0 + v1 + v2 + v3;
    float s2 = v0 * v0 + v1 * v1 + v2 * v2 + v3 * v3;
#pragma unroll
    for (int o = 16; o > 0; o >>= 1) {
        s  += __shfl_xor_sync(0xffffffffu, s,  o);
        s2 += __shfl_xor_sync(0xffffffffu, s2, o);
    }
    __shared__ float ss[4], ss2[4];
    if ((t & 31) == 0) { ss[t >> 5] = s; ss2[t >> 5] = s2; }
    __syncthreads();
    s  = ss[0]  + ss[1]  + ss[2]  + ss[3];
    s2 = ss2[0] + ss2[1] + ss2[2] + ss2[3];
    const float mean = s * (1.f / 512.f);
    const float var  = s2 * (1.f / 512.f) - mean * mean;
    const float inv  = rsqrtf(var + 1e-5f);
    float* o = out + (long)row * 512;
    o[t]       = (v0 - mean) * inv * gam[t]       + bet[t];
    o[t + 128] = (v1 - mean) * inv * gam[t + 128] + bet[t + 128];
    o[t + 256] = (v2 - mean) * inv * gam[t + 256] + bet[t + 256];
    o[t + 384] = (v3 - mean) * inv * gam[t + 384] + bet[t + 384];
}

// ---------------------------------------------------------------------------
// k/v head split; v gets the raw-reshape LoRA fixup
// ---------------------------------------------------------------------------
__global__ void build_kv(const float* __restrict__ kv,
                         const float* __restrict__ lv,
                         float* __restrict__ k, float* __restrict__ v)
{
    const int idx = blockIdx.x * 256 + threadIdx.x;
    const int dd = idx & 63;
    const int m  = (idx >> 6) % 576;
    const int bh = idx / 36864;
    const int h  = bh & 7, b = bh >> 3;
    const long base = (long)(b * 576 + m) * 1024 + h * 64 + dd;
    k[idx] = kv[base];
    v[idx] = kv[base + 512] + lv[(long)b * 294912 + h * 36864 + m * 64 + dd];
}

// ---------------------------------------------------------------------------
// Flash-style tf32 attention. One block = 64 queries x one (b,h).
// Online softmax over 9 key chunks of 64. Smem ~70KB -> 2-3 CTAs/SM.
// 256 threads = 8 warps as 4(m) x 2(n).
// ---------------------------------------------------------------------------
#define TPa 68   // tile pitch (mod 32 == 4 -> conflict-free fragment loads)
#define ATTN_SMEM ((4 * 64 * TPa + 3 * 64) * 4)

__global__ void __launch_bounds__(256)
attn_flash(const float* __restrict__ qb,   // (B,N,512)
           const float* __restrict__ kb,   // (B*H,576,64)
           const float* __restrict__ vb,   // (B*H,576,64)
           float* __restrict__ ctx)        // (B,N,512)
{
    extern __shared__ float sm[];
    unsigned* Qs    = (unsigned*)sm;        // [q][dd]   64*TPa
    unsigned* Ks    = Qs + 64 * TPa;        // [key][dd] 64*TPa
    unsigned* Vs    = Ks + 64 * TPa;        // [dd][key] 64*TPa
    float*    Sc    = (float*)(Vs + 64 * TPa);  // [q][key] 64*TPa
    float*    m_run = Sc + 64 * TPa;        // 64
    float*    l_run = m_run + 64;           // 64
    float*    alf   = l_run + 64;           // 64

    const int t    = threadIdx.x;
    const int lane = t & 31, w = t >> 5;
    const int g  = lane >> 2, tg = lane & 3;
    const int wm = w >> 1,  wn = w & 1;
    const int bh = blockIdx.y, b = bh >> 3, h = bh & 7;
    const int n0 = blockIdx.x * 64;
    const int r0 = wm * 16 + g;

    // Q tile [q][dd] as tf32
#pragma unroll
    for (int r = 0; r < 16; r++) {
        int idx = r * 256 + t;
        int qq = idx >> 6, dd = idx & 63;
        Qs[qq * TPa + dd] = f2tf(qb[(long)(b * 9216 + n0 + qq) * 512 + h * 64 + dd]);
    }
    if (t < 64) { m_run[t] = -1e30f; l_run[t] = 0.f; }

    float O[4][4];
#pragma unroll
    for (int ni = 0; ni < 4; ni++)
#pragma unroll
        for (int c = 0; c < 4; c++) O[ni][c] = 0.f;

    for (int ch = 0; ch < 9; ch++) {
        const int m0c = ch * 64;
        __syncthreads();   // prev-chunk fragment loads done; safe to overwrite K/V
#pragma unroll
        for (int r = 0; r < 16; r++) {
            int idx = r * 256 + t;
            int key = idx >> 6, dd = idx & 63;
            float kvl = kb[(long)(bh * 576 + m0c + key) * 64 + dd];
            float vvl = vb[(long)(bh * 576 + m0c + key) * 64 + dd];
            Ks[key * TPa + dd] = f2tf(kvl);
            Vs[dd * TPa + key] = f2tf(vvl);
        }
        __syncthreads();

        // --- S chunk = (Q K^T) * 0.125 ---
        float acc[4][4];
#pragma unroll
        for (int ni = 0; ni < 4; ni++)
#pragma unroll
            for (int c = 0; c < 4; c++) acc[ni][c] = 0.f;
#pragma unroll
        for (int kk = 0; kk < 64; kk += 8) {
            unsigned af[4];
            af[0] = Qs[r0 * TPa + kk + tg];
            af[1] = Qs[(r0 + 8) * TPa + kk + tg];
            af[2] = Qs[r0 * TPa + kk + tg + 4];
            af[3] = Qs[(r0 + 8) * TPa + kk + tg + 4];
#pragma unroll
            for (int ni = 0; ni < 4; ni++) {
                const int rn = wn * 32 + ni * 8 + g;
                unsigned bf[2];
                bf[0] = Ks[rn * TPa + kk + tg];
                bf[1] = Ks[rn * TPa + kk + tg + 4];
                mma8(acc[ni], af, bf);
            }
        }
#pragma unroll
        for (int ni = 0; ni < 4; ni++) {
            const int c = wn * 32 + ni * 8 + 2 * tg;
            *(float2*)(Sc + r0 * TPa + c) =
                make_float2(acc[ni][0] * 0.125f, acc[ni][1] * 0.125f);
            *(float2*)(Sc + (r0 + 8) * TPa + c) =
                make_float2(acc[ni][2] * 0.125f, acc[ni][3] * 0.125f);
        }
        __syncthreads();

        // --- online softmax stats for this chunk ---
        {
            const int row = t >> 2, part = t & 3;
            float cm = -1e30f;
#pragma unroll
            for (int i = 0; i < 16; i++)
                cm = fmaxf(cm, Sc[row * TPa + 4 * i + part]);
            cm = fmaxf(cm, __shfl_xor_sync(0xffffffffu, cm, 1));
            cm = fmaxf(cm, __shfl_xor_sync(0xffffffffu, cm, 2));
            const float nm = fmaxf(m_run[row], cm);
            float sum = 0.f;
#pragma unroll
            for (int i = 0; i < 16; i++) {
                float e  = __expf(Sc[row * TPa + 4 * i + part] - nm);
                float et = __uint_as_float(f2tf(e));
                Sc[row * TPa + 4 * i + part] = et;
                sum += et;
            }
            sum += __shfl_xor_sync(0xffffffffu, sum, 1);
            sum += __shfl_xor_sync(0xffffffffu, sum, 2);
            if (part == 0) {
                float al = __expf(m_run[row] - nm);
                alf[row] = al;
                l_run[row] = l_run[row] * al + sum;
                m_run[row] = nm;
            }
        }
        __syncthreads();

        // --- rescale O and accumulate P @ V ---
        {
            const float a0 = alf[r0], a1 = alf[r0 + 8];
#pragma unroll
            for (int ni = 0; ni < 4; ni++) {
                O[ni][0] *= a0; O[ni][1] *= a0;
                O[ni][2] *= a1; O[ni][3] *= a1;
            }
        }
#pragma unroll
        for (int kk = 0; kk < 64; kk += 8) {
            unsigned af[4];
            af[0] = __float_as_uint(Sc[r0 * TPa + kk + tg]);
            af[1] = __float_as_uint(Sc[(r0 + 8) * TPa + kk + tg]);
            af[2] = __float_as_uint(Sc[r0 * TPa + kk + tg + 4]);
            af[3] = __float_as_uint(Sc[(r0 + 8) * TPa + kk + tg + 4]);
#pragma unroll
            for (int ni = 0; ni < 4; ni++) {
                const int rn = wn * 32 + ni * 8 + g;
                unsigned bf[2];
                bf[0] = Vs[rn * TPa + kk + tg];
                bf[1] = Vs[rn * TPa + kk + tg + 4];
                mma8(O[ni], af, bf);
            }
        }
    }

    const float inv0 = 1.f / l_run[r0];
    const float inv1 = 1.f / l_run[r0 + 8];
#pragma unroll
    for (int ni = 0; ni < 4; ni++) {
        const int c = wn * 32 + ni * 8 + 2 * tg;
        *(float2*)(ctx + (long)(b * 9216 + n0 + r0) * 512 + h * 64 + c) =
            make_float2(O[ni][0] * inv0, O[ni][1] * inv0);
        *(float2*)(ctx + (long)(b * 9216 + n0 + r0 + 8) * 512 + h * 64 + c) =
            make_float2(O[ni][2] * inv1, O[ni][3] * inv1);
    }
}

// ---------------------------------------------------------------------------
// Launch pipeline
// ---------------------------------------------------------------------------
extern "C" void kernel_launch(void* const* d_in, const int* in_sizes, int n_in,
                              void* d_out, int out_size)
{
    (void)in_sizes; (void)n_in; (void)out_size;
    const float* x      = (const float*)d_in[0];
    const float* w_q    = (const float*)d_in[1];
    const float* b_q    = (const float*)d_in[2];
    const float* w_kv   = (const float*)d_in[3];
    const float* b_kv   = (const float*)d_in[4];
    const float* w_proj = (const float*)d_in[5];
    const float* b_proj = (const float*)d_in[6];
    const float* w_sr   = (const float*)d_in[7];
    const float* b_sr   = (const float*)d_in[8];
    const float* ln_g   = (const float*)d_in[9];
    const float* ln_b   = (const float*)d_in[10];
    const float* lAq    = (const float*)d_in[11];
    const float* lBq    = (const float*)d_in[12];
    const float* lAv    = (const float*)d_in[13];
    const float* lBv    = (const float*)d_in[14];

    float *q, *xspre, *xs, *kv, *t2, *lv, *k, *v, *ctx, *im2c, *w2, *part;
    float *lAqp, *Bq2;
    cudaGetSymbolAddress((void**)&q,     g_q);
    cudaGetSymbolAddress((void**)&xspre, g_xspre);
    cudaGetSymbolAddress((void**)&xs,    g_xs);
    cudaGetSymbolAddress((void**)&kv,    g_kv);
    cudaGetSymbolAddress((void**)&t2,    g_t2);
    cudaGetSymbolAddress((void**)&lv,    g_lv);
    cudaGetSymbolAddress((void**)&k,     g_k);
    cudaGetSymbolAddress((void**)&v,     g_v);
    cudaGetSymbolAddress((void**)&ctx,   g_ctx);
    cudaGetSymbolAddress((void**)&im2c,  g_im2c);
    cudaGetSymbolAddress((void**)&w2,    g_w2);
    cudaGetSymbolAddress((void**)&part,  g_part);
    cudaGetSymbolAddress((void**)&lAqp,  g_lAqp);
    cudaGetSymbolAddress((void**)&Bq2,   g_Bq2);

    dim3 blk(256);

    // conv prep + lora prep
    reorder_w_kernel<<<16384, blk>>>(w_sr, w2);
    im2col_kernel<<<36864, blk>>>(x, im2c);
    prep_q_lora<<<128, blk>>>(lAq, lBq, lAqp, Bq2);

    // conv GEMM, 8-way split-K, hi/lo split-tf32 for accuracy
    gemm_tf32<1><<<dim3(8, 9, 8), blk>>>(1152, 512, 8192, im2c, 8192, w2, 8192,
                                         nullptr, nullptr, 1.f, nullptr, 512,
                                         1024, part, nullptr, 0, nullptr, 0, 0);
    reduce_part<<<2304, blk>>>(part, b_sr, xspre, 589824, 512, 8, 589824);
    layernorm_kernel<<<1152, 128>>>(xspre, ln_g, ln_b, xs);

    // t1p = X @ lAqp^T  (18432 x 64 x 512) -> reuse im2c (conv gemm done)
    float* t1p = im2c;
    gemm_tf32<0><<<dim3(1, 144, 1), blk>>>(18432, 64, 512, x, 512, lAqp, 512,
                                           nullptr, nullptr, 1.f, t1p, 64,
                                           512, nullptr, nullptr, 0, nullptr, 0, 0);
    // q = X Wq^T + b_q + t1p[:, :32] @ Bq2^T  (LoRA fused into K loop)
    gemm_tf32<0><<<dim3(8, 144, 1), blk>>>(18432, 512, 512, x, 512, w_q, 512,
                                           b_q, nullptr, 1.f, q, 512,
                                           512, nullptr, t1p, 64, Bq2, 32, 32);

    // kv = xs Wkv^T + b_kv  (4-way split-K)
    gemm_tf32<0><<<dim3(16, 9, 4), blk>>>(1152, 1024, 512, xs, 512, w_kv, 512,
                                          nullptr, nullptr, 1.f, nullptr, 1024,
                                          128, part, nullptr, 0, nullptr, 0, 0);
    reduce_part<<<4608, blk>>>(part, b_kv, kv, 1179648, 1024, 4, 1179648);

    // lv = (xs Av^T) Bv^T * SCALING
    gemm_abt<<<dim3(1, 18), blk>>>(1152, 32, 512, xs, 512, lAv, 512,
                                   nullptr, nullptr, 1.f, t2, 32);
    gemm_tf32<0><<<dim3(8, 9, 1), blk>>>(1152, 512, 32, t2, 32, lBv, 32,
                                         nullptr, nullptr, SCALING, lv, 512,
                                         32, nullptr, nullptr, 0, nullptr, 0, 0);

    build_kv<<<2304, blk>>>(kv, lv, k, v);

    cudaFuncSetAttribute(attn_flash,
                         cudaFuncAttributeMaxDynamicSharedMemorySize, ATTN_SMEM);
    attn_flash<<<dim3(144, 16), blk, ATTN_SMEM>>>(q, k, v, ctx);

    // out = ctx Wp^T + b_proj
    gemm_tf32<0><<<dim3(8, 144, 1), blk>>>(18432, 512, 512, ctx, 512, w_proj, 512,
                                           b_proj, nullptr, 1.f, (float*)d_out,
                                           512, 512, nullptr, nullptr, 0, nullptr, 0, 0);
}

// round 5
// speedup vs baseline: 3.2557x; 1.4073x over previous
#include <cuda_runtime.h>
#include <math.h>

// B=2, N=9216, C=512, HEAD=8, d=64, SR=4, H=W=96 -> Nkv=576, R=32
#define SCALING 0.125f

// ---------------------------------------------------------------------------
// Scratch
// ---------------------------------------------------------------------------
__device__ float g_q    [9437184];  // (B,N,C)
__device__ float g_xspre[589824];   // (B*576, 512)
__device__ float g_xs   [589824];
__device__ float g_kv   [1179648];  // (B*576, 1024)
__device__ float g_t2   [36864];
__device__ float g_lv   [589824];
__device__ float g_k    [589824];   // (B*H,576,64)
__device__ float g_v    [589824];
__device__ float g_ctx  [9437184];
__device__ float g_t1p  [1179648];  // 18432 x 64 padded lora-q intermediate
__device__ float g_w2   [4194304];  // 512 x 8192 reordered conv weight
__device__ float g_part [4718592];  // split-K partials
__device__ float g_lAqp [32768];    // 64 x 512 padded lora_A_q
__device__ float g_Bq2  [16384];    // 512 x 32 prescaled lora_B_q

// ---------------------------------------------------------------------------
// tf32 helpers
// ---------------------------------------------------------------------------
__device__ __forceinline__ unsigned f2tf(float x) {
    unsigned u;
    asm("cvt.rna.tf32.f32 %0, %1;" : "=r"(u) : "f"(x));
    return u;
}
__device__ __forceinline__ void mma8(float* c, const unsigned* a, const unsigned* b) {
    asm volatile(
        "mma.sync.aligned.m16n8k8.row.col.f32.tf32.tf32.f32 "
        "{%0,%1,%2,%3}, {%4,%5,%6,%7}, {%8,%9}, {%0,%1,%2,%3};"
        : "+f"(c[0]), "+f"(c[1]), "+f"(c[2]), "+f"(c[3])
        : "r"(a[0]), "r"(a[1]), "r"(a[2]), "r"(a[3]),
          "r"(b[0]), "r"(b[1]));
}

// ---------------------------------------------------------------------------
// tf32 tensor-core GEMM:  C = scale * (A @ B^T [+ A2 @ B2^T]) (+bias)
// A: MxK row-major, B: NxK row-major. REQUIRES M%128==0, N%BN==0, K%16==0.
// BM=128, BN in {64,128}, BK=16; 256 threads; warps 4(M)x2(N).
// Warp tile: 32 x (BN/2)  ->  NI = BN/16 n-fragments per warp.
// gridDim.z>1: raw partials to `part`.
// CONV=1: A is gathered from x with the SR-conv im2col mapping
//   (row m = b*576+py*24+px ; k = (i*4+j)*512+ci -> x[b,(4py+i)*96+4px+j,ci]).
// Optional second operand pair (A2,B2,K2) appended to the K loop.
// ---------------------------------------------------------------------------
template <int BN, int CONV>
__global__ void __launch_bounds__(256, 2)
gemm_tf32(int M, int N, int K,
          const float* __restrict__ A, int lda,
          const float* __restrict__ B, int ldb,
          const float* __restrict__ bias,
          float scale,
          float* __restrict__ C, int ldc,
          int kchunk, float* __restrict__ part,
          const float* __restrict__ A2, int lda2,
          const float* __restrict__ B2, int ldb2, int K2)
{
    constexpr int NI = BN / 16;           // n-fragments per warp
    __shared__ unsigned As[128][20];
    __shared__ unsigned Bs[BN][20];
    const int t    = threadIdx.x;
    const int lane = t & 31, w = t >> 5;
    const int g  = lane >> 2, tg = lane & 3;
    const int wm = w >> 1,  wn = w & 1;
    const long m0 = (long)blockIdx.y * 128;
    const int  n0 = blockIdx.x * BN;
    const int  kb = blockIdx.z * kchunk;

    const int ar  = t >> 2;            // loader row (and +64)
    const int kq4 = (t & 3) * 4;       // loader k sub-quad

    float acc[2][NI][4];
#pragma unroll
    for (int mi = 0; mi < 2; mi++)
#pragma unroll
        for (int ni = 0; ni < NI; ni++)
#pragma unroll
            for (int c = 0; c < 4; c++) acc[mi][ni][c] = 0.f;

    // A addressing
    const float* Ap0 = nullptr;
    const float* Ap1 = nullptr;
    long convRow0 = 0, convRow1 = 0;
    if (CONV) {
        int m = (int)m0 + ar;
        int b = m / 576, p = m % 576, py = p / 24, px = p % 24;
        convRow0 = (long)b * 9216 + (py * 4) * 96 + px * 4;
        m = (int)m0 + ar + 64;
        b = m / 576; p = m % 576; py = p / 24; px = p % 24;
        convRow1 = (long)b * 9216 + (py * 4) * 96 + px * 4;
    } else {
        Ap0 = A + (m0 + ar) * lda + kq4;
        Ap1 = A + (m0 + ar + 64) * lda + kq4;
    }
    const float* Bp0 = B + (long)(n0 + ar) * ldb + kq4;
    const float* Bp1 = (BN == 128) ? B + (long)(n0 + ar + 64) * ldb + kq4 : nullptr;

    for (int k0 = kb; k0 < kb + kchunk; k0 += 16) {
        float4 av0, av1, bv0, bv1;
        if (CONV) {
            const int s  = k0 >> 9;        // tap index 0..15
            const int ii = s >> 2, jj = s & 3;
            const int ci = (k0 & 511) + kq4;
            av0 = *(const float4*)(A + (convRow0 + ii * 96 + jj) * 512 + ci);
            av1 = *(const float4*)(A + (convRow1 + ii * 96 + jj) * 512 + ci);
        } else {
            av0 = *(const float4*)(Ap0 + k0);
            av1 = *(const float4*)(Ap1 + k0);
        }
        bv0 = *(const float4*)(Bp0 + k0);
        if (BN == 128) bv1 = *(const float4*)(Bp1 + k0);
        __syncthreads();
        {
            uint4 u;
            u.x = f2tf(av0.x); u.y = f2tf(av0.y); u.z = f2tf(av0.z); u.w = f2tf(av0.w);
            *(uint4*)&As[ar][kq4] = u;
            u.x = f2tf(av1.x); u.y = f2tf(av1.y); u.z = f2tf(av1.z); u.w = f2tf(av1.w);
            *(uint4*)&As[ar + 64][kq4] = u;
            u.x = f2tf(bv0.x); u.y = f2tf(bv0.y); u.z = f2tf(bv0.z); u.w = f2tf(bv0.w);
            *(uint4*)&Bs[ar][kq4] = u;
            if (BN == 128) {
                u.x = f2tf(bv1.x); u.y = f2tf(bv1.y);
                u.z = f2tf(bv1.z); u.w = f2tf(bv1.w);
                *(uint4*)&Bs[ar + 64][kq4] = u;
            }
        }
        __syncthreads();
#pragma unroll
        for (int kk = 0; kk < 16; kk += 8) {
            unsigned af[2][4], bf[NI][2];
#pragma unroll
            for (int mi = 0; mi < 2; mi++) {
                const int r = wm * 32 + mi * 16 + g;
                af[mi][0] = As[r][kk + tg];
                af[mi][1] = As[r + 8][kk + tg];
                af[mi][2] = As[r][kk + tg + 4];
                af[mi][3] = As[r + 8][kk + tg + 4];
            }
#pragma unroll
            for (int ni = 0; ni < NI; ni++) {
                const int rn = wn * (BN / 2) + ni * 8 + g;
                bf[ni][0] = Bs[rn][kk + tg];
                bf[ni][1] = Bs[rn][kk + tg + 4];
            }
#pragma unroll
            for (int mi = 0; mi < 2; mi++)
#pragma unroll
                for (int ni = 0; ni < NI; ni++)
                    mma8(acc[mi][ni], af[mi], bf[ni]);
        }
    }

    // Optional fused second operand pair (LoRA tail)
    if (K2 > 0) {
        const float* A2p0 = A2 + (m0 + ar) * lda2 + kq4;
        const float* A2p1 = A2 + (m0 + ar + 64) * lda2 + kq4;
        const float* B2p0 = B2 + (long)(n0 + ar) * ldb2 + kq4;
        const float* B2p1 = (BN == 128) ? B2 + (long)(n0 + ar + 64) * ldb2 + kq4
                                        : nullptr;
        for (int k0 = 0; k0 < K2; k0 += 16) {
            float4 av0 = *(const float4*)(A2p0 + k0);
            float4 av1 = *(const float4*)(A2p1 + k0);
            float4 bv0 = *(const float4*)(B2p0 + k0);
            float4 bv1;
            if (BN == 128) bv1 = *(const float4*)(B2p1 + k0);
            __syncthreads();
            uint4 u;
            u.x = f2tf(av0.x); u.y = f2tf(av0.y); u.z = f2tf(av0.z); u.w = f2tf(av0.w);
            *(uint4*)&As[ar][kq4] = u;
            u.x = f2tf(av1.x); u.y = f2tf(av1.y); u.z = f2tf(av1.z); u.w = f2tf(av1.w);
            *(uint4*)&As[ar + 64][kq4] = u;
            u.x = f2tf(bv0.x); u.y = f2tf(bv0.y); u.z = f2tf(bv0.z); u.w = f2tf(bv0.w);
            *(uint4*)&Bs[ar][kq4] = u;
            if (BN == 128) {
                u.x = f2tf(bv1.x); u.y = f2tf(bv1.y);
                u.z = f2tf(bv1.z); u.w = f2tf(bv1.w);
                *(uint4*)&Bs[ar + 64][kq4] = u;
            }
            __syncthreads();
#pragma unroll
            for (int kk = 0; kk < 16; kk += 8) {
                unsigned af[2][4], bf[NI][2];
#pragma unroll
                for (int mi = 0; mi < 2; mi++) {
                    const int r = wm * 32 + mi * 16 + g;
                    af[mi][0] = As[r][kk + tg];
                    af[mi][1] = As[r + 8][kk + tg];
                    af[mi][2] = As[r][kk + tg + 4];
                    af[mi][3] = As[r + 8][kk + tg + 4];
                }
#pragma unroll
                for (int ni = 0; ni < NI; ni++) {
                    const int rn = wn * (BN / 2) + ni * 8 + g;
                    bf[ni][0] = Bs[rn][kk + tg];
                    bf[ni][1] = Bs[rn][kk + tg + 4];
                }
#pragma unroll
                for (int mi = 0; mi < 2; mi++)
#pragma unroll
                    for (int ni = 0; ni < NI; ni++)
                        mma8(acc[mi][ni], af[mi], bf[ni]);
            }
        }
    }

    if (gridDim.z == 1) {
#pragma unroll
        for (int mi = 0; mi < 2; mi++) {
            const long r0 = m0 + wm * 32 + mi * 16 + g;
            const long r1 = r0 + 8;
#pragma unroll
            for (int ni = 0; ni < NI; ni++) {
                const int c = n0 + wn * (BN / 2) + ni * 8 + 2 * tg;
                float v00 = scale * acc[mi][ni][0];
                float v01 = scale * acc[mi][ni][1];
                float v10 = scale * acc[mi][ni][2];
                float v11 = scale * acc[mi][ni][3];
                if (bias) {
                    float b0 = bias[c], b1 = bias[c + 1];
                    v00 += b0; v01 += b1; v10 += b0; v11 += b1;
                }
                *(float2*)(C + r0 * ldc + c) = make_float2(v00, v01);
                *(float2*)(C + r1 * ldc + c) = make_float2(v10, v11);
            }
        }
    } else {
        float* P = part + (long)blockIdx.z * M * ldc;
#pragma unroll
        for (int mi = 0; mi < 2; mi++) {
            const long r0 = m0 + wm * 32 + mi * 16 + g;
            const long r1 = r0 + 8;
#pragma unroll
            for (int ni = 0; ni < NI; ni++) {
                const int c = n0 + wn * (BN / 2) + ni * 8 + 2 * tg;
                *(float2*)(P + r0 * ldc + c) =
                    make_float2(acc[mi][ni][0], acc[mi][ni][1]);
                *(float2*)(P + r1 * ldc + c) =
                    make_float2(acc[mi][ni][2], acc[mi][ni][3]);
            }
        }
    }
}

// out[i] = bias[i % ldc] + sum_z part[z*zstride + i]
__global__ void reduce_part(const float* __restrict__ part,
                            const float* __restrict__ bias,
                            float* __restrict__ out,
                            int total, int ldc, int nz, long zstride)
{
    const int i = blockIdx.x * 256 + threadIdx.x;
    if (i >= total) return;
    float s = bias[i % ldc];
    for (int z = 0; z < nz; z++) s += part[(long)z * zstride + i];
    out[i] = s;
}

// w2[co][(i*4+j)*512 + ci] = w_sr[co][ci][i][j]
__global__ void reorder_w_kernel(const float* __restrict__ w,
                                 float* __restrict__ w2)
{
    const int tid = blockIdx.x * 256 + threadIdx.x;
    const int ci = tid & 511;
    const int s  = (tid >> 9) & 15;
    const int co = tid >> 13;
    w2[tid] = w[(long)co * 8192 + ci * 16 + s];
}

// pad lora_A_q to 64x512 (zeros) and prescale lora_B_q by SCALING
__global__ void prep_q_lora(const float* __restrict__ lAq,
                            const float* __restrict__ lBq,
                            float* __restrict__ lAqp,
                            float* __restrict__ Bq2)
{
    const int i = blockIdx.x * 256 + threadIdx.x;
    if (i < 64 * 512) lAqp[i] = (i < 32 * 512) ? lAq[i] : 0.f;
    if (i < 512 * 32) Bq2[i] = lBq[i] * SCALING;
}

// ---------------------------------------------------------------------------
// SIMT GEMM kept for tiny LoRA-A on xs (1152 x 32 x 512)
// ---------------------------------------------------------------------------
__global__ void gemm_abt(int M, int N, int K,
                         const float* __restrict__ A, int lda,
                         const float* __restrict__ Bm, int ldb,
                         float* __restrict__ C, int ldc)
{
    __shared__ float As[16 * 64];
    __shared__ float Bs[16 * 64];
    const int t  = threadIdx.x;
    const int ty = t >> 4, tx = t & 15;
    const int m0 = blockIdx.y * 64, n0 = blockIdx.x * 64;
    const int lr = t >> 2;
    const int lk = (t & 3) << 2;

    float acc[4][4];
#pragma unroll
    for (int i = 0; i < 4; i++)
#pragma unroll
        for (int j = 0; j < 4; j++) acc[i][j] = 0.f;

    const int gmL = m0 + lr;
    const int gnL = n0 + lr;

    for (int k0 = 0; k0 < K; k0 += 16) {
        float4 av = make_float4(0.f, 0.f, 0.f, 0.f);
        float4 bv = make_float4(0.f, 0.f, 0.f, 0.f);
        if (gmL < M) av = *(const float4*)(A  + (long)gmL * lda + k0 + lk);
        if (gnL < N) bv = *(const float4*)(Bm + (long)gnL * ldb + k0 + lk);
        __syncthreads();
        As[(lk + 0) * 64 + lr] = av.x; As[(lk + 1) * 64 + lr] = av.y;
        As[(lk + 2) * 64 + lr] = av.z; As[(lk + 3) * 64 + lr] = av.w;
        Bs[(lk + 0) * 64 + lr] = bv.x; Bs[(lk + 1) * 64 + lr] = bv.y;
        Bs[(lk + 2) * 64 + lr] = bv.z; Bs[(lk + 3) * 64 + lr] = bv.w;
        __syncthreads();
#pragma unroll
        for (int kk = 0; kk < 16; kk++) {
            float4 a4 = *(const float4*)(As + kk * 64 + ty * 4);
            float4 b4 = *(const float4*)(Bs + kk * 64 + tx * 4);
            float ar[4] = {a4.x, a4.y, a4.z, a4.w};
            float br[4] = {b4.x, b4.y, b4.z, b4.w};
#pragma unroll
            for (int i = 0; i < 4; i++)
#pragma unroll
                for (int j = 0; j < 4; j++)
                    acc[i][j] += ar[i] * br[j];
        }
    }

#pragma unroll
    for (int i = 0; i < 4; i++) {
        int gm = m0 + ty * 4 + i;
        if (gm >= M) continue;
#pragma unroll
        for (int j = 0; j < 4; j++) {
            int gn = n0 + tx * 4 + j;
            if (gn >= N) continue;
            C[(long)gm * ldc + gn] = acc[i][j];
        }
    }
}

// ---------------------------------------------------------------------------
// LayerNorm over C=512
// ---------------------------------------------------------------------------
__global__ void layernorm_kernel(const float* __restrict__ in,
                                 const float* __restrict__ gam,
                                 const float* __restrict__ bet,
                                 float* __restrict__ out)
{
    const int row = blockIdx.x;
    const int t   = threadIdx.x;
    const float* x = in + (long)row * 512;
    float v0 = x[t], v1 = x[t + 128], v2 = x[t + 256], v3 = x[t + 384];
    float s  = v0 + v1 + v2 + v3;
    float s2 = v0 * v0 + v1 * v1 + v2 * v2 + v3 * v3;
#pragma unroll
    for (int o = 16; o > 0; o >>= 1) {
        s  += __shfl_xor_sync(0xffffffffu, s,  o);
        s2 += __shfl_xor_sync(0xffffffffu, s2, o);
    }
    __shared__ float ss[4], ss2[4];
    if ((t & 31) == 0) { ss[t >> 5] = s; ss2[t >> 5] = s2; }
    __syncthreads();
    s  = ss[0]  + ss[1]  + ss[2]  + ss[3];
    s2 = ss2[0] + ss2[1] + ss2[2] + ss2[3];
    const float mean = s * (1.f / 512.f);
    const float var  = s2 * (1.f / 512.f) - mean * mean;
    const float inv  = rsqrtf(var + 1e-5f);
    float* o = out + (long)row * 512;
    o[t]       = (v0 - mean) * inv * gam[t]       + bet[t];
    o[t + 128] = (v1 - mean) * inv * gam[t + 128] + bet[t + 128];
    o[t + 256] = (v2 - mean) * inv * gam[t + 256] + bet[t + 256];
    o[t + 384] = (v3 - mean) * inv * gam[t + 384] + bet[t + 384];
}

// ---------------------------------------------------------------------------
// k/v head split; v gets the raw-reshape LoRA fixup
// ---------------------------------------------------------------------------
__global__ void build_kv(const float* __restrict__ kv,
                         const float* __restrict__ lv,
                         float* __restrict__ k, float* __restrict__ v)
{
    const int idx = blockIdx.x * 256 + threadIdx.x;
    const int dd = idx & 63;
    const int m  = (idx >> 6) % 576;
    const int bh = idx / 36864;
    const int h  = bh & 7, b = bh >> 3;
    const long base = (long)(b * 576 + m) * 1024 + h * 64 + dd;
    k[idx] = kv[base];
    v[idx] = kv[base + 512] + lv[(long)b * 294912 + h * 36864 + m * 64 + dd];
}

// ---------------------------------------------------------------------------
// Flash-style tf32 attention. One block = 64 queries x one (b,h).
// Online softmax over 9 key chunks of 64.
// ---------------------------------------------------------------------------
#define TPa 68   // tile pitch (mod 32 == 4 -> conflict-free fragment loads)
#define ATTN_SMEM ((4 * 64 * TPa + 3 * 64) * 4)

__global__ void __launch_bounds__(256)
attn_flash(const float* __restrict__ qb,   // (B,N,512)
           const float* __restrict__ kb,   // (B*H,576,64)
           const float* __restrict__ vb,   // (B*H,576,64)
           float* __restrict__ ctx)        // (B,N,512)
{
    extern __shared__ float sm[];
    unsigned* Qs    = (unsigned*)sm;        // [q][dd]   64*TPa
    unsigned* Ks    = Qs + 64 * TPa;        // [key][dd] 64*TPa
    unsigned* Vs    = Ks + 64 * TPa;        // [dd][key] 64*TPa
    float*    Sc    = (float*)(Vs + 64 * TPa);  // [q][key] 64*TPa
    float*    m_run = Sc + 64 * TPa;        // 64
    float*    l_run = m_run + 64;           // 64
    float*    alf   = l_run + 64;           // 64

    const int t    = threadIdx.x;
    const int lane = t & 31, w = t >> 5;
    const int g  = lane >> 2, tg = lane & 3;
    const int wm = w >> 1,  wn = w & 1;
    const int bh = blockIdx.y, b = bh >> 3, h = bh & 7;
    const int n0 = blockIdx.x * 64;
    const int r0 = wm * 16 + g;

    // Q tile [q][dd] as tf32
#pragma unroll
    for (int r = 0; r < 16; r++) {
        int idx = r * 256 + t;
        int qq = idx >> 6, dd = idx & 63;
        Qs[qq * TPa + dd] = f2tf(qb[(long)(b * 9216 + n0 + qq) * 512 + h * 64 + dd]);
    }
    if (t < 64) { m_run[t] = -1e30f; l_run[t] = 0.f; }

    float O[4][4];
#pragma unroll
    for (int ni = 0; ni < 4; ni++)
#pragma unroll
        for (int c = 0; c < 4; c++) O[ni][c] = 0.f;

    for (int ch = 0; ch < 9; ch++) {
        const int m0c = ch * 64;
        __syncthreads();   // prev-chunk fragment loads done; safe to overwrite K/V
#pragma unroll
        for (int r = 0; r < 16; r++) {
            int idx = r * 256 + t;
            int key = idx >> 6, dd = idx & 63;
            float kvl = kb[(long)(bh * 576 + m0c + key) * 64 + dd];
            float vvl = vb[(long)(bh * 576 + m0c + key) * 64 + dd];
            Ks[key * TPa + dd] = f2tf(kvl);
            Vs[dd * TPa + key] = f2tf(vvl);
        }
        __syncthreads();

        // --- S chunk = (Q K^T) * 0.125 ---
        float acc[4][4];
#pragma unroll
        for (int ni = 0; ni < 4; ni++)
#pragma unroll
            for (int c = 0; c < 4; c++) acc[ni][c] = 0.f;
#pragma unroll
        for (int kk = 0; kk < 64; kk += 8) {
            unsigned af[4];
            af[0] = Qs[r0 * TPa + kk + tg];
            af[1] = Qs[(r0 + 8) * TPa + kk + tg];
            af[2] = Qs[r0 * TPa + kk + tg + 4];
            af[3] = Qs[(r0 + 8) * TPa + kk + tg + 4];
#pragma unroll
            for (int ni = 0; ni < 4; ni++) {
                const int rn = wn * 32 + ni * 8 + g;
                unsigned bf[2];
                bf[0] = Ks[rn * TPa + kk + tg];
                bf[1] = Ks[rn * TPa + kk + tg + 4];
                mma8(acc[ni], af, bf);
            }
        }
#pragma unroll
        for (int ni = 0; ni < 4; ni++) {
            const int c = wn * 32 + ni * 8 + 2 * tg;
            *(float2*)(Sc + r0 * TPa + c) =
                make_float2(acc[ni][0] * 0.125f, acc[ni][1] * 0.125f);
            *(float2*)(Sc + (r0 + 8) * TPa + c) =
                make_float2(acc[ni][2] * 0.125f, acc[ni][3] * 0.125f);
        }
        __syncthreads();

        // --- online softmax stats for this chunk ---
        {
            const int row = t >> 2, part = t & 3;
            float cm = -1e30f;
#pragma unroll
            for (int i = 0; i < 16; i++)
                cm = fmaxf(cm, Sc[row * TPa + 4 * i + part]);
            cm = fmaxf(cm, __shfl_xor_sync(0xffffffffu, cm, 1));
            cm = fmaxf(cm, __shfl_xor_sync(0xffffffffu, cm, 2));
            const float nm = fmaxf(m_run[row], cm);
            float sum = 0.f;
#pragma unroll
            for (int i = 0; i < 16; i++) {
                float e  = __expf(Sc[row * TPa + 4 * i + part] - nm);
                float et = __uint_as_float(f2tf(e));
                Sc[row * TPa + 4 * i + part] = et;
                sum += et;
            }
            sum += __shfl_xor_sync(0xffffffffu, sum, 1);
            sum += __shfl_xor_sync(0xffffffffu, sum, 2);
            if (part == 0) {
                float al = __expf(m_run[row] - nm);
                alf[row] = al;
                l_run[row] = l_run[row] * al + sum;
                m_run[row] = nm;
            }
        }
        __syncthreads();

        // --- rescale O and accumulate P @ V ---
        {
            const float a0 = alf[r0], a1 = alf[r0 + 8];
#pragma unroll
            for (int ni = 0; ni < 4; ni++) {
                O[ni][0] *= a0; O[ni][1] *= a0;
                O[ni][2] *= a1; O[ni][3] *= a1;
            }
        }
#pragma unroll
        for (int kk = 0; kk < 64; kk += 8) {
            unsigned af[4];
            af[0] = __float_as_uint(Sc[r0 * TPa + kk + tg]);
            af[1] = __float_as_uint(Sc[(r0 + 8) * TPa + kk + tg]);
            af[2] = __float_as_uint(Sc[r0 * TPa + kk + tg + 4]);
            af[3] = __float_as_uint(Sc[(r0 + 8) * TPa + kk + tg + 4]);
#pragma unroll
            for (int ni = 0; ni < 4; ni++) {
                const int rn = wn * 32 + ni * 8 + g;
                unsigned bf[2];
                bf[0] = Vs[rn * TPa + kk + tg];
                bf[1] = Vs[rn * TPa + kk + tg + 4];
                mma8(O[ni], af, bf);
            }
        }
    }

    const float inv0 = 1.f / l_run[r0];
    const float inv1 = 1.f / l_run[r0 + 8];
#pragma unroll
    for (int ni = 0; ni < 4; ni++) {
        const int c = wn * 32 + ni * 8 + 2 * tg;
        *(float2*)(ctx + (long)(b * 9216 + n0 + r0) * 512 + h * 64 + c) =
            make_float2(O[ni][0] * inv0, O[ni][1] * inv0);
        *(float2*)(ctx + (long)(b * 9216 + n0 + r0 + 8) * 512 + h * 64 + c) =
            make_float2(O[ni][2] * inv1, O[ni][3] * inv1);
    }
}

// ---------------------------------------------------------------------------
// Launch pipeline
// ---------------------------------------------------------------------------
extern "C" void kernel_launch(void* const* d_in, const int* in_sizes, int n_in,
                              void* d_out, int out_size)
{
    (void)in_sizes; (void)n_in; (void)out_size;
    const float* x      = (const float*)d_in[0];
    const float* w_q    = (const float*)d_in[1];
    const float* b_q    = (const float*)d_in[2];
    const float* w_kv   = (const float*)d_in[3];
    const float* b_kv   = (const float*)d_in[4];
    const float* w_proj = (const float*)d_in[5];
    const float* b_proj = (const float*)d_in[6];
    const float* w_sr   = (const float*)d_in[7];
    const float* b_sr   = (const float*)d_in[8];
    const float* ln_g   = (const float*)d_in[9];
    const float* ln_b   = (const float*)d_in[10];
    const float* lAq    = (const float*)d_in[11];
    const float* lBq    = (const float*)d_in[12];
    const float* lAv    = (const float*)d_in[13];
    const float* lBv    = (const float*)d_in[14];

    float *q, *xspre, *xs, *kv, *t2, *lv, *k, *v, *ctx, *t1p, *w2, *part;
    float *lAqp, *Bq2;
    cudaGetSymbolAddress((void**)&q,     g_q);
    cudaGetSymbolAddress((void**)&xspre, g_xspre);
    cudaGetSymbolAddress((void**)&xs,    g_xs);
    cudaGetSymbolAddress((void**)&kv,    g_kv);
    cudaGetSymbolAddress((void**)&t2,    g_t2);
    cudaGetSymbolAddress((void**)&lv,    g_lv);
    cudaGetSymbolAddress((void**)&k,     g_k);
    cudaGetSymbolAddress((void**)&v,     g_v);
    cudaGetSymbolAddress((void**)&ctx,   g_ctx);
    cudaGetSymbolAddress((void**)&t1p,   g_t1p);
    cudaGetSymbolAddress((void**)&w2,    g_w2);
    cudaGetSymbolAddress((void**)&part,  g_part);
    cudaGetSymbolAddress((void**)&lAqp,  g_lAqp);
    cudaGetSymbolAddress((void**)&Bq2,   g_Bq2);

    dim3 blk(256);

    // prep
    reorder_w_kernel<<<16384, blk>>>(w_sr, w2);
    prep_q_lora<<<128, blk>>>(lAq, lBq, lAqp, Bq2);

    // conv GEMM (A gathered from x directly), 8-way split-K
    gemm_tf32<128, 1><<<dim3(4, 9, 8), blk>>>(
        1152, 512, 8192, x, 512, w2, 8192, nullptr, 1.f, nullptr, 512,
        1024, part, nullptr, 0, nullptr, 0, 0);
    reduce_part<<<2304, blk>>>(part, b_sr, xspre, 589824, 512, 8, 589824);
    layernorm_kernel<<<1152, 128>>>(xspre, ln_g, ln_b, xs);

    // t1p = X @ lAqp^T  (18432 x 64 x 512)
    gemm_tf32<64, 0><<<dim3(1, 144, 1), blk>>>(
        18432, 64, 512, x, 512, lAqp, 512, nullptr, 1.f, t1p, 64,
        512, nullptr, nullptr, 0, nullptr, 0, 0);
    // q = X Wq^T + b_q + t1p[:, :32] @ Bq2^T  (LoRA fused into K loop)
    gemm_tf32<128, 0><<<dim3(4, 144, 1), blk>>>(
        18432, 512, 512, x, 512, w_q, 512, b_q, 1.f, q, 512,
        512, nullptr, t1p, 64, Bq2, 32, 32);

    // kv = xs Wkv^T + b_kv  (4-way split-K)
    gemm_tf32<128, 0><<<dim3(8, 9, 4), blk>>>(
        1152, 1024, 512, xs, 512, w_kv, 512, nullptr, 1.f, nullptr, 1024,
        128, part, nullptr, 0, nullptr, 0, 0);
    reduce_part<<<4608, blk>>>(part, b_kv, kv, 1179648, 1024, 4, 1179648);

    // lv = (xs Av^T) Bv^T * SCALING
    gemm_abt<<<dim3(1, 18), blk>>>(1152, 32, 512, xs, 512, lAv, 512, t2, 32);
    gemm_tf32<128, 0><<<dim3(4, 9, 1), blk>>>(
        1152, 512, 32, t2, 32, lBv, 32, nullptr, SCALING, lv, 512,
        32, nullptr, nullptr, 0, nullptr, 0, 0);

    build_kv<<<2304, blk>>>(kv, lv, k, v);

    cudaFuncSetAttribute(attn_flash,
                         cudaFuncAttributeMaxDynamicSharedMemorySize, ATTN_SMEM);
    attn_flash<<<dim3(144, 16), blk, ATTN_SMEM>>>(q, k, v, ctx);

    // out = ctx Wp^T + b_proj
    gemm_tf32<128, 0><<<dim3(4, 144, 1), blk>>>(
        18432, 512, 512, ctx, 512, w_proj, 512, b_proj, 1.f, (float*)d_out,
        512, 512, nullptr, nullptr, 0, nullptr, 0, 0);
}

// round 6
// speedup vs baseline: 3.6968x; 1.1355x over previous
#include <cuda_runtime.h>
#include <math.h>

// B=2, N=9216, C=512, HEAD=8, d=64, SR=4, H=W=96 -> Nkv=576, R=32
#define SCALING 0.125f

// ---------------------------------------------------------------------------
// Scratch
// ---------------------------------------------------------------------------
__device__ float g_q    [9437184];  // (B,N,C)
__device__ float g_xspre[589824];   // (B*576, 512)
__device__ float g_xs   [589824];
__device__ float g_kv   [1179648];  // (B*576, 1024)
__device__ float g_t2   [36864];
__device__ float g_lv   [589824];
__device__ float g_k    [589824];   // (B*H,576,64)
__device__ float g_v    [589824];
__device__ float g_ctx  [9437184];
__device__ float g_t1p  [1179648];  // 18432 x 64 padded lora-q intermediate
__device__ float g_w2   [4194304];  // 512 x 8192 reordered conv weight
__device__ float g_part [4718592];  // split-K partials
__device__ float g_lAqp [32768];    // 64 x 512 padded lora_A_q
__device__ float g_Bq2  [16384];    // 512 x 32 prescaled lora_B_q

// ---------------------------------------------------------------------------
// tf32 helpers
// ---------------------------------------------------------------------------
__device__ __forceinline__ unsigned f2tf(float x) {
    unsigned u;
    asm("cvt.rna.tf32.f32 %0, %1;" : "=r"(u) : "f"(x));
    return u;
}
__device__ __forceinline__ void mma8(float* c, const unsigned* a, const unsigned* b) {
    asm volatile(
        "mma.sync.aligned.m16n8k8.row.col.f32.tf32.tf32.f32 "
        "{%0,%1,%2,%3}, {%4,%5,%6,%7}, {%8,%9}, {%0,%1,%2,%3};"
        : "+f"(c[0]), "+f"(c[1]), "+f"(c[2]), "+f"(c[3])
        : "r"(a[0]), "r"(a[1]), "r"(a[2]), "r"(a[3]),
          "r"(b[0]), "r"(b[1]));
}

// ---------------------------------------------------------------------------
// tf32 tensor-core GEMM, 2-stage pipelined (double-buffered smem):
//   C = scale * (A @ B^T [+ A2 @ B2^T]) (+bias)
// A: MxK row-major, B: NxK row-major. REQUIRES M%128==0, N%BN==0, K%16==0.
// BM=128, BN in {64,128}, BK=16; 256 threads; warps 4(M)x2(N).
// gridDim.z>1: raw partials to `part`.
// CONV=1: A gathered from x with the SR-conv im2col mapping.
// ---------------------------------------------------------------------------
template <int BN, int CONV>
__global__ void __launch_bounds__(256, 2)
gemm_tf32(int M, int N, int K,
          const float* __restrict__ A, int lda,
          const float* __restrict__ B, int ldb,
          const float* __restrict__ bias,
          float scale,
          float* __restrict__ C, int ldc,
          int kchunk, float* __restrict__ part,
          const float* __restrict__ A2, int lda2,
          const float* __restrict__ B2, int ldb2, int K2)
{
    constexpr int NI = BN / 16;
    __shared__ unsigned As[2][128][20];
    __shared__ unsigned Bs[2][BN][20];
    const int t    = threadIdx.x;
    const int lane = t & 31, w = t >> 5;
    const int g  = lane >> 2, tg = lane & 3;
    const int wm = w >> 1,  wn = w & 1;
    const long m0 = (long)blockIdx.y * 128;
    const int  n0 = blockIdx.x * BN;
    const int  kb = blockIdx.z * kchunk;

    const int ar  = t >> 2;            // loader row (and +64)
    const int kq4 = (t & 3) * 4;       // loader k sub-quad

    float acc[2][NI][4];
#pragma unroll
    for (int mi = 0; mi < 2; mi++)
#pragma unroll
        for (int ni = 0; ni < NI; ni++)
#pragma unroll
            for (int c = 0; c < 4; c++) acc[mi][ni][c] = 0.f;

    // A addressing
    const float* Ap0 = nullptr;
    const float* Ap1 = nullptr;
    long convRow0 = 0, convRow1 = 0;
    if (CONV) {
        int m = (int)m0 + ar;
        int b = m / 576, p = m % 576, py = p / 24, px = p % 24;
        convRow0 = (long)b * 9216 + (py * 4) * 96 + px * 4;
        m = (int)m0 + ar + 64;
        b = m / 576; p = m % 576; py = p / 24; px = p % 24;
        convRow1 = (long)b * 9216 + (py * 4) * 96 + px * 4;
    } else {
        Ap0 = A + (m0 + ar) * lda + kq4;
        Ap1 = A + (m0 + ar + 64) * lda + kq4;
    }
    const float* Bp0 = B + (long)(n0 + ar) * ldb + kq4;
    const float* Bp1 = (BN == 128) ? B + (long)(n0 + ar + 64) * ldb + kq4 : nullptr;

    const int n1 = kchunk >> 4;
    const int n2 = K2 >> 4;
    const int nIter = n1 + n2;

    float4 av0, av1, bv0, bv1;

    auto loadTile = [&](int idx) {
        if (idx < n1) {
            const int k0 = kb + (idx << 4);
            if (CONV) {
                const int s  = k0 >> 9;        // tap 0..15
                const int ii = s >> 2, jj = s & 3;
                const int ci = (k0 & 511) + kq4;
                av0 = *(const float4*)(A + (convRow0 + ii * 96 + jj) * 512 + ci);
                av1 = *(const float4*)(A + (convRow1 + ii * 96 + jj) * 512 + ci);
            } else {
                av0 = *(const float4*)(Ap0 + k0);
                av1 = *(const float4*)(Ap1 + k0);
            }
            bv0 = *(const float4*)(Bp0 + k0);
            if (BN == 128) bv1 = *(const float4*)(Bp1 + k0);
        } else {
            const int k0 = ((idx - n1) << 4) + kq4;
            av0 = *(const float4*)(A2 + (m0 + ar) * lda2 + k0);
            av1 = *(const float4*)(A2 + (m0 + ar + 64) * lda2 + k0);
            bv0 = *(const float4*)(B2 + (long)(n0 + ar) * ldb2 + k0);
            if (BN == 128)
                bv1 = *(const float4*)(B2 + (long)(n0 + ar + 64) * ldb2 + k0);
        }
    };
    auto storeTile = [&](int buf) {
        uint4 u;
        u.x = f2tf(av0.x); u.y = f2tf(av0.y); u.z = f2tf(av0.z); u.w = f2tf(av0.w);
        *(uint4*)&As[buf][ar][kq4] = u;
        u.x = f2tf(av1.x); u.y = f2tf(av1.y); u.z = f2tf(av1.z); u.w = f2tf(av1.w);
        *(uint4*)&As[buf][ar + 64][kq4] = u;
        u.x = f2tf(bv0.x); u.y = f2tf(bv0.y); u.z = f2tf(bv0.z); u.w = f2tf(bv0.w);
        *(uint4*)&Bs[buf][ar][kq4] = u;
        if (BN == 128) {
            u.x = f2tf(bv1.x); u.y = f2tf(bv1.y);
            u.z = f2tf(bv1.z); u.w = f2tf(bv1.w);
            *(uint4*)&Bs[buf][ar + 64][kq4] = u;
        }
    };

    loadTile(0);
    storeTile(0);
    __syncthreads();
    int buf = 0;
    for (int it = 0; it < nIter; it++) {
        const bool more = (it + 1 < nIter);
        if (more) loadTile(it + 1);     // global prefetch overlapped with mma
#pragma unroll
        for (int kk = 0; kk < 16; kk += 8) {
            unsigned af[2][4], bf[NI][2];
#pragma unroll
            for (int mi = 0; mi < 2; mi++) {
                const int r = wm * 32 + mi * 16 + g;
                af[mi][0] = As[buf][r][kk + tg];
                af[mi][1] = As[buf][r + 8][kk + tg];
                af[mi][2] = As[buf][r][kk + tg + 4];
                af[mi][3] = As[buf][r + 8][kk + tg + 4];
            }
#pragma unroll
            for (int ni = 0; ni < NI; ni++) {
                const int rn = wn * (BN / 2) + ni * 8 + g;
                bf[ni][0] = Bs[buf][rn][kk + tg];
                bf[ni][1] = Bs[buf][rn][kk + tg + 4];
            }
#pragma unroll
            for (int mi = 0; mi < 2; mi++)
#pragma unroll
                for (int ni = 0; ni < NI; ni++)
                    mma8(acc[mi][ni], af[mi], bf[ni]);
        }
        if (more) {
            storeTile(buf ^ 1);
            __syncthreads();
            buf ^= 1;
        }
    }

    if (gridDim.z == 1) {
#pragma unroll
        for (int mi = 0; mi < 2; mi++) {
            const long r0 = m0 + wm * 32 + mi * 16 + g;
            const long r1 = r0 + 8;
#pragma unroll
            for (int ni = 0; ni < NI; ni++) {
                const int c = n0 + wn * (BN / 2) + ni * 8 + 2 * tg;
                float v00 = scale * acc[mi][ni][0];
                float v01 = scale * acc[mi][ni][1];
                float v10 = scale * acc[mi][ni][2];
                float v11 = scale * acc[mi][ni][3];
                if (bias) {
                    float b0 = bias[c], b1 = bias[c + 1];
                    v00 += b0; v01 += b1; v10 += b0; v11 += b1;
                }
                *(float2*)(C + r0 * ldc + c) = make_float2(v00, v01);
                *(float2*)(C + r1 * ldc + c) = make_float2(v10, v11);
            }
        }
    } else {
        float* P = part + (long)blockIdx.z * M * ldc;
#pragma unroll
        for (int mi = 0; mi < 2; mi++) {
            const long r0 = m0 + wm * 32 + mi * 16 + g;
            const long r1 = r0 + 8;
#pragma unroll
            for (int ni = 0; ni < NI; ni++) {
                const int c = n0 + wn * (BN / 2) + ni * 8 + 2 * tg;
                *(float2*)(P + r0 * ldc + c) =
                    make_float2(acc[mi][ni][0], acc[mi][ni][1]);
                *(float2*)(P + r1 * ldc + c) =
                    make_float2(acc[mi][ni][2], acc[mi][ni][3]);
            }
        }
    }
}

// out[i] = bias[i % ldc] + sum_z part[z*zstride + i]
__global__ void reduce_part(const float* __restrict__ part,
                            const float* __restrict__ bias,
                            float* __restrict__ out,
                            int total, int ldc, int nz, long zstride)
{
    const int i = blockIdx.x * 256 + threadIdx.x;
    if (i >= total) return;
    float s = bias[i % ldc];
    for (int z = 0; z < nz; z++) s += part[(long)z * zstride + i];
    out[i] = s;
}

// w2[co][(i*4+j)*512 + ci] = w_sr[co][ci][i][j]
__global__ void reorder_w_kernel(const float* __restrict__ w,
                                 float* __restrict__ w2)
{
    const int tid = blockIdx.x * 256 + threadIdx.x;
    const int ci = tid & 511;
    const int s  = (tid >> 9) & 15;
    const int co = tid >> 13;
    w2[tid] = w[(long)co * 8192 + ci * 16 + s];
}

// pad lora_A_q to 64x512 (zeros) and prescale lora_B_q by SCALING
__global__ void prep_q_lora(const float* __restrict__ lAq,
                            const float* __restrict__ lBq,
                            float* __restrict__ lAqp,
                            float* __restrict__ Bq2)
{
    const int i = blockIdx.x * 256 + threadIdx.x;
    if (i < 64 * 512) lAqp[i] = (i < 32 * 512) ? lAq[i] : 0.f;
    if (i < 512 * 32) Bq2[i] = lBq[i] * SCALING;
}

// ---------------------------------------------------------------------------
// SIMT GEMM kept for tiny LoRA-A on xs (1152 x 32 x 512)
// ---------------------------------------------------------------------------
__global__ void gemm_abt(int M, int N, int K,
                         const float* __restrict__ A, int lda,
                         const float* __restrict__ Bm, int ldb,
                         float* __restrict__ C, int ldc)
{
    __shared__ float As[16 * 64];
    __shared__ float Bs[16 * 64];
    const int t  = threadIdx.x;
    const int ty = t >> 4, tx = t & 15;
    const int m0 = blockIdx.y * 64, n0 = blockIdx.x * 64;
    const int lr = t >> 2;
    const int lk = (t & 3) << 2;

    float acc[4][4];
#pragma unroll
    for (int i = 0; i < 4; i++)
#pragma unroll
        for (int j = 0; j < 4; j++) acc[i][j] = 0.f;

    const int gmL = m0 + lr;
    const int gnL = n0 + lr;

    for (int k0 = 0; k0 < K; k0 += 16) {
        float4 av = make_float4(0.f, 0.f, 0.f, 0.f);
        float4 bv = make_float4(0.f, 0.f, 0.f, 0.f);
        if (gmL < M) av = *(const float4*)(A  + (long)gmL * lda + k0 + lk);
        if (gnL < N) bv = *(const float4*)(Bm + (long)gnL * ldb + k0 + lk);
        __syncthreads();
        As[(lk + 0) * 64 + lr] = av.x; As[(lk + 1) * 64 + lr] = av.y;
        As[(lk + 2) * 64 + lr] = av.z; As[(lk + 3) * 64 + lr] = av.w;
        Bs[(lk + 0) * 64 + lr] = bv.x; Bs[(lk + 1) * 64 + lr] = bv.y;
        Bs[(lk + 2) * 64 + lr] = bv.z; Bs[(lk + 3) * 64 + lr] = bv.w;
        __syncthreads();
#pragma unroll
        for (int kk = 0; kk < 16; kk++) {
            float4 a4 = *(const float4*)(As + kk * 64 + ty * 4);
            float4 b4 = *(const float4*)(Bs + kk * 64 + tx * 4);
            float ar[4] = {a4.x, a4.y, a4.z, a4.w};
            float br[4] = {b4.x, b4.y, b4.z, b4.w};
#pragma unroll
            for (int i = 0; i < 4; i++)
#pragma unroll
                for (int j = 0; j < 4; j++)
                    acc[i][j] += ar[i] * br[j];
        }
    }

#pragma unroll
    for (int i = 0; i < 4; i++) {
        int gm = m0 + ty * 4 + i;
        if (gm >= M) continue;
#pragma unroll
        for (int j = 0; j < 4; j++) {
            int gn = n0 + tx * 4 + j;
            if (gn >= N) continue;
            C[(long)gm * ldc + gn] = acc[i][j];
        }
    }
}

// ---------------------------------------------------------------------------
// LayerNorm over C=512
// ---------------------------------------------------------------------------
__global__ void layernorm_kernel(const float* __restrict__ in,
                                 const float* __restrict__ gam,
                                 const float* __restrict__ bet,
                                 float* __restrict__ out)
{
    const int row = blockIdx.x;
    const int t   = threadIdx.x;
    const float* x = in + (long)row * 512;
    float v0 = x[t], v1 = x[t + 128], v2 = x[t + 256], v3 = x[t + 384];
    float s  = v0 + v1 + v2 + v3;
    float s2 = v0 * v0 + v1 * v1 + v2 * v2 + v3 * v3;
#pragma unroll
    for (int o = 16; o > 0; o >>= 1) {
        s  += __shfl_xor_sync(0xffffffffu, s,  o);
        s2 += __shfl_xor_sync(0xffffffffu, s2, o);
    }
    __shared__ float ss[4], ss2[4];
    if ((t & 31) == 0) { ss[t >> 5] = s; ss2[t >> 5] = s2; }
    __syncthreads();
    s  = ss[0]  + ss[1]  + ss[2]  + ss[3];
    s2 = ss2[0] + ss2[1] + ss2[2] + ss2[3];
    const float mean = s * (1.f / 512.f);
    const float var  = s2 * (1.f / 512.f) - mean * mean;
    const float inv  = rsqrtf(var + 1e-5f);
    float* o = out + (long)row * 512;
    o[t]       = (v0 - mean) * inv * gam[t]       + bet[t];
    o[t + 128] = (v1 - mean) * inv * gam[t + 128] + bet[t + 128];
    o[t + 256] = (v2 - mean) * inv * gam[t + 256] + bet[t + 256];
    o[t + 384] = (v3 - mean) * inv * gam[t + 384] + bet[t + 384];
}

// ---------------------------------------------------------------------------
// k/v head split; v gets the raw-reshape LoRA fixup
// ---------------------------------------------------------------------------
__global__ void build_kv(const float* __restrict__ kv,
                         const float* __restrict__ lv,
                         float* __restrict__ k, float* __restrict__ v)
{
    const int idx = blockIdx.x * 256 + threadIdx.x;
    const int dd = idx & 63;
    const int m  = (idx >> 6) % 576;
    const int bh = idx / 36864;
    const int h  = bh & 7, b = bh >> 3;
    const long base = (long)(b * 576 + m) * 1024 + h * 64 + dd;
    k[idx] = kv[base];
    v[idx] = kv[base + 512] + lv[(long)b * 294912 + h * 36864 + m * 64 + dd];
}

// ---------------------------------------------------------------------------
// Flash-style tf32 attention. One block = 128 queries x one (b,h).
// Online softmax over 9 key chunks of 64. Smem ~104KB -> 2 CTAs/SM.
// 256 threads = 8 warps as 4(m) x 2(n); warp tile 32q x 32keys.
// ---------------------------------------------------------------------------
#define TPa 68   // tile pitch (mod 32 == 4 -> conflict-free fragment loads)
#define ATTN_SMEM ((TPa * 384 + 3 * 128) * 4)

__global__ void __launch_bounds__(256)
attn_flash(const float* __restrict__ qb,   // (B,N,512)
           const float* __restrict__ kb,   // (B*H,576,64)
           const float* __restrict__ vb,   // (B*H,576,64)
           float* __restrict__ ctx)        // (B,N,512)
{
    extern __shared__ float sm[];
    unsigned* Qs    = (unsigned*)sm;            // [q][dd]   128*TPa
    unsigned* Ks    = Qs + 128 * TPa;           // [key][dd] 64*TPa
    unsigned* Vs    = Ks + 64 * TPa;            // [dd][key] 64*TPa
    float*    Sc    = (float*)(Vs + 64 * TPa);  // [q][key]  128*TPa
    float*    m_run = Sc + 128 * TPa;           // 128
    float*    l_run = m_run + 128;              // 128
    float*    alf   = l_run + 128;              // 128

    const int t    = threadIdx.x;
    const int lane = t & 31, w = t >> 5;
    const int g  = lane >> 2, tg = lane & 3;
    const int wm = w >> 1,  wn = w & 1;
    const int bh = blockIdx.y, b = bh >> 3, h = bh & 7;
    const int n0 = blockIdx.x * 128;

    // Q tile [q][dd] as tf32 (128 x 64)
#pragma unroll
    for (int r = 0; r < 32; r++) {
        int idx = r * 256 + t;
        int qq = idx >> 6, dd = idx & 63;
        Qs[qq * TPa + dd] = f2tf(qb[(long)(b * 9216 + n0 + qq) * 512 + h * 64 + dd]);
    }
    if (t < 128) { m_run[t] = -1e30f; l_run[t] = 0.f; }

    float O[2][4][4];
#pragma unroll
    for (int mi = 0; mi < 2; mi++)
#pragma unroll
        for (int ni = 0; ni < 4; ni++)
#pragma unroll
            for (int c = 0; c < 4; c++) O[mi][ni][c] = 0.f;

    for (int ch = 0; ch < 9; ch++) {
        const int m0c = ch * 64;
        __syncthreads();   // prev-chunk V reads done; safe to overwrite K/V
#pragma unroll
        for (int r = 0; r < 16; r++) {
            int idx = r * 256 + t;
            int key = idx >> 6, dd = idx & 63;
            Ks[key * TPa + dd] = f2tf(kb[(long)(bh * 576 + m0c + key) * 64 + dd]);
            Vs[dd * TPa + key] = f2tf(vb[(long)(bh * 576 + m0c + key) * 64 + dd]);
        }
        __syncthreads();

        // --- S chunk = (Q K^T) * 0.125 : 128x64 ---
        float acc[2][4][4];
#pragma unroll
        for (int mi = 0; mi < 2; mi++)
#pragma unroll
            for (int ni = 0; ni < 4; ni++)
#pragma unroll
                for (int c = 0; c < 4; c++) acc[mi][ni][c] = 0.f;
#pragma unroll
        for (int kk = 0; kk < 64; kk += 8) {
            unsigned af[2][4], bf[4][2];
#pragma unroll
            for (int mi = 0; mi < 2; mi++) {
                const int r = wm * 32 + mi * 16 + g;
                af[mi][0] = Qs[r * TPa + kk + tg];
                af[mi][1] = Qs[(r + 8) * TPa + kk + tg];
                af[mi][2] = Qs[r * TPa + kk + tg + 4];
                af[mi][3] = Qs[(r + 8) * TPa + kk + tg + 4];
            }
#pragma unroll
            for (int ni = 0; ni < 4; ni++) {
                const int rn = wn * 32 + ni * 8 + g;
                bf[ni][0] = Ks[rn * TPa + kk + tg];
                bf[ni][1] = Ks[rn * TPa + kk + tg + 4];
            }
#pragma unroll
            for (int mi = 0; mi < 2; mi++)
#pragma unroll
                for (int ni = 0; ni < 4; ni++)
                    mma8(acc[mi][ni], af[mi], bf[ni]);
        }
#pragma unroll
        for (int mi = 0; mi < 2; mi++) {
            const int r = wm * 32 + mi * 16 + g;
#pragma unroll
            for (int ni = 0; ni < 4; ni++) {
                const int c = wn * 32 + ni * 8 + 2 * tg;
                *(float2*)(Sc + r * TPa + c) =
                    make_float2(acc[mi][ni][0] * 0.125f, acc[mi][ni][1] * 0.125f);
                *(float2*)(Sc + (r + 8) * TPa + c) =
                    make_float2(acc[mi][ni][2] * 0.125f, acc[mi][ni][3] * 0.125f);
            }
        }
        __syncthreads();

        // --- online softmax stats (2 threads per row) ---
        {
            const int row = t >> 1, part = t & 1;
            float cm = -1e30f;
#pragma unroll
            for (int i = 0; i < 32; i++)
                cm = fmaxf(cm, Sc[row * TPa + 2 * i + part]);
            cm = fmaxf(cm, __shfl_xor_sync(0xffffffffu, cm, 1));
            const float nm = fmaxf(m_run[row], cm);
            float sum = 0.f;
#pragma unroll
            for (int i = 0; i < 32; i++) {
                float e  = __expf(Sc[row * TPa + 2 * i + part] - nm);
                float et = __uint_as_float(f2tf(e));
                Sc[row * TPa + 2 * i + part] = et;
                sum += et;
            }
            sum += __shfl_xor_sync(0xffffffffu, sum, 1);
            if (part == 0) {
                float al = __expf(m_run[row] - nm);
                alf[row] = al;
                l_run[row] = l_run[row] * al + sum;
                m_run[row] = nm;
            }
        }
        __syncthreads();

        // --- rescale O and accumulate P @ V ---
#pragma unroll
        for (int mi = 0; mi < 2; mi++) {
            const int r = wm * 32 + mi * 16 + g;
            const float a0 = alf[r], a1 = alf[r + 8];
#pragma unroll
            for (int ni = 0; ni < 4; ni++) {
                O[mi][ni][0] *= a0; O[mi][ni][1] *= a0;
                O[mi][ni][2] *= a1; O[mi][ni][3] *= a1;
            }
        }
#pragma unroll
        for (int kk = 0; kk < 64; kk += 8) {
            unsigned af[2][4], bf[4][2];
#pragma unroll
            for (int mi = 0; mi < 2; mi++) {
                const int r = wm * 32 + mi * 16 + g;
                af[mi][0] = __float_as_uint(Sc[r * TPa + kk + tg]);
                af[mi][1] = __float_as_uint(Sc[(r + 8) * TPa + kk + tg]);
                af[mi][2] = __float_as_uint(Sc[r * TPa + kk + tg + 4]);
                af[mi][3] = __float_as_uint(Sc[(r + 8) * TPa + kk + tg + 4]);
            }
#pragma unroll
            for (int ni = 0; ni < 4; ni++) {
                const int rn = wn * 32 + ni * 8 + g;
                bf[ni][0] = Vs[rn * TPa + kk + tg];
                bf[ni][1] = Vs[rn * TPa + kk + tg + 4];
            }
#pragma unroll
            for (int mi = 0; mi < 2; mi++)
#pragma unroll
                for (int ni = 0; ni < 4; ni++)
                    mma8(O[mi][ni], af[mi], bf[ni]);
        }
    }

    // epilogue: normalize and store
#pragma unroll
    for (int mi = 0; mi < 2; mi++) {
        const int r = wm * 32 + mi * 16 + g;
        const float inv0 = 1.f / l_run[r];
        const float inv1 = 1.f / l_run[r + 8];
#pragma unroll
        for (int ni = 0; ni < 4; ni++) {
            const int c = wn * 32 + ni * 8 + 2 * tg;
            *(float2*)(ctx + (long)(b * 9216 + n0 + r) * 512 + h * 64 + c) =
                make_float2(O[mi][ni][0] * inv0, O[mi][ni][1] * inv0);
            *(float2*)(ctx + (long)(b * 9216 + n0 + r + 8) * 512 + h * 64 + c) =
                make_float2(O[mi][ni][2] * inv1, O[mi][ni][3] * inv1);
        }
    }
}

// ---------------------------------------------------------------------------
// Launch pipeline
// ---------------------------------------------------------------------------
extern "C" void kernel_launch(void* const* d_in, const int* in_sizes, int n_in,
                              void* d_out, int out_size)
{
    (void)in_sizes; (void)n_in; (void)out_size;
    const float* x      = (const float*)d_in[0];
    const float* w_q    = (const float*)d_in[1];
    const float* b_q    = (const float*)d_in[2];
    const float* w_kv   = (const float*)d_in[3];
    const float* b_kv   = (const float*)d_in[4];
    const float* w_proj = (const float*)d_in[5];
    const float* b_proj = (const float*)d_in[6];
    const float* w_sr   = (const float*)d_in[7];
    const float* b_sr   = (const float*)d_in[8];
    const float* ln_g   = (const float*)d_in[9];
    const float* ln_b   = (const float*)d_in[10];
    const float* lAq    = (const float*)d_in[11];
    const float* lBq    = (const float*)d_in[12];
    const float* lAv    = (const float*)d_in[13];
    const float* lBv    = (const float*)d_in[14];

    float *q, *xspre, *xs, *kv, *t2, *lv, *k, *v, *ctx, *t1p, *w2, *part;
    float *lAqp, *Bq2;
    cudaGetSymbolAddress((void**)&q,     g_q);
    cudaGetSymbolAddress((void**)&xspre, g_xspre);
    cudaGetSymbolAddress((void**)&xs,    g_xs);
    cudaGetSymbolAddress((void**)&kv,    g_kv);
    cudaGetSymbolAddress((void**)&t2,    g_t2);
    cudaGetSymbolAddress((void**)&lv,    g_lv);
    cudaGetSymbolAddress((void**)&k,     g_k);
    cudaGetSymbolAddress((void**)&v,     g_v);
    cudaGetSymbolAddress((void**)&ctx,   g_ctx);
    cudaGetSymbolAddress((void**)&t1p,   g_t1p);
    cudaGetSymbolAddress((void**)&w2,    g_w2);
    cudaGetSymbolAddress((void**)&part,  g_part);
    cudaGetSymbolAddress((void**)&lAqp,  g_lAqp);
    cudaGetSymbolAddress((void**)&Bq2,   g_Bq2);

    dim3 blk(256);

    // prep
    reorder_w_kernel<<<16384, blk>>>(w_sr, w2);
    prep_q_lora<<<128, blk>>>(lAq, lBq, lAqp, Bq2);

    // conv GEMM (A gathered from x directly), 8-way split-K
    gemm_tf32<128, 1><<<dim3(4, 9, 8), blk>>>(
        1152, 512, 8192, x, 512, w2, 8192, nullptr, 1.f, nullptr, 512,
        1024, part, nullptr, 0, nullptr, 0, 0);
    reduce_part<<<2304, blk>>>(part, b_sr, xspre, 589824, 512, 8, 589824);
    layernorm_kernel<<<1152, 128>>>(xspre, ln_g, ln_b, xs);

    // t1p = X @ lAqp^T  (18432 x 64 x 512)
    gemm_tf32<64, 0><<<dim3(1, 144, 1), blk>>>(
        18432, 64, 512, x, 512, lAqp, 512, nullptr, 1.f, t1p, 64,
        512, nullptr, nullptr, 0, nullptr, 0, 0);
    // q = X Wq^T + b_q + t1p[:, :32] @ Bq2^T  (LoRA fused into K loop)
    gemm_tf32<128, 0><<<dim3(4, 144, 1), blk>>>(
        18432, 512, 512, x, 512, w_q, 512, b_q, 1.f, q, 512,
        512, nullptr, t1p, 64, Bq2, 32, 32);

    // kv = xs Wkv^T + b_kv  (4-way split-K)
    gemm_tf32<128, 0><<<dim3(8, 9, 4), blk>>>(
        1152, 1024, 512, xs, 512, w_kv, 512, nullptr, 1.f, nullptr, 1024,
        128, part, nullptr, 0, nullptr, 0, 0);
    reduce_part<<<4608, blk>>>(part, b_kv, kv, 1179648, 1024, 4, 1179648);

    // lv = (xs Av^T) Bv^T * SCALING
    gemm_abt<<<dim3(1, 18), blk>>>(1152, 32, 512, xs, 512, lAv, 512, t2, 32);
    gemm_tf32<128, 0><<<dim3(4, 9, 1), blk>>>(
        1152, 512, 32, t2, 32, lBv, 32, nullptr, SCALING, lv, 512,
        32, nullptr, nullptr, 0, nullptr, 0, 0);

    build_kv<<<2304, blk>>>(kv, lv, k, v);

    cudaFuncSetAttribute(attn_flash,
                         cudaFuncAttributeMaxDynamicSharedMemorySize, ATTN_SMEM);
    attn_flash<<<dim3(72, 16), blk, ATTN_SMEM>>>(q, k, v, ctx);

    // out = ctx Wp^T + b_proj
    gemm_tf32<128, 0><<<dim3(4, 144, 1), blk>>>(
        18432, 512, 512, ctx, 512, w_proj, 512, b_proj, 1.f, (float*)d_out,
        512, 512, nullptr, nullptr, 0, nullptr, 0, 0);
}

// round 7
// speedup vs baseline: 3.9390x; 1.0655x over previous
#include <cuda_runtime.h>
#include <math.h>

// B=2, N=9216, C=512, HEAD=8, d=64, SR=4, H=W=96 -> Nkv=576, R=32
#define SCALING 0.125f

// ---------------------------------------------------------------------------
// Scratch
// ---------------------------------------------------------------------------
__device__ float g_q    [9437184];  // (B,N,C)
__device__ float g_xs   [589824];   // (B*576, 512) post-LN
__device__ float g_t2   [36864];
__device__ float g_lv   [589824];
__device__ float g_k    [589824];   // (B*H,576,64)
__device__ float g_v    [589824];
__device__ float g_ctx  [9437184];
__device__ float g_t1p  [1179648];  // 18432 x 64 padded lora-q intermediate
__device__ float g_w2   [4194304];  // 512 x 8192 reordered conv weight
__device__ float g_part [4718592];  // split-K partials
__device__ float g_lAqp [32768];    // 64 x 512 padded lora_A_q
__device__ float g_Bq2  [16384];    // 512 x 32 prescaled lora_B_q

// ---------------------------------------------------------------------------
// tf32 helpers
// ---------------------------------------------------------------------------
__device__ __forceinline__ unsigned f2tf(float x) {
    unsigned u;
    asm("cvt.rna.tf32.f32 %0, %1;" : "=r"(u) : "f"(x));
    return u;
}
__device__ __forceinline__ void mma8(float* c, const unsigned* a, const unsigned* b) {
    asm volatile(
        "mma.sync.aligned.m16n8k8.row.col.f32.tf32.tf32.f32 "
        "{%0,%1,%2,%3}, {%4,%5,%6,%7}, {%8,%9}, {%0,%1,%2,%3};"
        : "+f"(c[0]), "+f"(c[1]), "+f"(c[2]), "+f"(c[3])
        : "r"(a[0]), "r"(a[1]), "r"(a[2]), "r"(a[3]),
          "r"(b[0]), "r"(b[1]));
}

// ---------------------------------------------------------------------------
// tf32 tensor-core GEMM, 2-stage pipelined (double-buffered smem):
//   C = scale * (A @ B^T [+ A2 @ B2^T]) (+bias)
// A: MxK row-major, B: NxK row-major. REQUIRES M%128==0, N%BN==0, K%16==0.
// BM=128, BN in {64,128}, BK=16; 256 threads; warps 4(M)x2(N).
// gridDim.z>1: raw partials to `part`.
// CONV=1: A gathered from x with the SR-conv im2col mapping.
// ---------------------------------------------------------------------------
template <int BN, int CONV>
__global__ void __launch_bounds__(256, 2)
gemm_tf32(int M, int N, int K,
          const float* __restrict__ A, int lda,
          const float* __restrict__ B, int ldb,
          const float* __restrict__ bias,
          float scale,
          float* __restrict__ C, int ldc,
          int kchunk, float* __restrict__ part,
          const float* __restrict__ A2, int lda2,
          const float* __restrict__ B2, int ldb2, int K2)
{
    constexpr int NI = BN / 16;
    __shared__ unsigned As[2][128][20];
    __shared__ unsigned Bs[2][BN][20];
    const int t    = threadIdx.x;
    const int lane = t & 31, w = t >> 5;
    const int g  = lane >> 2, tg = lane & 3;
    const int wm = w >> 1,  wn = w & 1;
    const long m0 = (long)blockIdx.y * 128;
    const int  n0 = blockIdx.x * BN;
    const int  kb = blockIdx.z * kchunk;

    const int ar  = t >> 2;
    const int kq4 = (t & 3) * 4;

    float acc[2][NI][4];
#pragma unroll
    for (int mi = 0; mi < 2; mi++)
#pragma unroll
        for (int ni = 0; ni < NI; ni++)
#pragma unroll
            for (int c = 0; c < 4; c++) acc[mi][ni][c] = 0.f;

    const float* Ap0 = nullptr;
    const float* Ap1 = nullptr;
    long convRow0 = 0, convRow1 = 0;
    if (CONV) {
        int m = (int)m0 + ar;
        int b = m / 576, p = m % 576, py = p / 24, px = p % 24;
        convRow0 = (long)b * 9216 + (py * 4) * 96 + px * 4;
        m = (int)m0 + ar + 64;
        b = m / 576; p = m % 576; py = p / 24; px = p % 24;
        convRow1 = (long)b * 9216 + (py * 4) * 96 + px * 4;
    } else {
        Ap0 = A + (m0 + ar) * lda + kq4;
        Ap1 = A + (m0 + ar + 64) * lda + kq4;
    }
    const float* Bp0 = B + (long)(n0 + ar) * ldb + kq4;
    const float* Bp1 = (BN == 128) ? B + (long)(n0 + ar + 64) * ldb + kq4 : nullptr;

    const int n1 = kchunk >> 4;
    const int n2 = K2 >> 4;
    const int nIter = n1 + n2;

    float4 av0, av1, bv0, bv1;

    auto loadTile = [&](int idx) {
        if (idx < n1) {
            const int k0 = kb + (idx << 4);
            if (CONV) {
                const int s  = k0 >> 9;
                const int ii = s >> 2, jj = s & 3;
                const int ci = (k0 & 511) + kq4;
                av0 = *(const float4*)(A + (convRow0 + ii * 96 + jj) * 512 + ci);
                av1 = *(const float4*)(A + (convRow1 + ii * 96 + jj) * 512 + ci);
            } else {
                av0 = *(const float4*)(Ap0 + k0);
                av1 = *(const float4*)(Ap1 + k0);
            }
            bv0 = *(const float4*)(Bp0 + k0);
            if (BN == 128) bv1 = *(const float4*)(Bp1 + k0);
        } else {
            const int k0 = ((idx - n1) << 4) + kq4;
            av0 = *(const float4*)(A2 + (m0 + ar) * lda2 + k0);
            av1 = *(const float4*)(A2 + (m0 + ar + 64) * lda2 + k0);
            bv0 = *(const float4*)(B2 + (long)(n0 + ar) * ldb2 + k0);
            if (BN == 128)
                bv1 = *(const float4*)(B2 + (long)(n0 + ar + 64) * ldb2 + k0);
        }
    };
    auto storeTile = [&](int buf) {
        uint4 u;
        u.x = f2tf(av0.x); u.y = f2tf(av0.y); u.z = f2tf(av0.z); u.w = f2tf(av0.w);
        *(uint4*)&As[buf][ar][kq4] = u;
        u.x = f2tf(av1.x); u.y = f2tf(av1.y); u.z = f2tf(av1.z); u.w = f2tf(av1.w);
        *(uint4*)&As[buf][ar + 64][kq4] = u;
        u.x = f2tf(bv0.x); u.y = f2tf(bv0.y); u.z = f2tf(bv0.z); u.w = f2tf(bv0.w);
        *(uint4*)&Bs[buf][ar][kq4] = u;
        if (BN == 128) {
            u.x = f2tf(bv1.x); u.y = f2tf(bv1.y);
            u.z = f2tf(bv1.z); u.w = f2tf(bv1.w);
            *(uint4*)&Bs[buf][ar + 64][kq4] = u;
        }
    };

    loadTile(0);
    storeTile(0);
    __syncthreads();
    int buf = 0;
    for (int it = 0; it < nIter; it++) {
        const bool more = (it + 1 < nIter);
        if (more) loadTile(it + 1);
#pragma unroll
        for (int kk = 0; kk < 16; kk += 8) {
            unsigned af[2][4], bf[NI][2];
#pragma unroll
            for (int mi = 0; mi < 2; mi++) {
                const int r = wm * 32 + mi * 16 + g;
                af[mi][0] = As[buf][r][kk + tg];
                af[mi][1] = As[buf][r + 8][kk + tg];
                af[mi][2] = As[buf][r][kk + tg + 4];
                af[mi][3] = As[buf][r + 8][kk + tg + 4];
            }
#pragma unroll
            for (int ni = 0; ni < NI; ni++) {
                const int rn = wn * (BN / 2) + ni * 8 + g;
                bf[ni][0] = Bs[buf][rn][kk + tg];
                bf[ni][1] = Bs[buf][rn][kk + tg + 4];
            }
#pragma unroll
            for (int mi = 0; mi < 2; mi++)
#pragma unroll
                for (int ni = 0; ni < NI; ni++)
                    mma8(acc[mi][ni], af[mi], bf[ni]);
        }
        if (more) {
            storeTile(buf ^ 1);
            __syncthreads();
            buf ^= 1;
        }
    }

    if (gridDim.z == 1) {
#pragma unroll
        for (int mi = 0; mi < 2; mi++) {
            const long r0 = m0 + wm * 32 + mi * 16 + g;
            const long r1 = r0 + 8;
#pragma unroll
            for (int ni = 0; ni < NI; ni++) {
                const int c = n0 + wn * (BN / 2) + ni * 8 + 2 * tg;
                float v00 = scale * acc[mi][ni][0];
                float v01 = scale * acc[mi][ni][1];
                float v10 = scale * acc[mi][ni][2];
                float v11 = scale * acc[mi][ni][3];
                if (bias) {
                    float b0 = bias[c], b1 = bias[c + 1];
                    v00 += b0; v01 += b1; v10 += b0; v11 += b1;
                }
                *(float2*)(C + r0 * ldc + c) = make_float2(v00, v01);
                *(float2*)(C + r1 * ldc + c) = make_float2(v10, v11);
            }
        }
    } else {
        float* P = part + (long)blockIdx.z * M * ldc;
#pragma unroll
        for (int mi = 0; mi < 2; mi++) {
            const long r0 = m0 + wm * 32 + mi * 16 + g;
            const long r1 = r0 + 8;
#pragma unroll
            for (int ni = 0; ni < NI; ni++) {
                const int c = n0 + wn * (BN / 2) + ni * 8 + 2 * tg;
                *(float2*)(P + r0 * ldc + c) =
                    make_float2(acc[mi][ni][0], acc[mi][ni][1]);
                *(float2*)(P + r1 * ldc + c) =
                    make_float2(acc[mi][ni][2], acc[mi][ni][3]);
            }
        }
    }
}

// ---------------------------------------------------------------------------
// Fused conv split-K reduce + bias + LayerNorm.  One block (128 thr) per row.
// part: 8 partials of (1152 x 512).  out = LN(sum_z part + b_sr) * g + b
// ---------------------------------------------------------------------------
__global__ void reduce_ln(const float* __restrict__ part,
                          const float* __restrict__ bias,
                          const float* __restrict__ gam,
                          const float* __restrict__ bet,
                          float* __restrict__ out)
{
    const int row = blockIdx.x;
    const int t   = threadIdx.x;   // 0..127
    float v[4];
#pragma unroll
    for (int j = 0; j < 4; j++) {
        const int col = t + j * 128;
        float s = bias[col];
        const long off = (long)row * 512 + col;
#pragma unroll
        for (int z = 0; z < 8; z++) s += part[z * 589824 + off];
        v[j] = s;
    }
    float s  = v[0] + v[1] + v[2] + v[3];
    float s2 = v[0]*v[0] + v[1]*v[1] + v[2]*v[2] + v[3]*v[3];
#pragma unroll
    for (int o = 16; o > 0; o >>= 1) {
        s  += __shfl_xor_sync(0xffffffffu, s,  o);
        s2 += __shfl_xor_sync(0xffffffffu, s2, o);
    }
    __shared__ float ss[4], ss2[4];
    if ((t & 31) == 0) { ss[t >> 5] = s; ss2[t >> 5] = s2; }
    __syncthreads();
    s  = ss[0]  + ss[1]  + ss[2]  + ss[3];
    s2 = ss2[0] + ss2[1] + ss2[2] + ss2[3];
    const float mean = s * (1.f / 512.f);
    const float var  = s2 * (1.f / 512.f) - mean * mean;
    const float inv  = rsqrtf(var + 1e-5f);
    float* o = out + (long)row * 512;
#pragma unroll
    for (int j = 0; j < 4; j++) {
        const int col = t + j * 128;
        o[col] = (v[j] - mean) * inv * gam[col] + bet[col];
    }
}

// ---------------------------------------------------------------------------
// Fused kv split-K reduce + bias + head split + LoRA-v raw-reshape fixup.
// part: 4 partials of (1152 x 1024).
//   k[b,h,m,dd] = sum_z part[..., h*64+dd]       + b_kv[h*64+dd]
//   v[b,h,m,dd] = sum_z part[..., 512+h*64+dd]   + b_kv[512+h*64+dd]
//                 + lv[b, h*36864 + m*64 + dd]
// ---------------------------------------------------------------------------
__global__ void reduce_build_kv(const float* __restrict__ part,
                                const float* __restrict__ bias,
                                const float* __restrict__ lv,
                                float* __restrict__ k, float* __restrict__ v)
{
    const int idx = blockIdx.x * 256 + threadIdx.x;   // < 589824
    const int dd = idx & 63;
    const int m  = (idx >> 6) % 576;
    const int bh = idx / 36864;
    const int h  = bh & 7, b = bh >> 3;
    const int ck = h * 64 + dd;
    const long mrow = (long)(b * 576 + m) * 1024;
    float sk = bias[ck], sv = bias[512 + ck];
#pragma unroll
    for (int z = 0; z < 4; z++) {
        sk += part[z * 1179648 + mrow + ck];
        sv += part[z * 1179648 + mrow + 512 + ck];
    }
    k[idx] = sk;
    v[idx] = sv + lv[(long)b * 294912 + h * 36864 + m * 64 + dd];
}

// w2[co][(i*4+j)*512 + ci] = w_sr[co][ci][i][j]
__global__ void reorder_w_kernel(const float* __restrict__ w,
                                 float* __restrict__ w2)
{
    const int tid = blockIdx.x * 256 + threadIdx.x;
    const int ci = tid & 511;
    const int s  = (tid >> 9) & 15;
    const int co = tid >> 13;
    w2[tid] = w[(long)co * 8192 + ci * 16 + s];
}

// pad lora_A_q to 64x512 (zeros) and prescale lora_B_q by SCALING
__global__ void prep_q_lora(const float* __restrict__ lAq,
                            const float* __restrict__ lBq,
                            float* __restrict__ lAqp,
                            float* __restrict__ Bq2)
{
    const int i = blockIdx.x * 256 + threadIdx.x;
    if (i < 64 * 512) lAqp[i] = (i < 32 * 512) ? lAq[i] : 0.f;
    if (i < 512 * 32) Bq2[i] = lBq[i] * SCALING;
}

// ---------------------------------------------------------------------------
// SIMT GEMM kept for tiny LoRA-A on xs (1152 x 32 x 512)
// ---------------------------------------------------------------------------
__global__ void gemm_abt(int M, int N, int K,
                         const float* __restrict__ A, int lda,
                         const float* __restrict__ Bm, int ldb,
                         float* __restrict__ C, int ldc)
{
    __shared__ float As[16 * 64];
    __shared__ float Bs[16 * 64];
    const int t  = threadIdx.x;
    const int ty = t >> 4, tx = t & 15;
    const int m0 = blockIdx.y * 64, n0 = blockIdx.x * 64;
    const int lr = t >> 2;
    const int lk = (t & 3) << 2;

    float acc[4][4];
#pragma unroll
    for (int i = 0; i < 4; i++)
#pragma unroll
        for (int j = 0; j < 4; j++) acc[i][j] = 0.f;

    const int gmL = m0 + lr;
    const int gnL = n0 + lr;

    for (int k0 = 0; k0 < K; k0 += 16) {
        float4 av = make_float4(0.f, 0.f, 0.f, 0.f);
        float4 bv = make_float4(0.f, 0.f, 0.f, 0.f);
        if (gmL < M) av = *(const float4*)(A  + (long)gmL * lda + k0 + lk);
        if (gnL < N) bv = *(const float4*)(Bm + (long)gnL * ldb + k0 + lk);
        __syncthreads();
        As[(lk + 0) * 64 + lr] = av.x; As[(lk + 1) * 64 + lr] = av.y;
        As[(lk + 2) * 64 + lr] = av.z; As[(lk + 3) * 64 + lr] = av.w;
        Bs[(lk + 0) * 64 + lr] = bv.x; Bs[(lk + 1) * 64 + lr] = bv.y;
        Bs[(lk + 2) * 64 + lr] = bv.z; Bs[(lk + 3) * 64 + lr] = bv.w;
        __syncthreads();
#pragma unroll
        for (int kk = 0; kk < 16; kk++) {
            float4 a4 = *(const float4*)(As + kk * 64 + ty * 4);
            float4 b4 = *(const float4*)(Bs + kk * 64 + tx * 4);
            float ar[4] = {a4.x, a4.y, a4.z, a4.w};
            float br[4] = {b4.x, b4.y, b4.z, b4.w};
#pragma unroll
            for (int i = 0; i < 4; i++)
#pragma unroll
                for (int j = 0; j < 4; j++)
                    acc[i][j] += ar[i] * br[j];
        }
    }

#pragma unroll
    for (int i = 0; i < 4; i++) {
        int gm = m0 + ty * 4 + i;
        if (gm >= M) continue;
#pragma unroll
        for (int j = 0; j < 4; j++) {
            int gn = n0 + tx * 4 + j;
            if (gn >= N) continue;
            C[(long)gm * ldc + gn] = acc[i][j];
        }
    }
}

// ---------------------------------------------------------------------------
// Flash-style tf32 attention. One block = 128 queries x one (b,h).
// ---------------------------------------------------------------------------
#define TPa 68
#define ATTN_SMEM ((TPa * 384 + 3 * 128) * 4)

__global__ void __launch_bounds__(256)
attn_flash(const float* __restrict__ qb,
           const float* __restrict__ kb,
           const float* __restrict__ vb,
           float* __restrict__ ctx)
{
    extern __shared__ float sm[];
    unsigned* Qs    = (unsigned*)sm;
    unsigned* Ks    = Qs + 128 * TPa;
    unsigned* Vs    = Ks + 64 * TPa;
    float*    Sc    = (float*)(Vs + 64 * TPa);
    float*    m_run = Sc + 128 * TPa;
    float*    l_run = m_run + 128;
    float*    alf   = l_run + 128;

    const int t    = threadIdx.x;
    const int lane = t & 31, w = t >> 5;
    const int g  = lane >> 2, tg = lane & 3;
    const int wm = w >> 1,  wn = w & 1;
    const int bh = blockIdx.y, b = bh >> 3, h = bh & 7;
    const int n0 = blockIdx.x * 128;

#pragma unroll
    for (int r = 0; r < 32; r++) {
        int idx = r * 256 + t;
        int qq = idx >> 6, dd = idx & 63;
        Qs[qq * TPa + dd] = f2tf(qb[(long)(b * 9216 + n0 + qq) * 512 + h * 64 + dd]);
    }
    if (t < 128) { m_run[t] = -1e30f; l_run[t] = 0.f; }

    float O[2][4][4];
#pragma unroll
    for (int mi = 0; mi < 2; mi++)
#pragma unroll
        for (int ni = 0; ni < 4; ni++)
#pragma unroll
            for (int c = 0; c < 4; c++) O[mi][ni][c] = 0.f;

    for (int ch = 0; ch < 9; ch++) {
        const int m0c = ch * 64;
        __syncthreads();
#pragma unroll
        for (int r = 0; r < 16; r++) {
            int idx = r * 256 + t;
            int key = idx >> 6, dd = idx & 63;
            Ks[key * TPa + dd] = f2tf(kb[(long)(bh * 576 + m0c + key) * 64 + dd]);
            Vs[dd * TPa + key] = f2tf(vb[(long)(bh * 576 + m0c + key) * 64 + dd]);
        }
        __syncthreads();

        float acc[2][4][4];
#pragma unroll
        for (int mi = 0; mi < 2; mi++)
#pragma unroll
            for (int ni = 0; ni < 4; ni++)
#pragma unroll
                for (int c = 0; c < 4; c++) acc[mi][ni][c] = 0.f;
#pragma unroll
        for (int kk = 0; kk < 64; kk += 8) {
            unsigned af[2][4], bf[4][2];
#pragma unroll
            for (int mi = 0; mi < 2; mi++) {
                const int r = wm * 32 + mi * 16 + g;
                af[mi][0] = Qs[r * TPa + kk + tg];
                af[mi][1] = Qs[(r + 8) * TPa + kk + tg];
                af[mi][2] = Qs[r * TPa + kk + tg + 4];
                af[mi][3] = Qs[(r + 8) * TPa + kk + tg + 4];
            }
#pragma unroll
            for (int ni = 0; ni < 4; ni++) {
                const int rn = wn * 32 + ni * 8 + g;
                bf[ni][0] = Ks[rn * TPa + kk + tg];
                bf[ni][1] = Ks[rn * TPa + kk + tg + 4];
            }
#pragma unroll
            for (int mi = 0; mi < 2; mi++)
#pragma unroll
                for (int ni = 0; ni < 4; ni++)
                    mma8(acc[mi][ni], af[mi], bf[ni]);
        }
#pragma unroll
        for (int mi = 0; mi < 2; mi++) {
            const int r = wm * 32 + mi * 16 + g;
#pragma unroll
            for (int ni = 0; ni < 4; ni++) {
                const int c = wn * 32 + ni * 8 + 2 * tg;
                *(float2*)(Sc + r * TPa + c) =
                    make_float2(acc[mi][ni][0] * 0.125f, acc[mi][ni][1] * 0.125f);
                *(float2*)(Sc + (r + 8) * TPa + c) =
                    make_float2(acc[mi][ni][2] * 0.125f, acc[mi][ni][3] * 0.125f);
            }
        }
        __syncthreads();

        {
            const int row = t >> 1, part = t & 1;
            float cm = -1e30f;
#pragma unroll
            for (int i = 0; i < 32; i++)
                cm = fmaxf(cm, Sc[row * TPa + 2 * i + part]);
            cm = fmaxf(cm, __shfl_xor_sync(0xffffffffu, cm, 1));
            const float nm = fmaxf(m_run[row], cm);
            float sum = 0.f;
#pragma unroll
            for (int i = 0; i < 32; i++) {
                float e  = __expf(Sc[row * TPa + 2 * i + part] - nm);
                float et = __uint_as_float(f2tf(e));
                Sc[row * TPa + 2 * i + part] = et;
                sum += et;
            }
            sum += __shfl_xor_sync(0xffffffffu, sum, 1);
            if (part == 0) {
                float al = __expf(m_run[row] - nm);
                alf[row] = al;
                l_run[row] = l_run[row] * al + sum;
                m_run[row] = nm;
            }
        }
        __syncthreads();

#pragma unroll
        for (int mi = 0; mi < 2; mi++) {
            const int r = wm * 32 + mi * 16 + g;
            const float a0 = alf[r], a1 = alf[r + 8];
#pragma unroll
            for (int ni = 0; ni < 4; ni++) {
                O[mi][ni][0] *= a0; O[mi][ni][1] *= a0;
                O[mi][ni][2] *= a1; O[mi][ni][3] *= a1;
            }
        }
#pragma unroll
        for (int kk = 0; kk < 64; kk += 8) {
            unsigned af[2][4], bf[4][2];
#pragma unroll
            for (int mi = 0; mi < 2; mi++) {
                const int r = wm * 32 + mi * 16 + g;
                af[mi][0] = __float_as_uint(Sc[r * TPa + kk + tg]);
                af[mi][1] = __float_as_uint(Sc[(r + 8) * TPa + kk + tg]);
                af[mi][2] = __float_as_uint(Sc[r * TPa + kk + tg + 4]);
                af[mi][3] = __float_as_uint(Sc[(r + 8) * TPa + kk + tg + 4]);
            }
#pragma unroll
            for (int ni = 0; ni < 4; ni++) {
                const int rn = wn * 32 + ni * 8 + g;
                bf[ni][0] = Vs[rn * TPa + kk + tg];
                bf[ni][1] = Vs[rn * TPa + kk + tg + 4];
            }
#pragma unroll
            for (int mi = 0; mi < 2; mi++)
#pragma unroll
                for (int ni = 0; ni < 4; ni++)
                    mma8(O[mi][ni], af[mi], bf[ni]);
        }
    }

#pragma unroll
    for (int mi = 0; mi < 2; mi++) {
        const int r = wm * 32 + mi * 16 + g;
        const float inv0 = 1.f / l_run[r];
        const float inv1 = 1.f / l_run[r + 8];
#pragma unroll
        for (int ni = 0; ni < 4; ni++) {
            const int c = wn * 32 + ni * 8 + 2 * tg;
            *(float2*)(ctx + (long)(b * 9216 + n0 + r) * 512 + h * 64 + c) =
                make_float2(O[mi][ni][0] * inv0, O[mi][ni][1] * inv0);
            *(float2*)(ctx + (long)(b * 9216 + n0 + r + 8) * 512 + h * 64 + c) =
                make_float2(O[mi][ni][2] * inv1, O[mi][ni][3] * inv1);
        }
    }
}

// ---------------------------------------------------------------------------
// Launch pipeline: two independent chains forked onto a second stream.
//   main  : prep_q_lora -> t1p -> q-GEMM            (needs only x)
//   side  : reorder_w -> conv -> reduce_ln -> kv -> lv -> reduce_build_kv
//   join  : attention -> proj
// ---------------------------------------------------------------------------
extern "C" void kernel_launch(void* const* d_in, const int* in_sizes, int n_in,
                              void* d_out, int out_size)
{
    (void)in_sizes; (void)n_in; (void)out_size;
    const float* x      = (const float*)d_in[0];
    const float* w_q    = (const float*)d_in[1];
    const float* b_q    = (const float*)d_in[2];
    const float* w_kv   = (const float*)d_in[3];
    const float* b_kv   = (const float*)d_in[4];
    const float* w_proj = (const float*)d_in[5];
    const float* b_proj = (const float*)d_in[6];
    const float* w_sr   = (const float*)d_in[7];
    const float* b_sr   = (const float*)d_in[8];
    const float* ln_g   = (const float*)d_in[9];
    const float* ln_b   = (const float*)d_in[10];
    const float* lAq    = (const float*)d_in[11];
    const float* lBq    = (const float*)d_in[12];
    const float* lAv    = (const float*)d_in[13];
    const float* lBv    = (const float*)d_in[14];

    float *q, *xs, *t2, *lv, *k, *v, *ctx, *t1p, *w2, *part, *lAqp, *Bq2;
    cudaGetSymbolAddress((void**)&q,     g_q);
    cudaGetSymbolAddress((void**)&xs,    g_xs);
    cudaGetSymbolAddress((void**)&t2,    g_t2);
    cudaGetSymbolAddress((void**)&lv,    g_lv);
    cudaGetSymbolAddress((void**)&k,     g_k);
    cudaGetSymbolAddress((void**)&v,     g_v);
    cudaGetSymbolAddress((void**)&ctx,   g_ctx);
    cudaGetSymbolAddress((void**)&t1p,   g_t1p);
    cudaGetSymbolAddress((void**)&w2,    g_w2);
    cudaGetSymbolAddress((void**)&part,  g_part);
    cudaGetSymbolAddress((void**)&lAqp,  g_lAqp);
    cudaGetSymbolAddress((void**)&Bq2,   g_Bq2);

    // capture-safe fork stream + events (created once, never destroyed)
    static cudaStream_t s2 = nullptr;
    static cudaEvent_t evF = nullptr, evJ = nullptr;
    if (!s2) {
        cudaStreamCreateWithFlags(&s2, cudaStreamNonBlocking);
        cudaEventCreateWithFlags(&evF, cudaEventDisableTiming);
        cudaEventCreateWithFlags(&evJ, cudaEventDisableTiming);
    }

    dim3 blk(256);
    cudaFuncSetAttribute(attn_flash,
                         cudaFuncAttributeMaxDynamicSharedMemorySize, ATTN_SMEM);

    // ---- fork ----
    cudaEventRecord(evF, 0);
    cudaStreamWaitEvent(s2, evF, 0);

    // ---- side chain (stream s2): xs / k / v ----
    reorder_w_kernel<<<16384, blk, 0, s2>>>(w_sr, w2);
    gemm_tf32<128, 1><<<dim3(4, 9, 8), blk, 0, s2>>>(
        1152, 512, 8192, x, 512, w2, 8192, nullptr, 1.f, nullptr, 512,
        1024, part, nullptr, 0, nullptr, 0, 0);
    reduce_ln<<<1152, 128, 0, s2>>>(part, b_sr, ln_g, ln_b, xs);
    gemm_tf32<128, 0><<<dim3(8, 9, 4), blk, 0, s2>>>(
        1152, 1024, 512, xs, 512, w_kv, 512, nullptr, 1.f, nullptr, 1024,
        128, part, nullptr, 0, nullptr, 0, 0);
    gemm_abt<<<dim3(1, 18), blk, 0, s2>>>(1152, 32, 512, xs, 512, lAv, 512,
                                          t2, 32);
    gemm_tf32<128, 0><<<dim3(4, 9, 1), blk, 0, s2>>>(
        1152, 512, 32, t2, 32, lBv, 32, nullptr, SCALING, lv, 512,
        32, nullptr, nullptr, 0, nullptr, 0, 0);
    reduce_build_kv<<<2304, blk, 0, s2>>>(part, b_kv, lv, k, v);
    cudaEventRecord(evJ, s2);

    // ---- main chain (default stream): q ----
    prep_q_lora<<<128, blk>>>(lAq, lBq, lAqp, Bq2);
    gemm_tf32<64, 0><<<dim3(1, 144, 1), blk>>>(
        18432, 64, 512, x, 512, lAqp, 512, nullptr, 1.f, t1p, 64,
        512, nullptr, nullptr, 0, nullptr, 0, 0);
    gemm_tf32<128, 0><<<dim3(4, 144, 1), blk>>>(
        18432, 512, 512, x, 512, w_q, 512, b_q, 1.f, q, 512,
        512, nullptr, t1p, 64, Bq2, 32, 32);

    // ---- join ----
    cudaStreamWaitEvent(0, evJ, 0);

    attn_flash<<<dim3(72, 16), blk, ATTN_SMEM>>>(q, k, v, ctx);

    gemm_tf32<128, 0><<<dim3(4, 144, 1), blk>>>(
        18432, 512, 512, ctx, 512, w_proj, 512, b_proj, 1.f, (float*)d_out,
        512, 512, nullptr, nullptr, 0, nullptr, 0, 0);
}

// round 8
// speedup vs baseline: 4.1965x; 1.0654x over previous
#include <cuda_runtime.h>
#include <math.h>

// B=2, N=9216, C=512, HEAD=8, d=64, SR=4, H=W=96 -> Nkv=576, R=32
#define SCALING 0.125f

// ---------------------------------------------------------------------------
// Scratch
// ---------------------------------------------------------------------------
__device__ float g_q    [9437184];  // (B,N,C)
__device__ float g_xs   [589824];   // (B*576, 512) post-LN
__device__ float g_t2p  [73728];    // 1152 x 64 lora-v intermediate
__device__ float g_lv   [589824];
__device__ float g_k    [589824];   // (B*H,576,64)
__device__ float g_v    [589824];
__device__ float g_ctx  [9437184];
__device__ float g_t1p  [1179648];  // 18432 x 64 lora-q intermediate
__device__ float g_w2   [4194304];  // 512 x 8192 reordered conv weight
__device__ float g_part [4718592];  // split-K partials
__device__ float g_lAqp [32768];    // 64 x 512 padded lora_A_q
__device__ float g_lAvp [32768];    // 64 x 512 padded lora_A_v
__device__ float g_Bq2  [16384];    // 512 x 32 prescaled lora_B_q

// ---------------------------------------------------------------------------
// tf32 / mma / ldmatrix helpers
// ---------------------------------------------------------------------------
__device__ __forceinline__ unsigned f2tf(float x) {
    unsigned u;
    asm("cvt.rna.tf32.f32 %0, %1;" : "=r"(u) : "f"(x));
    return u;
}
__device__ __forceinline__ void mma8(float* c, const unsigned* a, const unsigned* b) {
    asm volatile(
        "mma.sync.aligned.m16n8k8.row.col.f32.tf32.tf32.f32 "
        "{%0,%1,%2,%3}, {%4,%5,%6,%7}, {%8,%9}, {%0,%1,%2,%3};"
        : "+f"(c[0]), "+f"(c[1]), "+f"(c[2]), "+f"(c[3])
        : "r"(a[0]), "r"(a[1]), "r"(a[2]), "r"(a[3]),
          "r"(b[0]), "r"(b[1]));
}
// one x4 ldmatrix: 4 tiles of 8 rows x 16B
__device__ __forceinline__ void ldsm4(unsigned* r, unsigned addr) {
    asm volatile(
        "ldmatrix.sync.aligned.m8n8.x4.shared.b16 {%0,%1,%2,%3}, [%4];"
        : "=r"(r[0]), "=r"(r[1]), "=r"(r[2]), "=r"(r[3]) : "r"(addr));
}

// ---------------------------------------------------------------------------
// tf32 tensor-core GEMM, 2-stage pipelined, ldmatrix fragment loads:
//   C = scale * (A @ B^T [+ A2 @ B2^T]) (+bias)
// A: MxK row-major, B: NxK row-major. REQUIRES M%128==0, N%BN==0, K%16==0.
// BM=128, BN in {64,128}, BK=16; 256 threads; warps 4(M)x2(N).
// gridDim.z>1: raw partials to `part`.
// CONV=1: A gathered from x with the SR-conv im2col mapping.
// ---------------------------------------------------------------------------
template <int BN, int CONV>
__global__ void __launch_bounds__(256, 2)
gemm_tf32(int M, int N, int K,
          const float* __restrict__ A, int lda,
          const float* __restrict__ B, int ldb,
          const float* __restrict__ bias,
          float scale,
          float* __restrict__ C, int ldc,
          int kchunk, float* __restrict__ part,
          const float* __restrict__ A2, int lda2,
          const float* __restrict__ B2, int ldb2, int K2)
{
    constexpr int NI = BN / 16;
    __shared__ unsigned As[2][128][20];
    __shared__ unsigned Bs[2][BN][20];
    const int t    = threadIdx.x;
    const int lane = t & 31, w = t >> 5;
    const int g  = lane >> 2, tg = lane & 3;
    const int wm = w >> 1,  wn = w & 1;
    const long m0 = (long)blockIdx.y * 128;
    const int  n0 = blockIdx.x * BN;
    const int  kb = blockIdx.z * kchunk;

    const int ar  = t >> 2;
    const int kq4 = (t & 3) * 4;

    // ldmatrix per-lane address bases (byte offsets into As / Bs)
    const int tS = lane >> 3;   // tile index 0..3
    const unsigned asBase = (unsigned)__cvta_generic_to_shared(&As[0][0][0]);
    const unsigned bsBase = (unsigned)__cvta_generic_to_shared(&Bs[0][0][0]);
    const unsigned aOff = ((wm * 32 + (tS & 1) * 8 + (lane & 7)) * 20
                           + (tS >> 1) * 4) * 4;
    const unsigned bOff = ((wn * (BN / 2) + (tS >> 1) * 8 + (lane & 7)) * 20
                           + (tS & 1) * 4) * 4;

    float acc[2][NI][4];
#pragma unroll
    for (int mi = 0; mi < 2; mi++)
#pragma unroll
        for (int ni = 0; ni < NI; ni++)
#pragma unroll
            for (int c = 0; c < 4; c++) acc[mi][ni][c] = 0.f;

    const float* Ap0 = nullptr;
    const float* Ap1 = nullptr;
    long convRow0 = 0, convRow1 = 0;
    if (CONV) {
        int m = (int)m0 + ar;
        int b = m / 576, p = m % 576, py = p / 24, px = p % 24;
        convRow0 = (long)b * 9216 + (py * 4) * 96 + px * 4;
        m = (int)m0 + ar + 64;
        b = m / 576; p = m % 576; py = p / 24; px = p % 24;
        convRow1 = (long)b * 9216 + (py * 4) * 96 + px * 4;
    } else {
        Ap0 = A + (m0 + ar) * lda + kq4;
        Ap1 = A + (m0 + ar + 64) * lda + kq4;
    }
    const float* Bp0 = B + (long)(n0 + ar) * ldb + kq4;
    const float* Bp1 = (BN == 128) ? B + (long)(n0 + ar + 64) * ldb + kq4 : nullptr;

    const int n1 = kchunk >> 4;
    const int n2 = K2 >> 4;
    const int nIter = n1 + n2;

    float4 av0, av1, bv0, bv1;

    auto loadTile = [&](int idx) {
        if (idx < n1) {
            const int k0 = kb + (idx << 4);
            if (CONV) {
                const int s  = k0 >> 9;
                const int ii = s >> 2, jj = s & 3;
                const int ci = (k0 & 511) + kq4;
                av0 = *(const float4*)(A + (convRow0 + ii * 96 + jj) * 512 + ci);
                av1 = *(const float4*)(A + (convRow1 + ii * 96 + jj) * 512 + ci);
            } else {
                av0 = *(const float4*)(Ap0 + k0);
                av1 = *(const float4*)(Ap1 + k0);
            }
            bv0 = *(const float4*)(Bp0 + k0);
            if (BN == 128) bv1 = *(const float4*)(Bp1 + k0);
        } else {
            const int k0 = ((idx - n1) << 4) + kq4;
            av0 = *(const float4*)(A2 + (m0 + ar) * lda2 + k0);
            av1 = *(const float4*)(A2 + (m0 + ar + 64) * lda2 + k0);
            bv0 = *(const float4*)(B2 + (long)(n0 + ar) * ldb2 + k0);
            if (BN == 128)
                bv1 = *(const float4*)(B2 + (long)(n0 + ar + 64) * ldb2 + k0);
        }
    };
    auto storeTile = [&](int buf) {
        uint4 u;
        u.x = f2tf(av0.x); u.y = f2tf(av0.y); u.z = f2tf(av0.z); u.w = f2tf(av0.w);
        *(uint4*)&As[buf][ar][kq4] = u;
        u.x = f2tf(av1.x); u.y = f2tf(av1.y); u.z = f2tf(av1.z); u.w = f2tf(av1.w);
        *(uint4*)&As[buf][ar + 64][kq4] = u;
        u.x = f2tf(bv0.x); u.y = f2tf(bv0.y); u.z = f2tf(bv0.z); u.w = f2tf(bv0.w);
        *(uint4*)&Bs[buf][ar][kq4] = u;
        if (BN == 128) {
            u.x = f2tf(bv1.x); u.y = f2tf(bv1.y);
            u.z = f2tf(bv1.z); u.w = f2tf(bv1.w);
            *(uint4*)&Bs[buf][ar + 64][kq4] = u;
        }
    };

    loadTile(0);
    storeTile(0);
    __syncthreads();
    int buf = 0;
    for (int it = 0; it < nIter; it++) {
        const bool more = (it + 1 < nIter);
        if (more) loadTile(it + 1);
        const unsigned aB = asBase + buf * (128 * 80) + aOff;
        const unsigned bB = bsBase + buf * (BN * 80) + bOff;
#pragma unroll
        for (int kk = 0; kk < 16; kk += 8) {
            unsigned af[2][4], bf[NI][2];
#pragma unroll
            for (int mi = 0; mi < 2; mi++)
                ldsm4(af[mi], aB + mi * (16 * 80) + kk * 4);
#pragma unroll
            for (int p = 0; p < NI / 2; p++) {
                unsigned q4[4];
                ldsm4(q4, bB + p * (16 * 80) + kk * 4);
                bf[2 * p][0] = q4[0]; bf[2 * p][1] = q4[1];
                bf[2 * p + 1][0] = q4[2]; bf[2 * p + 1][1] = q4[3];
            }
#pragma unroll
            for (int mi = 0; mi < 2; mi++)
#pragma unroll
                for (int ni = 0; ni < NI; ni++)
                    mma8(acc[mi][ni], af[mi], bf[ni]);
        }
        if (more) {
            storeTile(buf ^ 1);
            __syncthreads();
            buf ^= 1;
        }
    }

    if (gridDim.z == 1) {
#pragma unroll
        for (int mi = 0; mi < 2; mi++) {
            const long r0 = m0 + wm * 32 + mi * 16 + g;
            const long r1 = r0 + 8;
#pragma unroll
            for (int ni = 0; ni < NI; ni++) {
                const int c = n0 + wn * (BN / 2) + ni * 8 + 2 * tg;
                float v00 = scale * acc[mi][ni][0];
                float v01 = scale * acc[mi][ni][1];
                float v10 = scale * acc[mi][ni][2];
                float v11 = scale * acc[mi][ni][3];
                if (bias) {
                    float b0 = bias[c], b1 = bias[c + 1];
                    v00 += b0; v01 += b1; v10 += b0; v11 += b1;
                }
                *(float2*)(C + r0 * ldc + c) = make_float2(v00, v01);
                *(float2*)(C + r1 * ldc + c) = make_float2(v10, v11);
            }
        }
    } else {
        float* P = part + (long)blockIdx.z * M * ldc;
#pragma unroll
        for (int mi = 0; mi < 2; mi++) {
            const long r0 = m0 + wm * 32 + mi * 16 + g;
            const long r1 = r0 + 8;
#pragma unroll
            for (int ni = 0; ni < NI; ni++) {
                const int c = n0 + wn * (BN / 2) + ni * 8 + 2 * tg;
                *(float2*)(P + r0 * ldc + c) =
                    make_float2(acc[mi][ni][0], acc[mi][ni][1]);
                *(float2*)(P + r1 * ldc + c) =
                    make_float2(acc[mi][ni][2], acc[mi][ni][3]);
            }
        }
    }
}

// ---------------------------------------------------------------------------
// Fused conv split-K reduce + bias + LayerNorm.  One block (128 thr) per row.
// ---------------------------------------------------------------------------
__global__ void reduce_ln(const float* __restrict__ part,
                          const float* __restrict__ bias,
                          const float* __restrict__ gam,
                          const float* __restrict__ bet,
                          float* __restrict__ out)
{
    const int row = blockIdx.x;
    const int t   = threadIdx.x;
    float v[4];
#pragma unroll
    for (int j = 0; j < 4; j++) {
        const int col = t + j * 128;
        float s = bias[col];
        const long off = (long)row * 512 + col;
#pragma unroll
        for (int z = 0; z < 8; z++) s += part[z * 589824 + off];
        v[j] = s;
    }
    float s  = v[0] + v[1] + v[2] + v[3];
    float s2 = v[0]*v[0] + v[1]*v[1] + v[2]*v[2] + v[3]*v[3];
#pragma unroll
    for (int o = 16; o > 0; o >>= 1) {
        s  += __shfl_xor_sync(0xffffffffu, s,  o);
        s2 += __shfl_xor_sync(0xffffffffu, s2, o);
    }
    __shared__ float ss[4], ss2[4];
    if ((t & 31) == 0) { ss[t >> 5] = s; ss2[t >> 5] = s2; }
    __syncthreads();
    s  = ss[0]  + ss[1]  + ss[2]  + ss[3];
    s2 = ss2[0] + ss2[1] + ss2[2] + ss2[3];
    const float mean = s * (1.f / 512.f);
    const float var  = s2 * (1.f / 512.f) - mean * mean;
    const float inv  = rsqrtf(var + 1e-5f);
    float* o = out + (long)row * 512;
#pragma unroll
    for (int j = 0; j < 4; j++) {
        const int col = t + j * 128;
        o[col] = (v[j] - mean) * inv * gam[col] + bet[col];
    }
}

// ---------------------------------------------------------------------------
// Fused kv split-K reduce + bias + head split + LoRA-v raw-reshape fixup.
// ---------------------------------------------------------------------------
__global__ void reduce_build_kv(const float* __restrict__ part,
                                const float* __restrict__ bias,
                                const float* __restrict__ lv,
                                float* __restrict__ k, float* __restrict__ v)
{
    const int idx = blockIdx.x * 256 + threadIdx.x;
    const int dd = idx & 63;
    const int m  = (idx >> 6) % 576;
    const int bh = idx / 36864;
    const int h  = bh & 7, b = bh >> 3;
    const int ck = h * 64 + dd;
    const long mrow = (long)(b * 576 + m) * 1024;
    float sk = bias[ck], sv = bias[512 + ck];
#pragma unroll
    for (int z = 0; z < 4; z++) {
        sk += part[z * 1179648 + mrow + ck];
        sv += part[z * 1179648 + mrow + 512 + ck];
    }
    k[idx] = sk;
    v[idx] = sv + lv[(long)b * 294912 + h * 36864 + m * 64 + dd];
}

// w2[co][(i*4+j)*512 + ci] = w_sr[co][ci][i][j]
__global__ void reorder_w_kernel(const float* __restrict__ w,
                                 float* __restrict__ w2)
{
    const int tid = blockIdx.x * 256 + threadIdx.x;
    const int ci = tid & 511;
    const int s  = (tid >> 9) & 15;
    const int co = tid >> 13;
    w2[tid] = w[(long)co * 8192 + ci * 16 + s];
}

// pad lora_A_q / lora_A_v to 64x512; prescale lora_B_q by SCALING
__global__ void prep_lora(const float* __restrict__ lAq,
                          const float* __restrict__ lBq,
                          const float* __restrict__ lAv,
                          float* __restrict__ lAqp,
                          float* __restrict__ lAvp,
                          float* __restrict__ Bq2)
{
    const int i = blockIdx.x * 256 + threadIdx.x;
    if (i < 64 * 512) {
        lAqp[i] = (i < 32 * 512) ? lAq[i] : 0.f;
        lAvp[i] = (i < 32 * 512) ? lAv[i] : 0.f;
    }
    if (i < 512 * 32) Bq2[i] = lBq[i] * SCALING;
}

// ---------------------------------------------------------------------------
// Flash-style tf32 attention, ldmatrix fragment loads.
// One block = 128 queries x one (b,h). 9 key chunks of 64.
// ---------------------------------------------------------------------------
#define TPa 68
#define ATTN_SMEM ((TPa * 384 + 3 * 128) * 4)

__global__ void __launch_bounds__(256)
attn_flash(const float* __restrict__ qb,
           const float* __restrict__ kb,
           const float* __restrict__ vb,
           float* __restrict__ ctx)
{
    extern __shared__ float sm[];
    unsigned* Qs    = (unsigned*)sm;            // [q][dd]   128*TPa
    unsigned* Ks    = Qs + 128 * TPa;           // [key][dd] 64*TPa
    unsigned* Vs    = Ks + 64 * TPa;            // [dd][key] 64*TPa
    float*    Sc    = (float*)(Vs + 64 * TPa);  // [q][key]  128*TPa
    float*    m_run = Sc + 128 * TPa;
    float*    l_run = m_run + 128;
    float*    alf   = l_run + 128;

    const int t    = threadIdx.x;
    const int lane = t & 31, w = t >> 5;
    const int g  = lane >> 2, tg = lane & 3;
    const int wm = w >> 1,  wn = w & 1;
    const int bh = blockIdx.y, b = bh >> 3, h = bh & 7;
    const int n0 = blockIdx.x * 128;

    // ldmatrix lane bases (pitch TPa words = 272 bytes)
    const int tS = lane >> 3;
    const unsigned qsB = (unsigned)__cvta_generic_to_shared(Qs);
    const unsigned ksB = (unsigned)__cvta_generic_to_shared(Ks);
    const unsigned vsB = (unsigned)__cvta_generic_to_shared(Vs);
    const unsigned scB = (unsigned)__cvta_generic_to_shared(Sc);
    const unsigned aRow = (wm * 32 + (tS & 1) * 8 + (lane & 7));
    const unsigned aOff = (aRow * TPa + (tS >> 1) * 4) * 4;
    const unsigned bRow = (wn * 32 + (tS >> 1) * 8 + (lane & 7));
    const unsigned bOff = (bRow * TPa + (tS & 1) * 4) * 4;

#pragma unroll
    for (int r = 0; r < 32; r++) {
        int idx = r * 256 + t;
        int qq = idx >> 6, dd = idx & 63;
        Qs[qq * TPa + dd] = f2tf(qb[(long)(b * 9216 + n0 + qq) * 512 + h * 64 + dd]);
    }
    if (t < 128) { m_run[t] = -1e30f; l_run[t] = 0.f; }

    float O[2][4][4];
#pragma unroll
    for (int mi = 0; mi < 2; mi++)
#pragma unroll
        for (int ni = 0; ni < 4; ni++)
#pragma unroll
            for (int c = 0; c < 4; c++) O[mi][ni][c] = 0.f;

    for (int ch = 0; ch < 9; ch++) {
        const int m0c = ch * 64;
        __syncthreads();
#pragma unroll
        for (int r = 0; r < 16; r++) {
            int idx = r * 256 + t;
            int key = idx >> 6, dd = idx & 63;
            Ks[key * TPa + dd] = f2tf(kb[(long)(bh * 576 + m0c + key) * 64 + dd]);
            Vs[dd * TPa + key] = f2tf(vb[(long)(bh * 576 + m0c + key) * 64 + dd]);
        }
        __syncthreads();

        // --- S chunk = (Q K^T) * 0.125 ---
        float acc[2][4][4];
#pragma unroll
        for (int mi = 0; mi < 2; mi++)
#pragma unroll
            for (int ni = 0; ni < 4; ni++)
#pragma unroll
                for (int c = 0; c < 4; c++) acc[mi][ni][c] = 0.f;
#pragma unroll
        for (int kk = 0; kk < 64; kk += 8) {
            unsigned af[2][4], bf[4][2];
#pragma unroll
            for (int mi = 0; mi < 2; mi++)
                ldsm4(af[mi], qsB + aOff + mi * (16 * TPa * 4) + kk * 4);
#pragma unroll
            for (int p = 0; p < 2; p++) {
                unsigned q4[4];
                ldsm4(q4, ksB + bOff + p * (16 * TPa * 4) + kk * 4);
                bf[2 * p][0] = q4[0]; bf[2 * p][1] = q4[1];
                bf[2 * p + 1][0] = q4[2]; bf[2 * p + 1][1] = q4[3];
            }
#pragma unroll
            for (int mi = 0; mi < 2; mi++)
#pragma unroll
                for (int ni = 0; ni < 4; ni++)
                    mma8(acc[mi][ni], af[mi], bf[ni]);
        }
#pragma unroll
        for (int mi = 0; mi < 2; mi++) {
            const int r = wm * 32 + mi * 16 + g;
#pragma unroll
            for (int ni = 0; ni < 4; ni++) {
                const int c = wn * 32 + ni * 8 + 2 * tg;
                *(float2*)(Sc + r * TPa + c) =
                    make_float2(acc[mi][ni][0] * 0.125f, acc[mi][ni][1] * 0.125f);
                *(float2*)(Sc + (r + 8) * TPa + c) =
                    make_float2(acc[mi][ni][2] * 0.125f, acc[mi][ni][3] * 0.125f);
            }
        }
        __syncthreads();

        // --- online softmax stats (2 threads per row) ---
        {
            const int row = t >> 1, part = t & 1;
            float cm = -1e30f;
#pragma unroll
            for (int i = 0; i < 32; i++)
                cm = fmaxf(cm, Sc[row * TPa + 2 * i + part]);
            cm = fmaxf(cm, __shfl_xor_sync(0xffffffffu, cm, 1));
            const float nm = fmaxf(m_run[row], cm);
            float sum = 0.f;
#pragma unroll
            for (int i = 0; i < 32; i++) {
                float e  = __expf(Sc[row * TPa + 2 * i + part] - nm);
                float et = __uint_as_float(f2tf(e));
                Sc[row * TPa + 2 * i + part] = et;
                sum += et;
            }
            sum += __shfl_xor_sync(0xffffffffu, sum, 1);
            if (part == 0) {
                float al = __expf(m_run[row] - nm);
                alf[row] = al;
                l_run[row] = l_run[row] * al + sum;
                m_run[row] = nm;
            }
        }
        __syncthreads();

        // --- rescale O and accumulate P @ V ---
#pragma unroll
        for (int mi = 0; mi < 2; mi++) {
            const int r = wm * 32 + mi * 16 + g;
            const float a0 = alf[r], a1 = alf[r + 8];
#pragma unroll
            for (int ni = 0; ni < 4; ni++) {
                O[mi][ni][0] *= a0; O[mi][ni][1] *= a0;
                O[mi][ni][2] *= a1; O[mi][ni][3] *= a1;
            }
        }
#pragma unroll
        for (int kk = 0; kk < 64; kk += 8) {
            unsigned af[2][4], bf[4][2];
#pragma unroll
            for (int mi = 0; mi < 2; mi++)
                ldsm4(af[mi], scB + aOff + mi * (16 * TPa * 4) + kk * 4);
#pragma unroll
            for (int p = 0; p < 2; p++) {
                unsigned q4[4];
                ldsm4(q4, vsB + bOff + p * (16 * TPa * 4) + kk * 4);
                bf[2 * p][0] = q4[0]; bf[2 * p][1] = q4[1];
                bf[2 * p + 1][0] = q4[2]; bf[2 * p + 1][1] = q4[3];
            }
#pragma unroll
            for (int mi = 0; mi < 2; mi++)
#pragma unroll
                for (int ni = 0; ni < 4; ni++)
                    mma8(O[mi][ni], af[mi], bf[ni]);
        }
    }

#pragma unroll
    for (int mi = 0; mi < 2; mi++) {
        const int r = wm * 32 + mi * 16 + g;
        const float inv0 = 1.f / l_run[r];
        const float inv1 = 1.f / l_run[r + 8];
#pragma unroll
        for (int ni = 0; ni < 4; ni++) {
            const int c = wn * 32 + ni * 8 + 2 * tg;
            *(float2*)(ctx + (long)(b * 9216 + n0 + r) * 512 + h * 64 + c) =
                make_float2(O[mi][ni][0] * inv0, O[mi][ni][1] * inv0);
            *(float2*)(ctx + (long)(b * 9216 + n0 + r + 8) * 512 + h * 64 + c) =
                make_float2(O[mi][ni][2] * inv1, O[mi][ni][3] * inv1);
        }
    }
}

// ---------------------------------------------------------------------------
// Launch pipeline: two chains forked onto a second stream.
// ---------------------------------------------------------------------------
extern "C" void kernel_launch(void* const* d_in, const int* in_sizes, int n_in,
                              void* d_out, int out_size)
{
    (void)in_sizes; (void)n_in; (void)out_size;
    const float* x      = (const float*)d_in[0];
    const float* w_q    = (const float*)d_in[1];
    const float* b_q    = (const float*)d_in[2];
    const float* w_kv   = (const float*)d_in[3];
    const float* b_kv   = (const float*)d_in[4];
    const float* w_proj = (const float*)d_in[5];
    const float* b_proj = (const float*)d_in[6];
    const float* w_sr   = (const float*)d_in[7];
    const float* b_sr   = (const float*)d_in[8];
    const float* ln_g   = (const float*)d_in[9];
    const float* ln_b   = (const float*)d_in[10];
    const float* lAq    = (const float*)d_in[11];
    const float* lBq    = (const float*)d_in[12];
    const float* lAv    = (const float*)d_in[13];
    const float* lBv    = (const float*)d_in[14];

    float *q, *xs, *t2p, *lv, *k, *v, *ctx, *t1p, *w2, *part;
    float *lAqp, *lAvp, *Bq2;
    cudaGetSymbolAddress((void**)&q,     g_q);
    cudaGetSymbolAddress((void**)&xs,    g_xs);
    cudaGetSymbolAddress((void**)&t2p,   g_t2p);
    cudaGetSymbolAddress((void**)&lv,    g_lv);
    cudaGetSymbolAddress((void**)&k,     g_k);
    cudaGetSymbolAddress((void**)&v,     g_v);
    cudaGetSymbolAddress((void**)&ctx,   g_ctx);
    cudaGetSymbolAddress((void**)&t1p,   g_t1p);
    cudaGetSymbolAddress((void**)&w2,    g_w2);
    cudaGetSymbolAddress((void**)&part,  g_part);
    cudaGetSymbolAddress((void**)&lAqp,  g_lAqp);
    cudaGetSymbolAddress((void**)&lAvp,  g_lAvp);
    cudaGetSymbolAddress((void**)&Bq2,   g_Bq2);

    static cudaStream_t s2 = nullptr;
    static cudaEvent_t evF = nullptr, evJ = nullptr;
    if (!s2) {
        cudaStreamCreateWithFlags(&s2, cudaStreamNonBlocking);
        cudaEventCreateWithFlags(&evF, cudaEventDisableTiming);
        cudaEventCreateWithFlags(&evJ, cudaEventDisableTiming);
    }

    dim3 blk(256);
    cudaFuncSetAttribute(attn_flash,
                         cudaFuncAttributeMaxDynamicSharedMemorySize, ATTN_SMEM);

    // prep (both chains depend on it)
    prep_lora<<<128, blk>>>(lAq, lBq, lAv, lAqp, lAvp, Bq2);

    // ---- fork ----
    cudaEventRecord(evF, 0);
    cudaStreamWaitEvent(s2, evF, 0);

    // ---- side chain (stream s2): xs / k / v ----
    reorder_w_kernel<<<16384, blk, 0, s2>>>(w_sr, w2);
    gemm_tf32<128, 1><<<dim3(4, 9, 8), blk, 0, s2>>>(
        1152, 512, 8192, x, 512, w2, 8192, nullptr, 1.f, nullptr, 512,
        1024, part, nullptr, 0, nullptr, 0, 0);
    reduce_ln<<<1152, 128, 0, s2>>>(part, b_sr, ln_g, ln_b, xs);
    gemm_tf32<128, 0><<<dim3(8, 9, 4), blk, 0, s2>>>(
        1152, 1024, 512, xs, 512, w_kv, 512, nullptr, 1.f, nullptr, 1024,
        128, part, nullptr, 0, nullptr, 0, 0);
    gemm_tf32<64, 0><<<dim3(1, 9, 1), blk, 0, s2>>>(
        1152, 64, 512, xs, 512, lAvp, 512, nullptr, 1.f, t2p, 64,
        512, nullptr, nullptr, 0, nullptr, 0, 0);
    gemm_tf32<128, 0><<<dim3(4, 9, 1), blk, 0, s2>>>(
        1152, 512, 32, t2p, 64, lBv, 32, nullptr, SCALING, lv, 512,
        32, nullptr, nullptr, 0, nullptr, 0, 0);
    reduce_build_kv<<<2304, blk, 0, s2>>>(part, b_kv, lv, k, v);
    cudaEventRecord(evJ, s2);

    // ---- main chain (default stream): q ----
    gemm_tf32<64, 0><<<dim3(1, 144, 1), blk>>>(
        18432, 64, 512, x, 512, lAqp, 512, nullptr, 1.f, t1p, 64,
        512, nullptr, nullptr, 0, nullptr, 0, 0);
    gemm_tf32<128, 0><<<dim3(4, 144, 1), blk>>>(
        18432, 512, 512, x, 512, w_q, 512, b_q, 1.f, q, 512,
        512, nullptr, t1p, 64, Bq2, 32, 32);

    // ---- join ----
    cudaStreamWaitEvent(0, evJ, 0);

    attn_flash<<<dim3(72, 16), blk, ATTN_SMEM>>>(q, k, v, ctx);

    gemm_tf32<128, 0><<<dim3(4, 144, 1), blk>>>(
        18432, 512, 512, ctx, 512, w_proj, 512, b_proj, 1.f, (float*)d_out,
        512, 512, nullptr, nullptr, 0, nullptr, 0, 0);
}

// round 9
// speedup vs baseline: 4.7091x; 1.1222x over previous
#include <cuda_runtime.h>
#include <math.h>

// B=2, N=9216, C=512, HEAD=8, d=64, SR=4, H=W=96 -> Nkv=576, R=32
#define SCALING 0.125f

// ---------------------------------------------------------------------------
// Scratch
// ---------------------------------------------------------------------------
__device__ float g_q    [9437184];  // (B,N,C)
__device__ float g_xs   [589824];   // (B*576, 512) post-LN
__device__ float g_t2p  [73728];    // 1152 x 64 lora-v intermediate
__device__ float g_lv   [589824];
__device__ float g_k    [589824];   // (B*H,576,64)
__device__ float g_v    [589824];
__device__ float g_ctx  [9437184];
__device__ float g_t1p  [1179648];  // 18432 x 64 lora-q intermediate
__device__ float g_w2   [4194304];  // 512 x 8192 reordered conv weight
__device__ float g_part [4718592];  // split-K partials
__device__ float g_lAqp [32768];    // 64 x 512 padded lora_A_q
__device__ float g_lAvp [32768];    // 64 x 512 padded lora_A_v
__device__ float g_Bq2  [16384];    // 512 x 32 prescaled lora_B_q

// ---------------------------------------------------------------------------
// tf32 / mma / ldmatrix helpers
// ---------------------------------------------------------------------------
__device__ __forceinline__ unsigned f2tf(float x) {
    unsigned u;
    asm("cvt.rna.tf32.f32 %0, %1;" : "=r"(u) : "f"(x));
    return u;
}
__device__ __forceinline__ void mma8(float* c, const unsigned* a, const unsigned* b) {
    asm volatile(
        "mma.sync.aligned.m16n8k8.row.col.f32.tf32.tf32.f32 "
        "{%0,%1,%2,%3}, {%4,%5,%6,%7}, {%8,%9}, {%0,%1,%2,%3};"
        : "+f"(c[0]), "+f"(c[1]), "+f"(c[2]), "+f"(c[3])
        : "r"(a[0]), "r"(a[1]), "r"(a[2]), "r"(a[3]),
          "r"(b[0]), "r"(b[1]));
}
__device__ __forceinline__ void ldsm4(unsigned* r, unsigned addr) {
    asm volatile(
        "ldmatrix.sync.aligned.m8n8.x4.shared.b16 {%0,%1,%2,%3}, [%4];"
        : "=r"(r[0]), "=r"(r[1]), "=r"(r[2]), "=r"(r[3]) : "r"(addr));
}

// ---------------------------------------------------------------------------
// tf32 tensor-core GEMM, 2-stage pipelined, ldmatrix fragment loads:
//   C = scale * (A @ B^T [+ A2 @ B2^T]) (+bias)
// ---------------------------------------------------------------------------
template <int BN, int CONV>
__global__ void __launch_bounds__(256, 2)
gemm_tf32(int M, int N, int K,
          const float* __restrict__ A, int lda,
          const float* __restrict__ B, int ldb,
          const float* __restrict__ bias,
          float scale,
          float* __restrict__ C, int ldc,
          int kchunk, float* __restrict__ part,
          const float* __restrict__ A2, int lda2,
          const float* __restrict__ B2, int ldb2, int K2)
{
    constexpr int NI = BN / 16;
    __shared__ unsigned As[2][128][20];
    __shared__ unsigned Bs[2][BN][20];
    const int t    = threadIdx.x;
    const int lane = t & 31, w = t >> 5;
    const int g  = lane >> 2, tg = lane & 3;
    const int wm = w >> 1,  wn = w & 1;
    const long m0 = (long)blockIdx.y * 128;
    const int  n0 = blockIdx.x * BN;
    const int  kb = blockIdx.z * kchunk;

    const int ar  = t >> 2;
    const int kq4 = (t & 3) * 4;

    const int tS = lane >> 3;
    const unsigned asBase = (unsigned)__cvta_generic_to_shared(&As[0][0][0]);
    const unsigned bsBase = (unsigned)__cvta_generic_to_shared(&Bs[0][0][0]);
    const unsigned aOff = ((wm * 32 + (tS & 1) * 8 + (lane & 7)) * 20
                           + (tS >> 1) * 4) * 4;
    const unsigned bOff = ((wn * (BN / 2) + (tS >> 1) * 8 + (lane & 7)) * 20
                           + (tS & 1) * 4) * 4;

    float acc[2][NI][4];
#pragma unroll
    for (int mi = 0; mi < 2; mi++)
#pragma unroll
        for (int ni = 0; ni < NI; ni++)
#pragma unroll
            for (int c = 0; c < 4; c++) acc[mi][ni][c] = 0.f;

    const float* Ap0 = nullptr;
    const float* Ap1 = nullptr;
    long convRow0 = 0, convRow1 = 0;
    if (CONV) {
        int m = (int)m0 + ar;
        int b = m / 576, p = m % 576, py = p / 24, px = p % 24;
        convRow0 = (long)b * 9216 + (py * 4) * 96 + px * 4;
        m = (int)m0 + ar + 64;
        b = m / 576; p = m % 576; py = p / 24; px = p % 24;
        convRow1 = (long)b * 9216 + (py * 4) * 96 + px * 4;
    } else {
        Ap0 = A + (m0 + ar) * lda + kq4;
        Ap1 = A + (m0 + ar + 64) * lda + kq4;
    }
    const float* Bp0 = B + (long)(n0 + ar) * ldb + kq4;
    const float* Bp1 = (BN == 128) ? B + (long)(n0 + ar + 64) * ldb + kq4 : nullptr;

    const int n1 = kchunk >> 4;
    const int n2 = K2 >> 4;
    const int nIter = n1 + n2;

    float4 av0, av1, bv0, bv1;

    auto loadTile = [&](int idx) {
        if (idx < n1) {
            const int k0 = kb + (idx << 4);
            if (CONV) {
                const int s  = k0 >> 9;
                const int ii = s >> 2, jj = s & 3;
                const int ci = (k0 & 511) + kq4;
                av0 = *(const float4*)(A + (convRow0 + ii * 96 + jj) * 512 + ci);
                av1 = *(const float4*)(A + (convRow1 + ii * 96 + jj) * 512 + ci);
            } else {
                av0 = *(const float4*)(Ap0 + k0);
                av1 = *(const float4*)(Ap1 + k0);
            }
            bv0 = *(const float4*)(Bp0 + k0);
            if (BN == 128) bv1 = *(const float4*)(Bp1 + k0);
        } else {
            const int k0 = ((idx - n1) << 4) + kq4;
            av0 = *(const float4*)(A2 + (m0 + ar) * lda2 + k0);
            av1 = *(const float4*)(A2 + (m0 + ar + 64) * lda2 + k0);
            bv0 = *(const float4*)(B2 + (long)(n0 + ar) * ldb2 + k0);
            if (BN == 128)
                bv1 = *(const float4*)(B2 + (long)(n0 + ar + 64) * ldb2 + k0);
        }
    };
    auto storeTile = [&](int buf) {
        uint4 u;
        u.x = f2tf(av0.x); u.y = f2tf(av0.y); u.z = f2tf(av0.z); u.w = f2tf(av0.w);
        *(uint4*)&As[buf][ar][kq4] = u;
        u.x = f2tf(av1.x); u.y = f2tf(av1.y); u.z = f2tf(av1.z); u.w = f2tf(av1.w);
        *(uint4*)&As[buf][ar + 64][kq4] = u;
        u.x = f2tf(bv0.x); u.y = f2tf(bv0.y); u.z = f2tf(bv0.z); u.w = f2tf(bv0.w);
        *(uint4*)&Bs[buf][ar][kq4] = u;
        if (BN == 128) {
            u.x = f2tf(bv1.x); u.y = f2tf(bv1.y);
            u.z = f2tf(bv1.z); u.w = f2tf(bv1.w);
            *(uint4*)&Bs[buf][ar + 64][kq4] = u;
        }
    };

    loadTile(0);
    storeTile(0);
    __syncthreads();
    int buf = 0;
    for (int it = 0; it < nIter; it++) {
        const bool more = (it + 1 < nIter);
        if (more) loadTile(it + 1);
        const unsigned aB = asBase + buf * (128 * 80) + aOff;
        const unsigned bB = bsBase + buf * (BN * 80) + bOff;
#pragma unroll
        for (int kk = 0; kk < 16; kk += 8) {
            unsigned af[2][4], bf[NI][2];
#pragma unroll
            for (int mi = 0; mi < 2; mi++)
                ldsm4(af[mi], aB + mi * (16 * 80) + kk * 4);
#pragma unroll
            for (int p = 0; p < NI / 2; p++) {
                unsigned q4[4];
                ldsm4(q4, bB + p * (16 * 80) + kk * 4);
                bf[2 * p][0] = q4[0]; bf[2 * p][1] = q4[1];
                bf[2 * p + 1][0] = q4[2]; bf[2 * p + 1][1] = q4[3];
            }
#pragma unroll
            for (int mi = 0; mi < 2; mi++)
#pragma unroll
                for (int ni = 0; ni < NI; ni++)
                    mma8(acc[mi][ni], af[mi], bf[ni]);
        }
        if (more) {
            storeTile(buf ^ 1);
            __syncthreads();
            buf ^= 1;
        }
    }

    if (gridDim.z == 1) {
#pragma unroll
        for (int mi = 0; mi < 2; mi++) {
            const long r0 = m0 + wm * 32 + mi * 16 + g;
            const long r1 = r0 + 8;
#pragma unroll
            for (int ni = 0; ni < NI; ni++) {
                const int c = n0 + wn * (BN / 2) + ni * 8 + 2 * tg;
                float v00 = scale * acc[mi][ni][0];
                float v01 = scale * acc[mi][ni][1];
                float v10 = scale * acc[mi][ni][2];
                float v11 = scale * acc[mi][ni][3];
                if (bias) {
                    float b0 = bias[c], b1 = bias[c + 1];
                    v00 += b0; v01 += b1; v10 += b0; v11 += b1;
                }
                *(float2*)(C + r0 * ldc + c) = make_float2(v00, v01);
                *(float2*)(C + r1 * ldc + c) = make_float2(v10, v11);
            }
        }
    } else {
        float* P = part + (long)blockIdx.z * M * ldc;
#pragma unroll
        for (int mi = 0; mi < 2; mi++) {
            const long r0 = m0 + wm * 32 + mi * 16 + g;
            const long r1 = r0 + 8;
#pragma unroll
            for (int ni = 0; ni < NI; ni++) {
                const int c = n0 + wn * (BN / 2) + ni * 8 + 2 * tg;
                *(float2*)(P + r0 * ldc + c) =
                    make_float2(acc[mi][ni][0], acc[mi][ni][1]);
                *(float2*)(P + r1 * ldc + c) =
                    make_float2(acc[mi][ni][2], acc[mi][ni][3]);
            }
        }
    }
}

// ---------------------------------------------------------------------------
// Fused conv split-K reduce + bias + LayerNorm.
// ---------------------------------------------------------------------------
__global__ void reduce_ln(const float* __restrict__ part,
                          const float* __restrict__ bias,
                          const float* __restrict__ gam,
                          const float* __restrict__ bet,
                          float* __restrict__ out)
{
    const int row = blockIdx.x;
    const int t   = threadIdx.x;
    float v[4];
#pragma unroll
    for (int j = 0; j < 4; j++) {
        const int col = t + j * 128;
        float s = bias[col];
        const long off = (long)row * 512 + col;
#pragma unroll
        for (int z = 0; z < 8; z++) s += part[z * 589824 + off];
        v[j] = s;
    }
    float s  = v[0] + v[1] + v[2] + v[3];
    float s2 = v[0]*v[0] + v[1]*v[1] + v[2]*v[2] + v[3]*v[3];
#pragma unroll
    for (int o = 16; o > 0; o >>= 1) {
        s  += __shfl_xor_sync(0xffffffffu, s,  o);
        s2 += __shfl_xor_sync(0xffffffffu, s2, o);
    }
    __shared__ float ss[4], ss2[4];
    if ((t & 31) == 0) { ss[t >> 5] = s; ss2[t >> 5] = s2; }
    __syncthreads();
    s  = ss[0]  + ss[1]  + ss[2]  + ss[3];
    s2 = ss2[0] + ss2[1] + ss2[2] + ss2[3];
    const float mean = s * (1.f / 512.f);
    const float var  = s2 * (1.f / 512.f) - mean * mean;
    const float inv  = rsqrtf(var + 1e-5f);
    float* o = out + (long)row * 512;
#pragma unroll
    for (int j = 0; j < 4; j++) {
        const int col = t + j * 128;
        o[col] = (v[j] - mean) * inv * gam[col] + bet[col];
    }
}

// ---------------------------------------------------------------------------
// Fused kv split-K reduce + bias + head split + LoRA-v raw-reshape fixup.
// ---------------------------------------------------------------------------
__global__ void reduce_build_kv(const float* __restrict__ part,
                                const float* __restrict__ bias,
                                const float* __restrict__ lv,
                                float* __restrict__ k, float* __restrict__ v)
{
    const int idx = blockIdx.x * 256 + threadIdx.x;
    const int dd = idx & 63;
    const int m  = (idx >> 6) % 576;
    const int bh = idx / 36864;
    const int h  = bh & 7, b = bh >> 3;
    const int ck = h * 64 + dd;
    const long mrow = (long)(b * 576 + m) * 1024;
    float sk = bias[ck], sv = bias[512 + ck];
#pragma unroll
    for (int z = 0; z < 4; z++) {
        sk += part[z * 1179648 + mrow + ck];
        sv += part[z * 1179648 + mrow + 512 + ck];
    }
    k[idx] = sk;
    v[idx] = sv + lv[(long)b * 294912 + h * 36864 + m * 64 + dd];
}

// w2[co][(i*4+j)*512 + ci] = w_sr[co][ci][i][j]
__global__ void reorder_w_kernel(const float* __restrict__ w,
                                 float* __restrict__ w2)
{
    const int tid = blockIdx.x * 256 + threadIdx.x;
    const int ci = tid & 511;
    const int s  = (tid >> 9) & 15;
    const int co = tid >> 13;
    w2[tid] = w[(long)co * 8192 + ci * 16 + s];
}

// pad lora_A_q / lora_A_v to 64x512; prescale lora_B_q by SCALING
__global__ void prep_lora(const float* __restrict__ lAq,
                          const float* __restrict__ lBq,
                          const float* __restrict__ lAv,
                          float* __restrict__ lAqp,
                          float* __restrict__ lAvp,
                          float* __restrict__ Bq2)
{
    const int i = blockIdx.x * 256 + threadIdx.x;
    if (i < 64 * 512) {
        lAqp[i] = (i < 32 * 512) ? lAq[i] : 0.f;
        lAvp[i] = (i < 32 * 512) ? lAv[i] : 0.f;
    }
    if (i < 512 * 32) Bq2[i] = lBq[i] * SCALING;
}

// ---------------------------------------------------------------------------
// FA2-style tf32 attention. Block = 128 q-rows x one (b,h); 8 warps, each
// owning 16 q-rows x the FULL 64-key chunk. Softmax entirely in registers;
// P relayout via per-warp private smem scratch (+ __syncwarp only).
// Smem: Sw(Q stage / P scratch) 128x68 + Ks 64x68 + Vs[dd][key] 64x68 = 68KB.
// ---------------------------------------------------------------------------
#define TPw 68
#define ATTN_SMEM (TPw * 256 * 4)   // (128 + 64 + 64) rows * 68 * 4B

__global__ void __launch_bounds__(256, 2)
attn_flash(const float* __restrict__ qb,
           const float* __restrict__ kb,
           const float* __restrict__ vb,
           float* __restrict__ ctx)
{
    extern __shared__ float sm[];
    float*    Sw = sm;                          // 128 x TPw
    unsigned* Ks = (unsigned*)(sm + 128 * TPw); // 64 x TPw  [key][dd]
    unsigned* Vs = Ks + 64 * TPw;               // 64 x TPw  [dd][key]

    const int t    = threadIdx.x;
    const int lane = t & 31, w = t >> 5;
    const int g  = lane >> 2, tg = lane & 3;
    const int bh = blockIdx.y, b = bh >> 3, h = bh & 7;
    const int n0 = blockIdx.x * 128;

    const int tS = lane >> 3;
    const unsigned swB = (unsigned)__cvta_generic_to_shared(Sw);
    const unsigned ksB = (unsigned)__cvta_generic_to_shared(Ks);
    const unsigned vsB = (unsigned)__cvta_generic_to_shared(Vs);
    // A-frag base (own warp's 16 rows) and B-frag base (shared K/V tiles)
    const unsigned aOff = ((w * 16 + (tS & 1) * 8 + (lane & 7)) * TPw
                           + (tS >> 1) * 4) * 4;
    const unsigned bOff = (((tS >> 1) * 8 + (lane & 7)) * TPw
                           + (tS & 1) * 4) * 4;

    // ---- stage Q (prescaled by 0.125, tf32) into Sw, extract frags ----
#pragma unroll
    for (int r = 0; r < 8; r++) {
        int idx = r * 256 + t;
        int qq = idx >> 4, d4 = (idx & 15) * 4;
        float4 qv = *(const float4*)(qb + (long)(b * 9216 + n0 + qq) * 512
                                        + h * 64 + d4);
        uint4 u;
        u.x = f2tf(qv.x * 0.125f); u.y = f2tf(qv.y * 0.125f);
        u.z = f2tf(qv.z * 0.125f); u.w = f2tf(qv.w * 0.125f);
        *(uint4*)&Sw[qq * TPw + d4] = u;
    }
    __syncthreads();
    unsigned Qf[8][4];
#pragma unroll
    for (int kk = 0; kk < 8; kk++)
        ldsm4(Qf[kk], swB + aOff + kk * 32);
    // own-region read; no cross-warp hazard yet

    float O[8][4];
#pragma unroll
    for (int nd = 0; nd < 8; nd++)
#pragma unroll
        for (int c = 0; c < 4; c++) O[nd][c] = 0.f;
    float m0 = -1e30f, l0 = 0.f, m1 = -1e30f, l1 = 0.f;

    for (int ch = 0; ch < 9; ch++) {
        __syncthreads();   // all warps done with prev K/V (and Q extraction)
        // load K (row-major) + V (transposed) as tf32
#pragma unroll
        for (int r = 0; r < 4; r++) {
            int idx = r * 256 + t;
            int key = idx >> 4, d4 = (idx & 15) * 4;
            long src = (long)(bh * 576 + ch * 64 + key) * 64 + d4;
            float4 kv4 = *(const float4*)(kb + src);
            float4 vv4 = *(const float4*)(vb + src);
            uint4 ku;
            ku.x = f2tf(kv4.x); ku.y = f2tf(kv4.y);
            ku.z = f2tf(kv4.z); ku.w = f2tf(kv4.w);
            *(uint4*)&Ks[key * TPw + d4] = ku;
            Vs[(d4 + 0) * TPw + key] = f2tf(vv4.x);
            Vs[(d4 + 1) * TPw + key] = f2tf(vv4.y);
            Vs[(d4 + 2) * TPw + key] = f2tf(vv4.z);
            Vs[(d4 + 3) * TPw + key] = f2tf(vv4.w);
        }
        __syncthreads();

        // ---- S = Q K^T (Q prescaled) : per warp 16 x 64 ----
        float acc[8][4];
#pragma unroll
        for (int ni = 0; ni < 8; ni++)
#pragma unroll
            for (int c = 0; c < 4; c++) acc[ni][c] = 0.f;
#pragma unroll
        for (int kk = 0; kk < 8; kk++) {
            unsigned bf[8][2];
#pragma unroll
            for (int p = 0; p < 4; p++) {
                unsigned q4[4];
                ldsm4(q4, ksB + bOff + p * (16 * TPw * 4) + kk * 32);
                bf[2 * p][0] = q4[0]; bf[2 * p][1] = q4[1];
                bf[2 * p + 1][0] = q4[2]; bf[2 * p + 1][1] = q4[3];
            }
#pragma unroll
            for (int ni = 0; ni < 8; ni++)
                mma8(acc[ni], Qf[kk], bf[ni]);
        }

        // ---- online softmax in registers (rows g and g+8) ----
        float cm0 = -1e30f, cm1 = -1e30f;
#pragma unroll
        for (int ni = 0; ni < 8; ni++) {
            cm0 = fmaxf(cm0, fmaxf(acc[ni][0], acc[ni][1]));
            cm1 = fmaxf(cm1, fmaxf(acc[ni][2], acc[ni][3]));
        }
        cm0 = fmaxf(cm0, __shfl_xor_sync(0xffffffffu, cm0, 1));
        cm0 = fmaxf(cm0, __shfl_xor_sync(0xffffffffu, cm0, 2));
        cm1 = fmaxf(cm1, __shfl_xor_sync(0xffffffffu, cm1, 1));
        cm1 = fmaxf(cm1, __shfl_xor_sync(0xffffffffu, cm1, 2));
        const float nm0 = fmaxf(m0, cm0), nm1 = fmaxf(m1, cm1);
        const float al0 = __expf(m0 - nm0), al1 = __expf(m1 - nm1);
        float sum0 = 0.f, sum1 = 0.f;
#pragma unroll
        for (int ni = 0; ni < 8; ni++) {
            float e0 = __uint_as_float(f2tf(__expf(acc[ni][0] - nm0)));
            float e1 = __uint_as_float(f2tf(__expf(acc[ni][1] - nm0)));
            float e2 = __uint_as_float(f2tf(__expf(acc[ni][2] - nm1)));
            float e3 = __uint_as_float(f2tf(__expf(acc[ni][3] - nm1)));
            acc[ni][0] = e0; acc[ni][1] = e1; acc[ni][2] = e2; acc[ni][3] = e3;
            sum0 += e0 + e1; sum1 += e2 + e3;
        }
        sum0 += __shfl_xor_sync(0xffffffffu, sum0, 1);
        sum0 += __shfl_xor_sync(0xffffffffu, sum0, 2);
        sum1 += __shfl_xor_sync(0xffffffffu, sum1, 1);
        sum1 += __shfl_xor_sync(0xffffffffu, sum1, 2);
        l0 = l0 * al0 + sum0; l1 = l1 * al1 + sum1;
        m0 = nm0; m1 = nm1;
        // rescale O
#pragma unroll
        for (int nd = 0; nd < 8; nd++) {
            O[nd][0] *= al0; O[nd][1] *= al0;
            O[nd][2] *= al1; O[nd][3] *= al1;
        }

        // ---- P: C-frag -> per-warp smem scratch -> A-frag ----
        float* SwW = Sw + w * 16 * TPw;
#pragma unroll
        for (int ni = 0; ni < 8; ni++) {
            *(float2*)&SwW[g * TPw + ni * 8 + 2 * tg] =
                make_float2(acc[ni][0], acc[ni][1]);
            *(float2*)&SwW[(g + 8) * TPw + ni * 8 + 2 * tg] =
                make_float2(acc[ni][2], acc[ni][3]);
        }
        __syncwarp();

        // ---- O += P @ V ----
#pragma unroll
        for (int kk = 0; kk < 8; kk++) {
            unsigned pa[4];
            ldsm4(pa, swB + aOff + kk * 32);
            unsigned bf[8][2];
#pragma unroll
            for (int p = 0; p < 4; p++) {
                unsigned q4[4];
                ldsm4(q4, vsB + bOff + p * (16 * TPw * 4) + kk * 32);
                bf[2 * p][0] = q4[0]; bf[2 * p][1] = q4[1];
                bf[2 * p + 1][0] = q4[2]; bf[2 * p + 1][1] = q4[3];
            }
#pragma unroll
            for (int nd = 0; nd < 8; nd++)
                mma8(O[nd], pa, bf[nd]);
        }
    }

    // ---- epilogue ----
    const float inv0 = 1.f / l0, inv1 = 1.f / l1;
    const long row0 = (long)(b * 9216 + n0 + w * 16 + g) * 512 + h * 64;
    const long row1 = row0 + 8 * 512;
#pragma unroll
    for (int nd = 0; nd < 8; nd++) {
        const int c = nd * 8 + 2 * tg;
        *(float2*)(ctx + row0 + c) =
            make_float2(O[nd][0] * inv0, O[nd][1] * inv0);
        *(float2*)(ctx + row1 + c) =
            make_float2(O[nd][2] * inv1, O[nd][3] * inv1);
    }
}

// ---------------------------------------------------------------------------
// Launch pipeline: two chains forked onto a second stream.
// ---------------------------------------------------------------------------
extern "C" void kernel_launch(void* const* d_in, const int* in_sizes, int n_in,
                              void* d_out, int out_size)
{
    (void)in_sizes; (void)n_in; (void)out_size;
    const float* x      = (const float*)d_in[0];
    const float* w_q    = (const float*)d_in[1];
    const float* b_q    = (const float*)d_in[2];
    const float* w_kv   = (const float*)d_in[3];
    const float* b_kv   = (const float*)d_in[4];
    const float* w_proj = (const float*)d_in[5];
    const float* b_proj = (const float*)d_in[6];
    const float* w_sr   = (const float*)d_in[7];
    const float* b_sr   = (const float*)d_in[8];
    const float* ln_g   = (const float*)d_in[9];
    const float* ln_b   = (const float*)d_in[10];
    const float* lAq    = (const float*)d_in[11];
    const float* lBq    = (const float*)d_in[12];
    const float* lAv    = (const float*)d_in[13];
    const float* lBv    = (const float*)d_in[14];

    float *q, *xs, *t2p, *lv, *k, *v, *ctx, *t1p, *w2, *part;
    float *lAqp, *lAvp, *Bq2;
    cudaGetSymbolAddress((void**)&q,     g_q);
    cudaGetSymbolAddress((void**)&xs,    g_xs);
    cudaGetSymbolAddress((void**)&t2p,   g_t2p);
    cudaGetSymbolAddress((void**)&lv,    g_lv);
    cudaGetSymbolAddress((void**)&k,     g_k);
    cudaGetSymbolAddress((void**)&v,     g_v);
    cudaGetSymbolAddress((void**)&ctx,   g_ctx);
    cudaGetSymbolAddress((void**)&t1p,   g_t1p);
    cudaGetSymbolAddress((void**)&w2,    g_w2);
    cudaGetSymbolAddress((void**)&part,  g_part);
    cudaGetSymbolAddress((void**)&lAqp,  g_lAqp);
    cudaGetSymbolAddress((void**)&lAvp,  g_lAvp);
    cudaGetSymbolAddress((void**)&Bq2,   g_Bq2);

    static cudaStream_t s2 = nullptr;
    static cudaEvent_t evF = nullptr, evJ = nullptr;
    if (!s2) {
        cudaStreamCreateWithFlags(&s2, cudaStreamNonBlocking);
        cudaEventCreateWithFlags(&evF, cudaEventDisableTiming);
        cudaEventCreateWithFlags(&evJ, cudaEventDisableTiming);
    }

    dim3 blk(256);
    cudaFuncSetAttribute(attn_flash,
                         cudaFuncAttributeMaxDynamicSharedMemorySize, ATTN_SMEM);

    // prep (both chains depend on it)
    prep_lora<<<128, blk>>>(lAq, lBq, lAv, lAqp, lAvp, Bq2);

    // ---- fork ----
    cudaEventRecord(evF, 0);
    cudaStreamWaitEvent(s2, evF, 0);

    // ---- side chain (stream s2): xs / k / v ----
    reorder_w_kernel<<<16384, blk, 0, s2>>>(w_sr, w2);
    gemm_tf32<128, 1><<<dim3(4, 9, 8), blk, 0, s2>>>(
        1152, 512, 8192, x, 512, w2, 8192, nullptr, 1.f, nullptr, 512,
        1024, part, nullptr, 0, nullptr, 0, 0);
    reduce_ln<<<1152, 128, 0, s2>>>(part, b_sr, ln_g, ln_b, xs);
    gemm_tf32<128, 0><<<dim3(8, 9, 4), blk, 0, s2>>>(
        1152, 1024, 512, xs, 512, w_kv, 512, nullptr, 1.f, nullptr, 1024,
        128, part, nullptr, 0, nullptr, 0, 0);
    gemm_tf32<64, 0><<<dim3(1, 9, 1), blk, 0, s2>>>(
        1152, 64, 512, xs, 512, lAvp, 512, nullptr, 1.f, t2p, 64,
        512, nullptr, nullptr, 0, nullptr, 0, 0);
    gemm_tf32<128, 0><<<dim3(4, 9, 1), blk, 0, s2>>>(
        1152, 512, 32, t2p, 64, lBv, 32, nullptr, SCALING, lv, 512,
        32, nullptr, nullptr, 0, nullptr, 0, 0);
    reduce_build_kv<<<2304, blk, 0, s2>>>(part, b_kv, lv, k, v);
    cudaEventRecord(evJ, s2);

    // ---- main chain (default stream): q ----
    gemm_tf32<64, 0><<<dim3(1, 144, 1), blk>>>(
        18432, 64, 512, x, 512, lAqp, 512, nullptr, 1.f, t1p, 64,
        512, nullptr, nullptr, 0, nullptr, 0, 0);
    gemm_tf32<128, 0><<<dim3(4, 144, 1), blk>>>(
        18432, 512, 512, x, 512, w_q, 512, b_q, 1.f, q, 512,
        512, nullptr, t1p, 64, Bq2, 32, 32);

    // ---- join ----
    cudaStreamWaitEvent(0, evJ, 0);

    attn_flash<<<dim3(72, 16), blk, ATTN_SMEM>>>(q, k, v, ctx);

    gemm_tf32<128, 0><<<dim3(4, 144, 1), blk>>>(
        18432, 512, 512, ctx, 512, w_proj, 512, b_proj, 1.f, (float*)d_out,
        512, 512, nullptr, nullptr, 0, nullptr, 0, 0);
}

// round 10
// speedup vs baseline: 4.9811x; 1.0578x over previous
#include <cuda_runtime.h>
#include <math.h>

// B=2, N=9216, C=512, HEAD=8, d=64, SR=4, H=W=96 -> Nkv=576, R=32
#define SCALING 0.125f

// ---------------------------------------------------------------------------
// Scratch
// ---------------------------------------------------------------------------
__device__ float g_q    [9437184];  // (B,N,C) -- prescaled*0.125, tf32-rounded
__device__ float g_xs   [589824];   // (B*576, 512) post-LN
__device__ float g_t2p  [73728];    // 1152 x 64 lora-v intermediate
__device__ float g_lv   [589824];
__device__ float g_k    [589824];   // (B*H,576,64)  tf32-rounded
__device__ float g_v    [589824];   // (B*H,64,576)  TRANSPOSED, tf32-rounded
__device__ float g_ctx  [9437184];
__device__ float g_t1p  [1179648];  // 18432 x 64 lora-q intermediate
__device__ float g_w2   [4194304];  // 512 x 8192 reordered conv weight
__device__ float g_part [4718592];  // split-K partials
__device__ float g_lAqp [32768];    // 64 x 512 padded lora_A_q
__device__ float g_lAvp [32768];    // 64 x 512 padded lora_A_v
__device__ float g_Bq2  [16384];    // 512 x 32 prescaled lora_B_q
__device__ float g_bq8  [512];      // b_q * 0.125

// ---------------------------------------------------------------------------
// helpers
// ---------------------------------------------------------------------------
__device__ __forceinline__ unsigned f2tf(float x) {
    unsigned u;
    asm("cvt.rna.tf32.f32 %0, %1;" : "=r"(u) : "f"(x));
    return u;
}
__device__ __forceinline__ void mma8(float* c, const unsigned* a, const unsigned* b) {
    asm volatile(
        "mma.sync.aligned.m16n8k8.row.col.f32.tf32.tf32.f32 "
        "{%0,%1,%2,%3}, {%4,%5,%6,%7}, {%8,%9}, {%0,%1,%2,%3};"
        : "+f"(c[0]), "+f"(c[1]), "+f"(c[2]), "+f"(c[3])
        : "r"(a[0]), "r"(a[1]), "r"(a[2]), "r"(a[3]),
          "r"(b[0]), "r"(b[1]));
}
__device__ __forceinline__ void ldsm4(unsigned* r, unsigned addr) {
    asm volatile(
        "ldmatrix.sync.aligned.m8n8.x4.shared.b16 {%0,%1,%2,%3}, [%4];"
        : "=r"(r[0]), "=r"(r[1]), "=r"(r[2]), "=r"(r[3]) : "r"(addr));
}
__device__ __forceinline__ void cpa16(unsigned dst, const void* src) {
    asm volatile("cp.async.cg.shared.global [%0], [%1], 16;" :: "r"(dst), "l"(src));
}
__device__ __forceinline__ void cpa_commit() {
    asm volatile("cp.async.commit_group;" ::: "memory");
}
__device__ __forceinline__ void cpa_wait0() {
    asm volatile("cp.async.wait_group 0;" ::: "memory");
}

// ---------------------------------------------------------------------------
// tf32 tensor-core GEMM, 2-stage pipelined, ldmatrix fragment loads:
//   C = scale * (A @ B^T [+ A2 @ B2^T]) (+bias)   [optional tf32-round of out]
// ---------------------------------------------------------------------------
template <int BN, int CONV>
__global__ void __launch_bounds__(256, 2)
gemm_tf32(int M, int N, int K,
          const float* __restrict__ A, int lda,
          const float* __restrict__ B, int ldb,
          const float* __restrict__ bias,
          float scale,
          float* __restrict__ C, int ldc,
          int kchunk, float* __restrict__ part,
          const float* __restrict__ A2, int lda2,
          const float* __restrict__ B2, int ldb2, int K2,
          int round_out)
{
    constexpr int NI = BN / 16;
    __shared__ unsigned As[2][128][20];
    __shared__ unsigned Bs[2][BN][20];
    const int t    = threadIdx.x;
    const int lane = t & 31, w = t >> 5;
    const int g  = lane >> 2, tg = lane & 3;
    const int wm = w >> 1,  wn = w & 1;
    const long m0 = (long)blockIdx.y * 128;
    const int  n0 = blockIdx.x * BN;
    const int  kb = blockIdx.z * kchunk;

    const int ar  = t >> 2;
    const int kq4 = (t & 3) * 4;

    const int tS = lane >> 3;
    const unsigned asBase = (unsigned)__cvta_generic_to_shared(&As[0][0][0]);
    const unsigned bsBase = (unsigned)__cvta_generic_to_shared(&Bs[0][0][0]);
    const unsigned aOff = ((wm * 32 + (tS & 1) * 8 + (lane & 7)) * 20
                           + (tS >> 1) * 4) * 4;
    const unsigned bOff = ((wn * (BN / 2) + (tS >> 1) * 8 + (lane & 7)) * 20
                           + (tS & 1) * 4) * 4;

    float acc[2][NI][4];
#pragma unroll
    for (int mi = 0; mi < 2; mi++)
#pragma unroll
        for (int ni = 0; ni < NI; ni++)
#pragma unroll
            for (int c = 0; c < 4; c++) acc[mi][ni][c] = 0.f;

    const float* Ap0 = nullptr;
    const float* Ap1 = nullptr;
    long convRow0 = 0, convRow1 = 0;
    if (CONV) {
        int m = (int)m0 + ar;
        int b = m / 576, p = m % 576, py = p / 24, px = p % 24;
        convRow0 = (long)b * 9216 + (py * 4) * 96 + px * 4;
        m = (int)m0 + ar + 64;
        b = m / 576; p = m % 576; py = p / 24; px = p % 24;
        convRow1 = (long)b * 9216 + (py * 4) * 96 + px * 4;
    } else {
        Ap0 = A + (m0 + ar) * lda + kq4;
        Ap1 = A + (m0 + ar + 64) * lda + kq4;
    }
    const float* Bp0 = B + (long)(n0 + ar) * ldb + kq4;
    const float* Bp1 = (BN == 128) ? B + (long)(n0 + ar + 64) * ldb + kq4 : nullptr;

    const int n1 = kchunk >> 4;
    const int n2 = K2 >> 4;
    const int nIter = n1 + n2;

    float4 av0, av1, bv0, bv1;

    auto loadTile = [&](int idx) {
        if (idx < n1) {
            const int k0 = kb + (idx << 4);
            if (CONV) {
                const int s  = k0 >> 9;
                const int ii = s >> 2, jj = s & 3;
                const int ci = (k0 & 511) + kq4;
                av0 = *(const float4*)(A + (convRow0 + ii * 96 + jj) * 512 + ci);
                av1 = *(const float4*)(A + (convRow1 + ii * 96 + jj) * 512 + ci);
            } else {
                av0 = *(const float4*)(Ap0 + k0);
                av1 = *(const float4*)(Ap1 + k0);
            }
            bv0 = *(const float4*)(Bp0 + k0);
            if (BN == 128) bv1 = *(const float4*)(Bp1 + k0);
        } else {
            const int k0 = ((idx - n1) << 4) + kq4;
            av0 = *(const float4*)(A2 + (m0 + ar) * lda2 + k0);
            av1 = *(const float4*)(A2 + (m0 + ar + 64) * lda2 + k0);
            bv0 = *(const float4*)(B2 + (long)(n0 + ar) * ldb2 + k0);
            if (BN == 128)
                bv1 = *(const float4*)(B2 + (long)(n0 + ar + 64) * ldb2 + k0);
        }
    };
    auto storeTile = [&](int buf) {
        uint4 u;
        u.x = f2tf(av0.x); u.y = f2tf(av0.y); u.z = f2tf(av0.z); u.w = f2tf(av0.w);
        *(uint4*)&As[buf][ar][kq4] = u;
        u.x = f2tf(av1.x); u.y = f2tf(av1.y); u.z = f2tf(av1.z); u.w = f2tf(av1.w);
        *(uint4*)&As[buf][ar + 64][kq4] = u;
        u.x = f2tf(bv0.x); u.y = f2tf(bv0.y); u.z = f2tf(bv0.z); u.w = f2tf(bv0.w);
        *(uint4*)&Bs[buf][ar][kq4] = u;
        if (BN == 128) {
            u.x = f2tf(bv1.x); u.y = f2tf(bv1.y);
            u.z = f2tf(bv1.z); u.w = f2tf(bv1.w);
            *(uint4*)&Bs[buf][ar + 64][kq4] = u;
        }
    };

    loadTile(0);
    storeTile(0);
    __syncthreads();
    int buf = 0;
    for (int it = 0; it < nIter; it++) {
        const bool more = (it + 1 < nIter);
        if (more) loadTile(it + 1);
        const unsigned aB = asBase + buf * (128 * 80) + aOff;
        const unsigned bB = bsBase + buf * (BN * 80) + bOff;
#pragma unroll
        for (int kk = 0; kk < 16; kk += 8) {
            unsigned af[2][4], bf[NI][2];
#pragma unroll
            for (int mi = 0; mi < 2; mi++)
                ldsm4(af[mi], aB + mi * (16 * 80) + kk * 4);
#pragma unroll
            for (int p = 0; p < NI / 2; p++) {
                unsigned q4[4];
                ldsm4(q4, bB + p * (16 * 80) + kk * 4);
                bf[2 * p][0] = q4[0]; bf[2 * p][1] = q4[1];
                bf[2 * p + 1][0] = q4[2]; bf[2 * p + 1][1] = q4[3];
            }
#pragma unroll
            for (int mi = 0; mi < 2; mi++)
#pragma unroll
                for (int ni = 0; ni < NI; ni++)
                    mma8(acc[mi][ni], af[mi], bf[ni]);
        }
        if (more) {
            storeTile(buf ^ 1);
            __syncthreads();
            buf ^= 1;
        }
    }

    if (gridDim.z == 1) {
#pragma unroll
        for (int mi = 0; mi < 2; mi++) {
            const long r0 = m0 + wm * 32 + mi * 16 + g;
            const long r1 = r0 + 8;
#pragma unroll
            for (int ni = 0; ni < NI; ni++) {
                const int c = n0 + wn * (BN / 2) + ni * 8 + 2 * tg;
                float v00 = scale * acc[mi][ni][0];
                float v01 = scale * acc[mi][ni][1];
                float v10 = scale * acc[mi][ni][2];
                float v11 = scale * acc[mi][ni][3];
                if (bias) {
                    float b0 = bias[c], b1 = bias[c + 1];
                    v00 += b0; v01 += b1; v10 += b0; v11 += b1;
                }
                if (round_out) {
                    v00 = __uint_as_float(f2tf(v00));
                    v01 = __uint_as_float(f2tf(v01));
                    v10 = __uint_as_float(f2tf(v10));
                    v11 = __uint_as_float(f2tf(v11));
                }
                *(float2*)(C + r0 * ldc + c) = make_float2(v00, v01);
                *(float2*)(C + r1 * ldc + c) = make_float2(v10, v11);
            }
        }
    } else {
        float* P = part + (long)blockIdx.z * M * ldc;
#pragma unroll
        for (int mi = 0; mi < 2; mi++) {
            const long r0 = m0 + wm * 32 + mi * 16 + g;
            const long r1 = r0 + 8;
#pragma unroll
            for (int ni = 0; ni < NI; ni++) {
                const int c = n0 + wn * (BN / 2) + ni * 8 + 2 * tg;
                *(float2*)(P + r0 * ldc + c) =
                    make_float2(acc[mi][ni][0], acc[mi][ni][1]);
                *(float2*)(P + r1 * ldc + c) =
                    make_float2(acc[mi][ni][2], acc[mi][ni][3]);
            }
        }
    }
}

// ---------------------------------------------------------------------------
// Fused conv split-K reduce + bias + LayerNorm.
// ---------------------------------------------------------------------------
__global__ void reduce_ln(const float* __restrict__ part,
                          const float* __restrict__ bias,
                          const float* __restrict__ gam,
                          const float* __restrict__ bet,
                          float* __restrict__ out)
{
    const int row = blockIdx.x;
    const int t   = threadIdx.x;
    float v[4];
#pragma unroll
    for (int j = 0; j < 4; j++) {
        const int col = t + j * 128;
        float s = bias[col];
        const long off = (long)row * 512 + col;
#pragma unroll
        for (int z = 0; z < 8; z++) s += part[z * 589824 + off];
        v[j] = s;
    }
    float s  = v[0] + v[1] + v[2] + v[3];
    float s2 = v[0]*v[0] + v[1]*v[1] + v[2]*v[2] + v[3]*v[3];
#pragma unroll
    for (int o = 16; o > 0; o >>= 1) {
        s  += __shfl_xor_sync(0xffffffffu, s,  o);
        s2 += __shfl_xor_sync(0xffffffffu, s2, o);
    }
    __shared__ float ss[4], ss2[4];
    if ((t & 31) == 0) { ss[t >> 5] = s; ss2[t >> 5] = s2; }
    __syncthreads();
    s  = ss[0]  + ss[1]  + ss[2]  + ss[3];
    s2 = ss2[0] + ss2[1] + ss2[2] + ss2[3];
    const float mean = s * (1.f / 512.f);
    const float var  = s2 * (1.f / 512.f) - mean * mean;
    const float inv  = rsqrtf(var + 1e-5f);
    float* o = out + (long)row * 512;
#pragma unroll
    for (int j = 0; j < 4; j++) {
        const int col = t + j * 128;
        o[col] = (v[j] - mean) * inv * gam[col] + bet[col];
    }
}

// ---------------------------------------------------------------------------
// Fused kv split-K reduce + bias + head split + LoRA-v fixup.
// k: [bh][m][dd] tf32-rounded.  v: [bh][dd][m] TRANSPOSED, tf32-rounded.
// ---------------------------------------------------------------------------
__global__ void reduce_build_kv(const float* __restrict__ part,
                                const float* __restrict__ bias,
                                const float* __restrict__ lv,
                                float* __restrict__ k, float* __restrict__ vt)
{
    const int idx = blockIdx.x * 256 + threadIdx.x;
    const int dd = idx & 63;
    const int m  = (idx >> 6) % 576;
    const int bh = idx / 36864;
    const int h  = bh & 7, b = bh >> 3;
    const int ck = h * 64 + dd;
    const long mrow = (long)(b * 576 + m) * 1024;
    float sk = bias[ck], sv = bias[512 + ck];
#pragma unroll
    for (int z = 0; z < 4; z++) {
        sk += part[z * 1179648 + mrow + ck];
        sv += part[z * 1179648 + mrow + 512 + ck];
    }
    k[idx] = __uint_as_float(f2tf(sk));
    float vv = sv + lv[(long)b * 294912 + h * 36864 + m * 64 + dd];
    vt[(long)bh * 36864 + dd * 576 + m] = __uint_as_float(f2tf(vv));
}

// w2[co][(i*4+j)*512 + ci] = w_sr[co][ci][i][j]
__global__ void reorder_w_kernel(const float* __restrict__ w,
                                 float* __restrict__ w2)
{
    const int tid = blockIdx.x * 256 + threadIdx.x;
    const int ci = tid & 511;
    const int s  = (tid >> 9) & 15;
    const int co = tid >> 13;
    w2[tid] = w[(long)co * 8192 + ci * 16 + s];
}

// pad lora_A_q / lora_A_v to 64x512; prescale lora_B_q, b_q
__global__ void prep_lora(const float* __restrict__ lAq,
                          const float* __restrict__ lBq,
                          const float* __restrict__ lAv,
                          const float* __restrict__ bq,
                          float* __restrict__ lAqp,
                          float* __restrict__ lAvp,
                          float* __restrict__ Bq2,
                          float* __restrict__ bq8)
{
    const int i = blockIdx.x * 256 + threadIdx.x;
    if (i < 64 * 512) {
        lAqp[i] = (i < 32 * 512) ? lAq[i] : 0.f;
        lAvp[i] = (i < 32 * 512) ? lAv[i] : 0.f;
    }
    if (i < 512 * 32) Bq2[i] = lBq[i] * SCALING;
    if (i < 512) bq8[i] = bq[i] * 0.125f;
}

// ---------------------------------------------------------------------------
// FA2-style tf32 attention, cp.async + double-buffered K/V.
// Block = 128 q-rows x one (b,h); 8 warps x (16 q x full 64-key chunk).
// Operands arrive pre-tf32 (q also pre-scaled); V pre-transposed in gmem.
// Smem: Sw 128x68 (Q stage / P scratch) + 2 x (Ks 64x68 + Vs 64x68) = 102KB.
// ---------------------------------------------------------------------------
#define TPw 68
#define ATTN_SMEM (TPw * 384 * 4)

__global__ void __launch_bounds__(256, 2)
attn_flash(const float* __restrict__ qb,   // (B,N,512) prescaled tf32
           const float* __restrict__ kb,   // (B*H,576,64) tf32
           const float* __restrict__ vtb,  // (B*H,64,576) tf32 transposed
           float* __restrict__ ctx)
{
    extern __shared__ float sm[];
    float*    Sw = sm;                           // 128 x TPw
    unsigned* KV = (unsigned*)(sm + 128 * TPw);  // 2 x (64+64) x TPw

    const int t    = threadIdx.x;
    const int lane = t & 31, w = t >> 5;
    const int g  = lane >> 2, tg = lane & 3;
    const int bh = blockIdx.y, b = bh >> 3, h = bh & 7;
    const int n0 = blockIdx.x * 128;

    const int tS = lane >> 3;
    const unsigned swB = (unsigned)__cvta_generic_to_shared(Sw);
    const unsigned kvB = (unsigned)__cvta_generic_to_shared(KV);
    const unsigned aOff = ((w * 16 + (tS & 1) * 8 + (lane & 7)) * TPw
                           + (tS >> 1) * 4) * 4;
    const unsigned bOff = (((tS >> 1) * 8 + (lane & 7)) * TPw
                           + (tS & 1) * 4) * 4;
    constexpr unsigned BUFB = 128 * TPw * 4;   // one K+V buffer in bytes
    constexpr unsigned VOFF = 64 * TPw * 4;    // V offset inside a buffer

    // ---- cp.async issue helpers (256 threads) ----
    // Q: 128 rows x 16 chunks of 16B
    auto loadQ = [&]() {
#pragma unroll
        for (int i = 0; i < 8; i++) {
            int c = i * 256 + t;
            int row = c >> 4, off = (c & 15) * 4;   // off in floats
            cpa16(swB + (row * TPw + off) * 4,
                  qb + (long)(b * 9216 + n0 + row) * 512 + h * 64 + off);
        }
    };
    // K+V chunk: each 64 rows x 16 chunks of 16B
    auto loadKV = [&](int ch, int buf) {
#pragma unroll
        for (int i = 0; i < 4; i++) {
            int c = i * 256 + t;
            int row = c >> 4, off = (c & 15) * 4;
            cpa16(kvB + buf * BUFB + (row * TPw + off) * 4,
                  kb + (long)(bh * 576 + ch * 64 + row) * 64 + off);
            cpa16(kvB + buf * BUFB + VOFF + (row * TPw + off) * 4,
                  vtb + (long)bh * 36864 + row * 576 + ch * 64 + off);
        }
    };

    // prologue: Q + chunk0
    loadQ();
    loadKV(0, 0);
    cpa_commit();
    cpa_wait0();
    __syncthreads();

    unsigned Qf[8][4];
#pragma unroll
    for (int kk = 0; kk < 8; kk++)
        ldsm4(Qf[kk], swB + aOff + kk * 32);

    float O[8][4];
#pragma unroll
    for (int nd = 0; nd < 8; nd++)
#pragma unroll
        for (int c = 0; c < 4; c++) O[nd][c] = 0.f;
    float m0 = -1e30f, l0 = 0.f, m1 = -1e30f, l1 = 0.f;

    int buf = 0;
    for (int ch = 0; ch < 9; ch++) {
        const bool more = (ch + 1 < 9);
        if (more) { loadKV(ch + 1, buf ^ 1); cpa_commit(); }

        const unsigned ksB = kvB + buf * BUFB + bOff;
        const unsigned vsB = kvB + buf * BUFB + VOFF + bOff;

        // ---- S = Q K^T (Q prescaled) ----
        float acc[8][4];
#pragma unroll
        for (int ni = 0; ni < 8; ni++)
#pragma unroll
            for (int c = 0; c < 4; c++) acc[ni][c] = 0.f;
#pragma unroll
        for (int kk = 0; kk < 8; kk++) {
            unsigned bf[8][2];
#pragma unroll
            for (int p = 0; p < 4; p++) {
                unsigned q4[4];
                ldsm4(q4, ksB + p * (16 * TPw * 4) + kk * 32);
                bf[2 * p][0] = q4[0]; bf[2 * p][1] = q4[1];
                bf[2 * p + 1][0] = q4[2]; bf[2 * p + 1][1] = q4[3];
            }
#pragma unroll
            for (int ni = 0; ni < 8; ni++)
                mma8(acc[ni], Qf[kk], bf[ni]);
        }

        // ---- online softmax in registers ----
        float cm0 = -1e30f, cm1 = -1e30f;
#pragma unroll
        for (int ni = 0; ni < 8; ni++) {
            cm0 = fmaxf(cm0, fmaxf(acc[ni][0], acc[ni][1]));
            cm1 = fmaxf(cm1, fmaxf(acc[ni][2], acc[ni][3]));
        }
        cm0 = fmaxf(cm0, __shfl_xor_sync(0xffffffffu, cm0, 1));
        cm0 = fmaxf(cm0, __shfl_xor_sync(0xffffffffu, cm0, 2));
        cm1 = fmaxf(cm1, __shfl_xor_sync(0xffffffffu, cm1, 1));
        cm1 = fmaxf(cm1, __shfl_xor_sync(0xffffffffu, cm1, 2));
        const float nm0 = fmaxf(m0, cm0), nm1 = fmaxf(m1, cm1);
        const float al0 = __expf(m0 - nm0), al1 = __expf(m1 - nm1);
        float sum0 = 0.f, sum1 = 0.f;
#pragma unroll
        for (int ni = 0; ni < 8; ni++) {
            float e0 = __uint_as_float(f2tf(__expf(acc[ni][0] - nm0)));
            float e1 = __uint_as_float(f2tf(__expf(acc[ni][1] - nm0)));
            float e2 = __uint_as_float(f2tf(__expf(acc[ni][2] - nm1)));
            float e3 = __uint_as_float(f2tf(__expf(acc[ni][3] - nm1)));
            acc[ni][0] = e0; acc[ni][1] = e1; acc[ni][2] = e2; acc[ni][3] = e3;
            sum0 += e0 + e1; sum1 += e2 + e3;
        }
        sum0 += __shfl_xor_sync(0xffffffffu, sum0, 1);
        sum0 += __shfl_xor_sync(0xffffffffu, sum0, 2);
        sum1 += __shfl_xor_sync(0xffffffffu, sum1, 1);
        sum1 += __shfl_xor_sync(0xffffffffu, sum1, 2);
        l0 = l0 * al0 + sum0; l1 = l1 * al1 + sum1;
        m0 = nm0; m1 = nm1;
#pragma unroll
        for (int nd = 0; nd < 8; nd++) {
            O[nd][0] *= al0; O[nd][1] *= al0;
            O[nd][2] *= al1; O[nd][3] *= al1;
        }

        // ---- P: C-frag -> per-warp smem scratch -> A-frag ----
        float* SwW = Sw + w * 16 * TPw;
#pragma unroll
        for (int ni = 0; ni < 8; ni++) {
            *(float2*)&SwW[g * TPw + ni * 8 + 2 * tg] =
                make_float2(acc[ni][0], acc[ni][1]);
            *(float2*)&SwW[(g + 8) * TPw + ni * 8 + 2 * tg] =
                make_float2(acc[ni][2], acc[ni][3]);
        }
        __syncwarp();

        // ---- O += P @ V ----
#pragma unroll
        for (int kk = 0; kk < 8; kk++) {
            unsigned pa[4];
            ldsm4(pa, swB + aOff + kk * 32);
            unsigned bf[8][2];
#pragma unroll
            for (int p = 0; p < 4; p++) {
                unsigned q4[4];
                ldsm4(q4, vsB + p * (16 * TPw * 4) + kk * 32);
                bf[2 * p][0] = q4[0]; bf[2 * p][1] = q4[1];
                bf[2 * p + 1][0] = q4[2]; bf[2 * p + 1][1] = q4[3];
            }
#pragma unroll
            for (int nd = 0; nd < 8; nd++)
                mma8(O[nd], pa, bf[nd]);
        }

        if (more) {
            cpa_wait0();       // next chunk landed
            __syncthreads();   // all warps done with current buf
            buf ^= 1;
        }
    }

    // ---- epilogue ----
    const float inv0 = 1.f / l0, inv1 = 1.f / l1;
    const long row0 = (long)(b * 9216 + n0 + w * 16 + g) * 512 + h * 64;
    const long row1 = row0 + 8 * 512;
#pragma unroll
    for (int nd = 0; nd < 8; nd++) {
        const int c = nd * 8 + 2 * tg;
        *(float2*)(ctx + row0 + c) =
            make_float2(O[nd][0] * inv0, O[nd][1] * inv0);
        *(float2*)(ctx + row1 + c) =
            make_float2(O[nd][2] * inv1, O[nd][3] * inv1);
    }
}

// ---------------------------------------------------------------------------
// Launch pipeline: two chains forked onto a second stream.
// ---------------------------------------------------------------------------
extern "C" void kernel_launch(void* const* d_in, const int* in_sizes, int n_in,
                              void* d_out, int out_size)
{
    (void)in_sizes; (void)n_in; (void)out_size;
    const float* x      = (const float*)d_in[0];
    const float* w_q    = (const float*)d_in[1];
    const float* b_q    = (const float*)d_in[2];
    const float* w_kv   = (const float*)d_in[3];
    const float* b_kv   = (const float*)d_in[4];
    const float* w_proj = (const float*)d_in[5];
    const float* b_proj = (const float*)d_in[6];
    const float* w_sr   = (const float*)d_in[7];
    const float* b_sr   = (const float*)d_in[8];
    const float* ln_g   = (const float*)d_in[9];
    const float* ln_b   = (const float*)d_in[10];
    const float* lAq    = (const float*)d_in[11];
    const float* lBq    = (const float*)d_in[12];
    const float* lAv    = (const float*)d_in[13];
    const float* lBv    = (const float*)d_in[14];

    float *q, *xs, *t2p, *lv, *k, *v, *ctx, *t1p, *w2, *part;
    float *lAqp, *lAvp, *Bq2, *bq8;
    cudaGetSymbolAddress((void**)&q,     g_q);
    cudaGetSymbolAddress((void**)&xs,    g_xs);
    cudaGetSymbolAddress((void**)&t2p,   g_t2p);
    cudaGetSymbolAddress((void**)&lv,    g_lv);
    cudaGetSymbolAddress((void**)&k,     g_k);
    cudaGetSymbolAddress((void**)&v,     g_v);
    cudaGetSymbolAddress((void**)&ctx,   g_ctx);
    cudaGetSymbolAddress((void**)&t1p,   g_t1p);
    cudaGetSymbolAddress((void**)&w2,    g_w2);
    cudaGetSymbolAddress((void**)&part,  g_part);
    cudaGetSymbolAddress((void**)&lAqp,  g_lAqp);
    cudaGetSymbolAddress((void**)&lAvp,  g_lAvp);
    cudaGetSymbolAddress((void**)&Bq2,   g_Bq2);
    cudaGetSymbolAddress((void**)&bq8,   g_bq8);

    static cudaStream_t s2 = nullptr;
    static cudaEvent_t evF = nullptr, evJ = nullptr;
    if (!s2) {
        cudaStreamCreateWithFlags(&s2, cudaStreamNonBlocking);
        cudaEventCreateWithFlags(&evF, cudaEventDisableTiming);
        cudaEventCreateWithFlags(&evJ, cudaEventDisableTiming);
    }

    dim3 blk(256);
    cudaFuncSetAttribute(attn_flash,
                         cudaFuncAttributeMaxDynamicSharedMemorySize, ATTN_SMEM);

    // prep (both chains depend on it)
    prep_lora<<<128, blk>>>(lAq, lBq, lAv, b_q, lAqp, lAvp, Bq2, bq8);

    // ---- fork ----
    cudaEventRecord(evF, 0);
    cudaStreamWaitEvent(s2, evF, 0);

    // ---- side chain (stream s2): xs / k / v ----
    reorder_w_kernel<<<16384, blk, 0, s2>>>(w_sr, w2);
    gemm_tf32<128, 1><<<dim3(4, 9, 8), blk, 0, s2>>>(
        1152, 512, 8192, x, 512, w2, 8192, nullptr, 1.f, nullptr, 512,
        1024, part, nullptr, 0, nullptr, 0, 0, 0);
    reduce_ln<<<1152, 128, 0, s2>>>(part, b_sr, ln_g, ln_b, xs);
    gemm_tf32<128, 0><<<dim3(8, 9, 4), blk, 0, s2>>>(
        1152, 1024, 512, xs, 512, w_kv, 512, nullptr, 1.f, nullptr, 1024,
        128, part, nullptr, 0, nullptr, 0, 0, 0);
    gemm_tf32<64, 0><<<dim3(1, 9, 1), blk, 0, s2>>>(
        1152, 64, 512, xs, 512, lAvp, 512, nullptr, 1.f, t2p, 64,
        512, nullptr, nullptr, 0, nullptr, 0, 0, 0);
    gemm_tf32<128, 0><<<dim3(4, 9, 1), blk, 0, s2>>>(
        1152, 512, 32, t2p, 64, lBv, 32, nullptr, SCALING, lv, 512,
        32, nullptr, nullptr, 0, nullptr, 0, 0, 0);
    reduce_build_kv<<<2304, blk, 0, s2>>>(part, b_kv, lv, k, v);
    cudaEventRecord(evJ, s2);

    // ---- main chain (default stream): q (prescaled 0.125, tf32-rounded) ----
    gemm_tf32<64, 0><<<dim3(1, 144, 1), blk>>>(
        18432, 64, 512, x, 512, lAqp, 512, nullptr, 1.f, t1p, 64,
        512, nullptr, nullptr, 0, nullptr, 0, 0, 0);
    gemm_tf32<128, 0><<<dim3(4, 144, 1), blk>>>(
        18432, 512, 512, x, 512, w_q, 512, bq8, 0.125f, q, 512,
        512, nullptr, t1p, 64, Bq2, 32, 32, 1);

    // ---- join ----
    cudaStreamWaitEvent(0, evJ, 0);

    attn_flash<<<dim3(72, 16), blk, ATTN_SMEM>>>(q, k, v, ctx);

    gemm_tf32<128, 0><<<dim3(4, 144, 1), blk>>>(
        18432, 512, 512, ctx, 512, w_proj, 512, b_proj, 1.f, (float*)d_out,
        512, 512, nullptr, nullptr, 0, nullptr, 0, 0, 0);
}

// round 11
// speedup vs baseline: 5.2131x; 1.0466x over previous
#include <cuda_runtime.h>
#include <math.h>

// B=2, N=9216, C=512, HEAD=8, d=64, SR=4, H=W=96 -> Nkv=576, R=32
#define SCALING 0.125f

// ---------------------------------------------------------------------------
// Scratch (all GEMM operands stored tf32-rounded)
// ---------------------------------------------------------------------------
__device__ float g_q    [9437184];  // (B,N,C) prescaled*0.125, tf32
__device__ float g_xtf  [9437184];  // x tf32-rounded
__device__ float g_xs   [589824];   // (B*576,512) post-LN, tf32
__device__ float g_t2p  [73728];    // 1152x64 lora-v intermediate, tf32
__device__ float g_lv   [589824];
__device__ float g_k    [589824];   // (B*H,576,64) tf32
__device__ float g_v    [589824];   // (B*H,64,576) TRANSPOSED, tf32
__device__ float g_ctx  [9437184];  // tf32
__device__ float g_t1p  [1179648];  // 18432x64 lora-q intermediate, tf32
__device__ float g_w2   [4194304];  // 512x8192 reordered conv weight, tf32
__device__ float g_part [4718592];  // split-K partials
__device__ float g_lAqp [32768];    // 64x512 padded lora_A_q, tf32
__device__ float g_lAvp [32768];    // 64x512 padded lora_A_v, tf32
__device__ float g_Bq2  [16384];    // 512x32 prescaled lora_B_q, tf32
__device__ float g_bq8  [512];      // b_q * 0.125
__device__ float g_wq2  [262144];   // w_q tf32
__device__ float g_wkv2 [524288];   // w_kv tf32
__device__ float g_wp2  [262144];   // w_proj tf32
__device__ float g_lBv2 [16384];    // lora_B_v tf32

// ---------------------------------------------------------------------------
// helpers
// ---------------------------------------------------------------------------
__device__ __forceinline__ unsigned f2tf(float x) {
    unsigned u;
    asm("cvt.rna.tf32.f32 %0, %1;" : "=r"(u) : "f"(x));
    return u;
}
__device__ __forceinline__ void mma8(float* c, const unsigned* a, const unsigned* b) {
    asm volatile(
        "mma.sync.aligned.m16n8k8.row.col.f32.tf32.tf32.f32 "
        "{%0,%1,%2,%3}, {%4,%5,%6,%7}, {%8,%9}, {%0,%1,%2,%3};"
        : "+f"(c[0]), "+f"(c[1]), "+f"(c[2]), "+f"(c[3])
        : "r"(a[0]), "r"(a[1]), "r"(a[2]), "r"(a[3]),
          "r"(b[0]), "r"(b[1]));
}
__device__ __forceinline__ void ldsm4(unsigned* r, unsigned addr) {
    asm volatile(
        "ldmatrix.sync.aligned.m8n8.x4.shared.b16 {%0,%1,%2,%3}, [%4];"
        : "=r"(r[0]), "=r"(r[1]), "=r"(r[2]), "=r"(r[3]) : "r"(addr));
}
__device__ __forceinline__ void cpa16(unsigned dst, const void* src) {
    asm volatile("cp.async.cg.shared.global [%0], [%1], 16;" :: "r"(dst), "l"(src));
}
__device__ __forceinline__ void cpa_commit() {
    asm volatile("cp.async.commit_group;" ::: "memory");
}
__device__ __forceinline__ void cpa_wait0() {
    asm volatile("cp.async.wait_group 0;" ::: "memory");
}
__device__ __forceinline__ void cpa_wait1() {
    asm volatile("cp.async.wait_group 1;" ::: "memory");
}

// elementwise tf32 round (n multiple of 1024)
__global__ void cvt_tf32(const float* __restrict__ in, float* __restrict__ out)
{
    const int i = (blockIdx.x * 256 + threadIdx.x) * 4;
    float4 v = *(const float4*)(in + i);
    uint4 u;
    u.x = f2tf(v.x); u.y = f2tf(v.y); u.z = f2tf(v.z); u.w = f2tf(v.w);
    *(uint4*)(out + i) = u;
}

// ---------------------------------------------------------------------------
// tf32 GEMM, 3-stage cp.async pipeline, ldmatrix frags. All operands pre-tf32.
//   C = scale * (A @ B^T [+ A2 @ B2^T]) (+bias)  [round_out: tf32-round C]
// BM=128, BN in {64,128}, BK=16; 256 threads; warps 4(M)x2(N).
// CONV=1: A gathered from x_tf with SR-conv im2col mapping.
// dyn smem: 3*(128+BN)*20*4 bytes.
// ---------------------------------------------------------------------------
template <int BN, int CONV>
__global__ void __launch_bounds__(256, 2)
gemm_tf32(int M, int N, int K,
          const float* __restrict__ A, int lda,
          const float* __restrict__ B, int ldb,
          const float* __restrict__ bias,
          float scale,
          float* __restrict__ C, int ldc,
          int kchunk, float* __restrict__ part,
          const float* __restrict__ A2, int lda2,
          const float* __restrict__ B2, int ldb2, int K2,
          int round_out)
{
    constexpr int NI = BN / 16;
    extern __shared__ unsigned gsm[];
    unsigned* AsU = gsm;                  // 3 x 128 x 20
    unsigned* BsU = gsm + 3 * 128 * 20;   // 3 x BN x 20

    const int t    = threadIdx.x;
    const int lane = t & 31, w = t >> 5;
    const int g  = lane >> 2, tg = lane & 3;
    const int wm = w >> 1,  wn = w & 1;
    const long m0 = (long)blockIdx.y * 128;
    const int  n0 = blockIdx.x * BN;
    const int  kb = blockIdx.z * kchunk;

    // loader mapping: A chunks c = t, t+256 (rows t>>2, 64+(t>>2)); B same rows
    const int arow0 = t >> 2;
    const int arow1 = 64 + (t >> 2);
    const int ak    = (t & 3) * 4;        // k offset in floats

    const int tS = lane >> 3;
    const unsigned asB = (unsigned)__cvta_generic_to_shared(AsU);
    const unsigned bsB = (unsigned)__cvta_generic_to_shared(BsU);
    const unsigned aOff = ((wm * 32 + (tS & 1) * 8 + (lane & 7)) * 20
                           + (tS >> 1) * 4) * 4;
    const unsigned bOff = ((wn * (BN / 2) + (tS >> 1) * 8 + (lane & 7)) * 20
                           + (tS & 1) * 4) * 4;

    float acc[2][NI][4];
#pragma unroll
    for (int mi = 0; mi < 2; mi++)
#pragma unroll
        for (int ni = 0; ni < NI; ni++)
#pragma unroll
            for (int c = 0; c < 4; c++) acc[mi][ni][c] = 0.f;

    long cr0 = 0, cr1 = 0;
    if (CONV) {
        int m = (int)m0 + arow0;
        int b = m / 576, p = m % 576, py = p / 24, px = p % 24;
        cr0 = (long)b * 9216 + (py * 4) * 96 + px * 4;
        m = (int)m0 + arow1;
        b = m / 576; p = m % 576; py = p / 24; px = p % 24;
        cr1 = (long)b * 9216 + (py * 4) * 96 + px * 4;
    }

    const int n1 = kchunk >> 4;
    const int nIter = n1 + (K2 >> 4);

    auto issueTile = [&](int idx, int s) {
        const unsigned aS = asB + s * (128 * 80);
        const unsigned bS = bsB + s * (BN * 80);
        if (idx < n1) {
            const int kk = kb + (idx << 4) + ak;
            const float *sa0, *sa1;
            if (CONV) {
                const int tap = kk >> 9, ci = kk & 511;
                const long off = (long)((tap >> 2) * 96 + (tap & 3)) * 512 + ci;
                sa0 = A + cr0 * 512 + off;
                sa1 = A + cr1 * 512 + off;
            } else {
                sa0 = A + (m0 + arow0) * lda + kk;
                sa1 = A + (m0 + arow1) * lda + kk;
            }
            cpa16(aS + (arow0 * 20 + ak) * 4, sa0);
            cpa16(aS + (arow1 * 20 + ak) * 4, sa1);
            cpa16(bS + (arow0 * 20 + ak) * 4, B + (long)(n0 + arow0) * ldb + kk);
            if (BN == 128)
                cpa16(bS + (arow1 * 20 + ak) * 4,
                      B + (long)(n0 + arow1) * ldb + kk);
        } else {
            const int kk = ((idx - n1) << 4) + ak;
            cpa16(aS + (arow0 * 20 + ak) * 4, A2 + (m0 + arow0) * lda2 + kk);
            cpa16(aS + (arow1 * 20 + ak) * 4, A2 + (m0 + arow1) * lda2 + kk);
            cpa16(bS + (arow0 * 20 + ak) * 4,
                  B2 + (long)(n0 + arow0) * ldb2 + kk);
            if (BN == 128)
                cpa16(bS + (arow1 * 20 + ak) * 4,
                      B2 + (long)(n0 + arow1) * ldb2 + kk);
        }
        cpa_commit();
    };

    issueTile(0, 0);
    if (nIter > 1) issueTile(1, 1);

    for (int it = 0; it < nIter; it++) {
        if (it + 2 <= nIter) cpa_wait1(); else cpa_wait0();
        __syncthreads();
        if (it + 2 < nIter) issueTile(it + 2, (it + 2) % 3);

        const int s = it % 3;
        const unsigned aB = asB + s * (128 * 80) + aOff;
        const unsigned bB = bsB + s * (BN * 80) + bOff;
#pragma unroll
        for (int kk = 0; kk < 16; kk += 8) {
            unsigned af[2][4], bf[NI][2];
#pragma unroll
            for (int mi = 0; mi < 2; mi++)
                ldsm4(af[mi], aB + mi * (16 * 80) + kk * 4);
#pragma unroll
            for (int p = 0; p < NI / 2; p++) {
                unsigned q4[4];
                ldsm4(q4, bB + p * (16 * 80) + kk * 4);
                bf[2 * p][0] = q4[0]; bf[2 * p][1] = q4[1];
                bf[2 * p + 1][0] = q4[2]; bf[2 * p + 1][1] = q4[3];
            }
#pragma unroll
            for (int mi = 0; mi < 2; mi++)
#pragma unroll
                for (int ni = 0; ni < NI; ni++)
                    mma8(acc[mi][ni], af[mi], bf[ni]);
        }
    }

    if (gridDim.z == 1) {
#pragma unroll
        for (int mi = 0; mi < 2; mi++) {
            const long r0 = m0 + wm * 32 + mi * 16 + g;
            const long r1 = r0 + 8;
#pragma unroll
            for (int ni = 0; ni < NI; ni++) {
                const int c = n0 + wn * (BN / 2) + ni * 8 + 2 * tg;
                float v00 = scale * acc[mi][ni][0];
                float v01 = scale * acc[mi][ni][1];
                float v10 = scale * acc[mi][ni][2];
                float v11 = scale * acc[mi][ni][3];
                if (bias) {
                    float b0 = bias[c], b1 = bias[c + 1];
                    v00 += b0; v01 += b1; v10 += b0; v11 += b1;
                }
                if (round_out) {
                    v00 = __uint_as_float(f2tf(v00));
                    v01 = __uint_as_float(f2tf(v01));
                    v10 = __uint_as_float(f2tf(v10));
                    v11 = __uint_as_float(f2tf(v11));
                }
                *(float2*)(C + r0 * ldc + c) = make_float2(v00, v01);
                *(float2*)(C + r1 * ldc + c) = make_float2(v10, v11);
            }
        }
    } else {
        float* P = part + (long)blockIdx.z * M * ldc;
#pragma unroll
        for (int mi = 0; mi < 2; mi++) {
            const long r0 = m0 + wm * 32 + mi * 16 + g;
            const long r1 = r0 + 8;
#pragma unroll
            for (int ni = 0; ni < NI; ni++) {
                const int c = n0 + wn * (BN / 2) + ni * 8 + 2 * tg;
                *(float2*)(P + r0 * ldc + c) =
                    make_float2(acc[mi][ni][0], acc[mi][ni][1]);
                *(float2*)(P + r1 * ldc + c) =
                    make_float2(acc[mi][ni][2], acc[mi][ni][3]);
            }
        }
    }
}

// ---------------------------------------------------------------------------
// Fused conv split-K reduce + bias + LayerNorm -> xs (tf32-rounded).
// ---------------------------------------------------------------------------
__global__ void reduce_ln(const float* __restrict__ part,
                          const float* __restrict__ bias,
                          const float* __restrict__ gam,
                          const float* __restrict__ bet,
                          float* __restrict__ out)
{
    const int row = blockIdx.x;
    const int t   = threadIdx.x;
    float v[4];
#pragma unroll
    for (int j = 0; j < 4; j++) {
        const int col = t + j * 128;
        float s = bias[col];
        const long off = (long)row * 512 + col;
#pragma unroll
        for (int z = 0; z < 8; z++) s += part[z * 589824 + off];
        v[j] = s;
    }
    float s  = v[0] + v[1] + v[2] + v[3];
    float s2 = v[0]*v[0] + v[1]*v[1] + v[2]*v[2] + v[3]*v[3];
#pragma unroll
    for (int o = 16; o > 0; o >>= 1) {
        s  += __shfl_xor_sync(0xffffffffu, s,  o);
        s2 += __shfl_xor_sync(0xffffffffu, s2, o);
    }
    __shared__ float ss[4], ss2[4];
    if ((t & 31) == 0) { ss[t >> 5] = s; ss2[t >> 5] = s2; }
    __syncthreads();
    s  = ss[0]  + ss[1]  + ss[2]  + ss[3];
    s2 = ss2[0] + ss2[1] + ss2[2] + ss2[3];
    const float mean = s * (1.f / 512.f);
    const float var  = s2 * (1.f / 512.f) - mean * mean;
    const float inv  = rsqrtf(var + 1e-5f);
    float* o = out + (long)row * 512;
#pragma unroll
    for (int j = 0; j < 4; j++) {
        const int col = t + j * 128;
        o[col] = __uint_as_float(f2tf((v[j] - mean) * inv * gam[col] + bet[col]));
    }
}

// ---------------------------------------------------------------------------
// Fused kv split-K reduce + bias + head split + LoRA-v fixup.
// k: [bh][m][dd] tf32.  v: [bh][dd][m] TRANSPOSED, tf32.
// ---------------------------------------------------------------------------
__global__ void reduce_build_kv(const float* __restrict__ part,
                                const float* __restrict__ bias,
                                const float* __restrict__ lv,
                                float* __restrict__ k, float* __restrict__ vt)
{
    const int idx = blockIdx.x * 256 + threadIdx.x;
    const int dd = idx & 63;
    const int m  = (idx >> 6) % 576;
    const int bh = idx / 36864;
    const int h  = bh & 7, b = bh >> 3;
    const int ck = h * 64 + dd;
    const long mrow = (long)(b * 576 + m) * 1024;
    float sk = bias[ck], sv = bias[512 + ck];
#pragma unroll
    for (int z = 0; z < 4; z++) {
        sk += part[z * 1179648 + mrow + ck];
        sv += part[z * 1179648 + mrow + 512 + ck];
    }
    k[idx] = __uint_as_float(f2tf(sk));
    float vv = sv + lv[(long)b * 294912 + h * 36864 + m * 64 + dd];
    vt[(long)bh * 36864 + dd * 576 + m] = __uint_as_float(f2tf(vv));
}

// w2[co][(i*4+j)*512 + ci] = tf32(w_sr[co][ci][i][j])
__global__ void reorder_w_kernel(const float* __restrict__ w,
                                 float* __restrict__ w2)
{
    const int tid = blockIdx.x * 256 + threadIdx.x;
    const int ci = tid & 511;
    const int s  = (tid >> 9) & 15;
    const int co = tid >> 13;
    w2[tid] = __uint_as_float(f2tf(w[(long)co * 8192 + ci * 16 + s]));
}

// pad lora_A_q / lora_A_v to 64x512 (tf32); prescale lora_B_q (tf32), b_q
__global__ void prep_lora(const float* __restrict__ lAq,
                          const float* __restrict__ lBq,
                          const float* __restrict__ lAv,
                          const float* __restrict__ bq,
                          float* __restrict__ lAqp,
                          float* __restrict__ lAvp,
                          float* __restrict__ Bq2,
                          float* __restrict__ bq8)
{
    const int i = blockIdx.x * 256 + threadIdx.x;
    if (i < 64 * 512) {
        lAqp[i] = (i < 32 * 512) ? __uint_as_float(f2tf(lAq[i])) : 0.f;
        lAvp[i] = (i < 32 * 512) ? __uint_as_float(f2tf(lAv[i])) : 0.f;
    }
    if (i < 512 * 32) Bq2[i] = __uint_as_float(f2tf(lBq[i] * SCALING));
    if (i < 512) bq8[i] = bq[i] * 0.125f;
}

// ---------------------------------------------------------------------------
// FA2-style tf32 attention, cp.async + double-buffered K/V (unchanged except
// ctx is emitted tf32-rounded for the proj GEMM).
// ---------------------------------------------------------------------------
#define TPw 68
#define ATTN_SMEM (TPw * 384 * 4)

__global__ void __launch_bounds__(256, 2)
attn_flash(const float* __restrict__ qb,
           const float* __restrict__ kb,
           const float* __restrict__ vtb,
           float* __restrict__ ctx)
{
    extern __shared__ float sm[];
    float*    Sw = sm;
    unsigned* KV = (unsigned*)(sm + 128 * TPw);

    const int t    = threadIdx.x;
    const int lane = t & 31, w = t >> 5;
    const int g  = lane >> 2, tg = lane & 3;
    const int bh = blockIdx.y, b = bh >> 3, h = bh & 7;
    const int n0 = blockIdx.x * 128;

    const int tS = lane >> 3;
    const unsigned swB = (unsigned)__cvta_generic_to_shared(Sw);
    const unsigned kvB = (unsigned)__cvta_generic_to_shared(KV);
    const unsigned aOff = ((w * 16 + (tS & 1) * 8 + (lane & 7)) * TPw
                           + (tS >> 1) * 4) * 4;
    const unsigned bOff = (((tS >> 1) * 8 + (lane & 7)) * TPw
                           + (tS & 1) * 4) * 4;
    constexpr unsigned BUFB = 128 * TPw * 4;
    constexpr unsigned VOFF = 64 * TPw * 4;

    auto loadQ = [&]() {
#pragma unroll
        for (int i = 0; i < 8; i++) {
            int c = i * 256 + t;
            int row = c >> 4, off = (c & 15) * 4;
            cpa16(swB + (row * TPw + off) * 4,
                  qb + (long)(b * 9216 + n0 + row) * 512 + h * 64 + off);
        }
    };
    auto loadKV = [&](int ch, int buf) {
#pragma unroll
        for (int i = 0; i < 4; i++) {
            int c = i * 256 + t;
            int row = c >> 4, off = (c & 15) * 4;
            cpa16(kvB + buf * BUFB + (row * TPw + off) * 4,
                  kb + (long)(bh * 576 + ch * 64 + row) * 64 + off);
            cpa16(kvB + buf * BUFB + VOFF + (row * TPw + off) * 4,
                  vtb + (long)bh * 36864 + row * 576 + ch * 64 + off);
        }
    };

    loadQ();
    loadKV(0, 0);
    cpa_commit();
    cpa_wait0();
    __syncthreads();

    unsigned Qf[8][4];
#pragma unroll
    for (int kk = 0; kk < 8; kk++)
        ldsm4(Qf[kk], swB + aOff + kk * 32);

    float O[8][4];
#pragma unroll
    for (int nd = 0; nd < 8; nd++)
#pragma unroll
        for (int c = 0; c < 4; c++) O[nd][c] = 0.f;
    float m0 = -1e30f, l0 = 0.f, m1 = -1e30f, l1 = 0.f;

    int buf = 0;
    for (int ch = 0; ch < 9; ch++) {
        const bool more = (ch + 1 < 9);
        if (more) { loadKV(ch + 1, buf ^ 1); cpa_commit(); }

        const unsigned ksB = kvB + buf * BUFB + bOff;
        const unsigned vsB = kvB + buf * BUFB + VOFF + bOff;

        float acc[8][4];
#pragma unroll
        for (int ni = 0; ni < 8; ni++)
#pragma unroll
            for (int c = 0; c < 4; c++) acc[ni][c] = 0.f;
#pragma unroll
        for (int kk = 0; kk < 8; kk++) {
            unsigned bf[8][2];
#pragma unroll
            for (int p = 0; p < 4; p++) {
                unsigned q4[4];
                ldsm4(q4, ksB + p * (16 * TPw * 4) + kk * 32);
                bf[2 * p][0] = q4[0]; bf[2 * p][1] = q4[1];
                bf[2 * p + 1][0] = q4[2]; bf[2 * p + 1][1] = q4[3];
            }
#pragma unroll
            for (int ni = 0; ni < 8; ni++)
                mma8(acc[ni], Qf[kk], bf[ni]);
        }

        float cm0 = -1e30f, cm1 = -1e30f;
#pragma unroll
        for (int ni = 0; ni < 8; ni++) {
            cm0 = fmaxf(cm0, fmaxf(acc[ni][0], acc[ni][1]));
            cm1 = fmaxf(cm1, fmaxf(acc[ni][2], acc[ni][3]));
        }
        cm0 = fmaxf(cm0, __shfl_xor_sync(0xffffffffu, cm0, 1));
        cm0 = fmaxf(cm0, __shfl_xor_sync(0xffffffffu, cm0, 2));
        cm1 = fmaxf(cm1, __shfl_xor_sync(0xffffffffu, cm1, 1));
        cm1 = fmaxf(cm1, __shfl_xor_sync(0xffffffffu, cm1, 2));
        const float nm0 = fmaxf(m0, cm0), nm1 = fmaxf(m1, cm1);
        const float al0 = __expf(m0 - nm0), al1 = __expf(m1 - nm1);
        float sum0 = 0.f, sum1 = 0.f;
#pragma unroll
        for (int ni = 0; ni < 8; ni++) {
            float e0 = __uint_as_float(f2tf(__expf(acc[ni][0] - nm0)));
            float e1 = __uint_as_float(f2tf(__expf(acc[ni][1] - nm0)));
            float e2 = __uint_as_float(f2tf(__expf(acc[ni][2] - nm1)));
            float e3 = __uint_as_float(f2tf(__expf(acc[ni][3] - nm1)));
            acc[ni][0] = e0; acc[ni][1] = e1; acc[ni][2] = e2; acc[ni][3] = e3;
            sum0 += e0 + e1; sum1 += e2 + e3;
        }
        sum0 += __shfl_xor_sync(0xffffffffu, sum0, 1);
        sum0 += __shfl_xor_sync(0xffffffffu, sum0, 2);
        sum1 += __shfl_xor_sync(0xffffffffu, sum1, 1);
        sum1 += __shfl_xor_sync(0xffffffffu, sum1, 2);
        l0 = l0 * al0 + sum0; l1 = l1 * al1 + sum1;
        m0 = nm0; m1 = nm1;
#pragma unroll
        for (int nd = 0; nd < 8; nd++) {
            O[nd][0] *= al0; O[nd][1] *= al0;
            O[nd][2] *= al1; O[nd][3] *= al1;
        }

        float* SwW = Sw + w * 16 * TPw;
#pragma unroll
        for (int ni = 0; ni < 8; ni++) {
            *(float2*)&SwW[g * TPw + ni * 8 + 2 * tg] =
                make_float2(acc[ni][0], acc[ni][1]);
            *(float2*)&SwW[(g + 8) * TPw + ni * 8 + 2 * tg] =
                make_float2(acc[ni][2], acc[ni][3]);
        }
        __syncwarp();

#pragma unroll
        for (int kk = 0; kk < 8; kk++) {
            unsigned pa[4];
            ldsm4(pa, swB + aOff + kk * 32);
            unsigned bf[8][2];
#pragma unroll
            for (int p = 0; p < 4; p++) {
                unsigned q4[4];
                ldsm4(q4, vsB + p * (16 * TPw * 4) + kk * 32);
                bf[2 * p][0] = q4[0]; bf[2 * p][1] = q4[1];
                bf[2 * p + 1][0] = q4[2]; bf[2 * p + 1][1] = q4[3];
            }
#pragma unroll
            for (int nd = 0; nd < 8; nd++)
                mma8(O[nd], pa, bf[nd]);
        }

        if (more) {
            cpa_wait0();
            __syncthreads();
            buf ^= 1;
        }
    }

    const float inv0 = 1.f / l0, inv1 = 1.f / l1;
    const long row0 = (long)(b * 9216 + n0 + w * 16 + g) * 512 + h * 64;
    const long row1 = row0 + 8 * 512;
#pragma unroll
    for (int nd = 0; nd < 8; nd++) {
        const int c = nd * 8 + 2 * tg;
        *(float2*)(ctx + row0 + c) =
            make_float2(__uint_as_float(f2tf(O[nd][0] * inv0)),
                        __uint_as_float(f2tf(O[nd][1] * inv0)));
        *(float2*)(ctx + row1 + c) =
            make_float2(__uint_as_float(f2tf(O[nd][2] * inv1)),
                        __uint_as_float(f2tf(O[nd][3] * inv1)));
    }
}

// ---------------------------------------------------------------------------
// Launch pipeline
// ---------------------------------------------------------------------------
extern "C" void kernel_launch(void* const* d_in, const int* in_sizes, int n_in,
                              void* d_out, int out_size)
{
    (void)in_sizes; (void)n_in; (void)out_size;
    const float* x      = (const float*)d_in[0];
    const float* w_q    = (const float*)d_in[1];
    const float* b_q    = (const float*)d_in[2];
    const float* w_kv   = (const float*)d_in[3];
    const float* b_kv   = (const float*)d_in[4];
    const float* w_proj = (const float*)d_in[5];
    const float* b_proj = (const float*)d_in[6];
    const float* w_sr   = (const float*)d_in[7];
    const float* b_sr   = (const float*)d_in[8];
    const float* ln_g   = (const float*)d_in[9];
    const float* ln_b   = (const float*)d_in[10];
    const float* lAq    = (const float*)d_in[11];
    const float* lBq    = (const float*)d_in[12];
    const float* lAv    = (const float*)d_in[13];
    const float* lBv    = (const float*)d_in[14];

    float *q, *xtf, *xs, *t2p, *lv, *k, *v, *ctx, *t1p, *w2, *part;
    float *lAqp, *lAvp, *Bq2, *bq8, *wq2, *wkv2, *wp2, *lBv2;
    cudaGetSymbolAddress((void**)&q,     g_q);
    cudaGetSymbolAddress((void**)&xtf,   g_xtf);
    cudaGetSymbolAddress((void**)&xs,    g_xs);
    cudaGetSymbolAddress((void**)&t2p,   g_t2p);
    cudaGetSymbolAddress((void**)&lv,    g_lv);
    cudaGetSymbolAddress((void**)&k,     g_k);
    cudaGetSymbolAddress((void**)&v,     g_v);
    cudaGetSymbolAddress((void**)&ctx,   g_ctx);
    cudaGetSymbolAddress((void**)&t1p,   g_t1p);
    cudaGetSymbolAddress((void**)&w2,    g_w2);
    cudaGetSymbolAddress((void**)&part,  g_part);
    cudaGetSymbolAddress((void**)&lAqp,  g_lAqp);
    cudaGetSymbolAddress((void**)&lAvp,  g_lAvp);
    cudaGetSymbolAddress((void**)&Bq2,   g_Bq2);
    cudaGetSymbolAddress((void**)&bq8,   g_bq8);
    cudaGetSymbolAddress((void**)&wq2,   g_wq2);
    cudaGetSymbolAddress((void**)&wkv2,  g_wkv2);
    cudaGetSymbolAddress((void**)&wp2,   g_wp2);
    cudaGetSymbolAddress((void**)&lBv2,  g_lBv2);

    static cudaStream_t s2 = nullptr;
    static cudaEvent_t evF = nullptr, evX = nullptr, evJ = nullptr;
    if (!s2) {
        cudaStreamCreateWithFlags(&s2, cudaStreamNonBlocking);
        cudaEventCreateWithFlags(&evF, cudaEventDisableTiming);
        cudaEventCreateWithFlags(&evX, cudaEventDisableTiming);
        cudaEventCreateWithFlags(&evJ, cudaEventDisableTiming);
    }

    dim3 blk(256);
    const int smem128 = 3 * 256 * 20 * 4;   // 61440
    const int smem64  = 3 * 192 * 20 * 4;   // 46080
    cudaFuncSetAttribute(gemm_tf32<128, 0>,
                         cudaFuncAttributeMaxDynamicSharedMemorySize, smem128);
    cudaFuncSetAttribute(gemm_tf32<128, 1>,
                         cudaFuncAttributeMaxDynamicSharedMemorySize, smem128);
    cudaFuncSetAttribute(gemm_tf32<64, 0>,
                         cudaFuncAttributeMaxDynamicSharedMemorySize, smem64);
    cudaFuncSetAttribute(attn_flash,
                         cudaFuncAttributeMaxDynamicSharedMemorySize, ATTN_SMEM);

    // ---- prep on main (both chains depend on parts of it) ----
    prep_lora<<<128, blk>>>(lAq, lBq, lAv, b_q, lAqp, lAvp, Bq2, bq8);

    // ---- fork (side chain starts with x-independent work) ----
    cudaEventRecord(evF, 0);
    cudaStreamWaitEvent(s2, evF, 0);

    // main: convert x (+ weights for q path)
    cvt_tf32<<<9216, blk>>>(x, xtf);
    cudaEventRecord(evX, 0);
    cvt_tf32<<<256, blk>>>(w_q, wq2);
    cvt_tf32<<<256, blk>>>(w_proj, wp2);

    // side: conv-weight reorder + kv/lBv weight conversion, then wait for xtf
    reorder_w_kernel<<<16384, blk, 0, s2>>>(w_sr, w2);
    cvt_tf32<<<512, blk, 0, s2>>>(w_kv, wkv2);
    cvt_tf32<<<16, blk, 0, s2>>>(lBv, lBv2);
    cudaStreamWaitEvent(s2, evX, 0);

    // side chain: conv -> LN -> kv -> lora-v -> build k/v
    gemm_tf32<128, 1><<<dim3(4, 9, 8), blk, smem128, s2>>>(
        1152, 512, 8192, xtf, 512, w2, 8192, nullptr, 1.f, nullptr, 512,
        1024, part, nullptr, 0, nullptr, 0, 0, 0);
    reduce_ln<<<1152, 128, 0, s2>>>(part, b_sr, ln_g, ln_b, xs);
    gemm_tf32<128, 0><<<dim3(8, 9, 4), blk, smem128, s2>>>(
        1152, 1024, 512, xs, 512, wkv2, 512, nullptr, 1.f, nullptr, 1024,
        128, part, nullptr, 0, nullptr, 0, 0, 0);
    gemm_tf32<64, 0><<<dim3(1, 9, 1), blk, smem64, s2>>>(
        1152, 64, 512, xs, 512, lAvp, 512, nullptr, 1.f, t2p, 64,
        512, nullptr, nullptr, 0, nullptr, 0, 0, 1);
    gemm_tf32<128, 0><<<dim3(4, 9, 1), blk, smem128, s2>>>(
        1152, 512, 32, t2p, 64, lBv2, 32, nullptr, SCALING, lv, 512,
        32, nullptr, nullptr, 0, nullptr, 0, 0, 0);
    reduce_build_kv<<<2304, blk, 0, s2>>>(part, b_kv, lv, k, v);
    cudaEventRecord(evJ, s2);

    // main chain: t1p -> q (prescaled 0.125, tf32-rounded)
    gemm_tf32<64, 0><<<dim3(1, 144, 1), blk, smem64>>>(
        18432, 64, 512, xtf, 512, lAqp, 512, nullptr, 1.f, t1p, 64,
        512, nullptr, nullptr, 0, nullptr, 0, 0, 1);
    gemm_tf32<128, 0><<<dim3(4, 144, 1), blk, smem128>>>(
        18432, 512, 512, xtf, 512, wq2, 512, bq8, 0.125f, q, 512,
        512, nullptr, t1p, 64, Bq2, 32, 32, 1);

    // join
    cudaStreamWaitEvent(0, evJ, 0);

    attn_flash<<<dim3(72, 16), blk, ATTN_SMEM>>>(q, k, v, ctx);

    gemm_tf32<128, 0><<<dim3(4, 144, 1), blk, smem128>>>(
        18432, 512, 512, ctx, 512, wp2, 512, b_proj, 1.f, (float*)d_out,
        512, 512, nullptr, nullptr, 0, nullptr, 0, 0, 0);
}

// round 12
// speedup vs baseline: 5.4286x; 1.0413x over previous
#include <cuda_runtime.h>
#include <math.h>

// B=2, N=9216, C=512, HEAD=8, d=64, SR=4, H=W=96 -> Nkv=576, R=32
#define SCALING 0.125f

// ---------------------------------------------------------------------------
// Scratch (all GEMM operands stored tf32-rounded)
// ---------------------------------------------------------------------------
__device__ float g_q    [9437184];  // (B,N,C) prescaled*0.125, tf32
__device__ float g_xtf  [9437184];  // x tf32-rounded
__device__ float g_xs   [589824];   // (B*576,512) post-LN, tf32
__device__ float g_t2p  [73728];    // 1152x64 lora-v intermediate, tf32
__device__ float g_lv   [589824];
__device__ float g_k    [589824];   // (B*H,576,64) tf32
__device__ float g_v    [589824];   // (B*H,64,576) TRANSPOSED, tf32
__device__ float g_ctx  [9437184];  // tf32
__device__ float g_t1p  [1179648];  // 18432x64 lora-q intermediate, tf32
__device__ float g_w2   [4194304];  // 512x8192 reordered conv weight, tf32
__device__ float g_part [4718592];  // split-K partials
__device__ float g_lAqp [32768];    // 64x512 padded lora_A_q, tf32
__device__ float g_lAvp [32768];    // 64x512 padded lora_A_v, tf32
__device__ float g_Bq2  [16384];    // 512x32 prescaled lora_B_q, tf32
__device__ float g_bq8  [512];      // b_q * 0.125
__device__ float g_wq2  [262144];   // w_q tf32
__device__ float g_wkv2 [524288];   // w_kv tf32
__device__ float g_wp2  [262144];   // w_proj tf32
__device__ float g_lBv2 [16384];    // lora_B_v tf32

// ---------------------------------------------------------------------------
// helpers
// ---------------------------------------------------------------------------
__device__ __forceinline__ unsigned f2tf(float x) {
    unsigned u;
    asm("cvt.rna.tf32.f32 %0, %1;" : "=r"(u) : "f"(x));
    return u;
}
__device__ __forceinline__ void mma8(float* c, const unsigned* a, const unsigned* b) {
    asm volatile(
        "mma.sync.aligned.m16n8k8.row.col.f32.tf32.tf32.f32 "
        "{%0,%1,%2,%3}, {%4,%5,%6,%7}, {%8,%9}, {%0,%1,%2,%3};"
        : "+f"(c[0]), "+f"(c[1]), "+f"(c[2]), "+f"(c[3])
        : "r"(a[0]), "r"(a[1]), "r"(a[2]), "r"(a[3]),
          "r"(b[0]), "r"(b[1]));
}
__device__ __forceinline__ void ldsm4(unsigned* r, unsigned addr) {
    asm volatile(
        "ldmatrix.sync.aligned.m8n8.x4.shared.b16 {%0,%1,%2,%3}, [%4];"
        : "=r"(r[0]), "=r"(r[1]), "=r"(r[2]), "=r"(r[3]) : "r"(addr));
}
__device__ __forceinline__ void cpa16(unsigned dst, const void* src) {
    asm volatile("cp.async.cg.shared.global [%0], [%1], 16;" :: "r"(dst), "l"(src));
}
__device__ __forceinline__ void cpa_commit() {
    asm volatile("cp.async.commit_group;" ::: "memory");
}
__device__ __forceinline__ void cpa_wait0() {
    asm volatile("cp.async.wait_group 0;" ::: "memory");
}

// elementwise tf32 round (n multiple of 1024)
__global__ void cvt_tf32(const float* __restrict__ in, float* __restrict__ out)
{
    const int i = (blockIdx.x * 256 + threadIdx.x) * 4;
    float4 v = *(const float4*)(in + i);
    uint4 u;
    u.x = f2tf(v.x); u.y = f2tf(v.y); u.z = f2tf(v.z); u.w = f2tf(v.w);
    *(uint4*)(out + i) = u;
}

// ---------------------------------------------------------------------------
// tf32 GEMM, BK=32, 2-stage cp.async pipeline, ldmatrix frags.
// All operands pre-tf32.  C = scale*(A@B^T [+ A2@B2^T]) (+bias) [round_out]
// BM=128, BN in {64,128}; 256 threads; warps 4(M)x2(N).
// REQUIRES kchunk%32==0, K2%32==0 (or 0).
// CONV=1: A gathered from x_tf with SR-conv im2col mapping.
// dyn smem: 2*(128+BN)*36*4 bytes.  Pitch 36 words (36 % 32 == 4).
// ---------------------------------------------------------------------------
template <int BN, int CONV>
__global__ void __launch_bounds__(256, 2)
gemm_tf32(int M, int N, int K,
          const float* __restrict__ A, int lda,
          const float* __restrict__ B, int ldb,
          const float* __restrict__ bias,
          float scale,
          float* __restrict__ C, int ldc,
          int kchunk, float* __restrict__ part,
          const float* __restrict__ A2, int lda2,
          const float* __restrict__ B2, int ldb2, int K2,
          int round_out)
{
    constexpr int NI = BN / 16;
    constexpr int P  = 36;                 // smem pitch (words)
    extern __shared__ unsigned gsm[];
    unsigned* AsU = gsm;                   // 2 x 128 x P
    unsigned* BsU = gsm + 2 * 128 * P;     // 2 x BN x P

    const int t    = threadIdx.x;
    const int lane = t & 31, w = t >> 5;
    const int g  = lane >> 2, tg = lane & 3;
    const int wm = w >> 1,  wn = w & 1;
    const long m0 = (long)blockIdx.y * 128;
    const int  n0 = blockIdx.x * BN;
    const int  kb = blockIdx.z * kchunk;

    // loader: chunk c covers row = c>>3, k-offset = (c&7)*4 (16B)
    const int lrow = t >> 3;               // 0..31
    const int lko  = (t & 7) * 4;          // 0..28

    const int tS = lane >> 3;
    const unsigned asB = (unsigned)__cvta_generic_to_shared(AsU);
    const unsigned bsB = (unsigned)__cvta_generic_to_shared(BsU);
    const unsigned aOff = ((wm * 32 + (tS & 1) * 8 + (lane & 7)) * P
                           + (tS >> 1) * 4) * 4;
    const unsigned bOff = ((wn * (BN / 2) + (tS >> 1) * 8 + (lane & 7)) * P
                           + (tS & 1) * 4) * 4;

    float acc[2][NI][4];
#pragma unroll
    for (int mi = 0; mi < 2; mi++)
#pragma unroll
        for (int ni = 0; ni < NI; ni++)
#pragma unroll
            for (int c = 0; c < 4; c++) acc[mi][ni][c] = 0.f;

    // conv row bases for the 4 A rows this thread loads
    long cr[4];
    if (CONV) {
#pragma unroll
        for (int i = 0; i < 4; i++) {
            int m = (int)m0 + i * 32 + lrow;
            int b = m / 576, p = m % 576, py = p / 24, px = p % 24;
            cr[i] = (long)b * 9216 + (py * 4) * 96 + px * 4;
        }
    }

    const int n1 = kchunk >> 5;
    const int nIter = n1 + (K2 >> 5);

    auto issueTile = [&](int idx, int s) {
        const unsigned aS = asB + s * (128 * P * 4);
        const unsigned bS = bsB + s * (BN * P * 4);
        if (idx < n1) {
            const int k0 = kb + (idx << 5);
            if (CONV) {
                const int tap = k0 >> 9;
                const int ci  = (k0 & 511) + lko;
                const long toff = (long)((tap >> 2) * 96 + (tap & 3)) * 512 + ci;
#pragma unroll
                for (int i = 0; i < 4; i++)
                    cpa16(aS + ((i * 32 + lrow) * P + lko) * 4,
                          A + cr[i] * 512 + toff);
            } else {
#pragma unroll
                for (int i = 0; i < 4; i++)
                    cpa16(aS + ((i * 32 + lrow) * P + lko) * 4,
                          A + (m0 + i * 32 + lrow) * lda + k0 + lko);
            }
#pragma unroll
            for (int i = 0; i < BN / 32; i++)
                cpa16(bS + ((i * 32 + lrow) * P + lko) * 4,
                      B + (long)(n0 + i * 32 + lrow) * ldb + k0 + lko);
        } else {
            const int k0 = (idx - n1) << 5;
#pragma unroll
            for (int i = 0; i < 4; i++)
                cpa16(aS + ((i * 32 + lrow) * P + lko) * 4,
                      A2 + (m0 + i * 32 + lrow) * lda2 + k0 + lko);
#pragma unroll
            for (int i = 0; i < BN / 32; i++)
                cpa16(bS + ((i * 32 + lrow) * P + lko) * 4,
                      B2 + (long)(n0 + i * 32 + lrow) * ldb2 + k0 + lko);
        }
        cpa_commit();
    };

    issueTile(0, 0);

    for (int it = 0; it < nIter; it++) {
        cpa_wait0();        // tile it arrived
        __syncthreads();    // all warps done with the other buffer
        if (it + 1 < nIter) issueTile(it + 1, (it + 1) & 1);

        const int s = it & 1;
        const unsigned aB = asB + s * (128 * P * 4) + aOff;
        const unsigned bB = bsB + s * (BN * P * 4) + bOff;
#pragma unroll
        for (int kk = 0; kk < 32; kk += 8) {
            unsigned af[2][4], bf[NI][2];
#pragma unroll
            for (int mi = 0; mi < 2; mi++)
                ldsm4(af[mi], aB + mi * (16 * P * 4) + kk * 4);
#pragma unroll
            for (int p = 0; p < NI / 2; p++) {
                unsigned q4[4];
                ldsm4(q4, bB + p * (16 * P * 4) + kk * 4);
                bf[2 * p][0] = q4[0]; bf[2 * p][1] = q4[1];
                bf[2 * p + 1][0] = q4[2]; bf[2 * p + 1][1] = q4[3];
            }
#pragma unroll
            for (int mi = 0; mi < 2; mi++)
#pragma unroll
                for (int ni = 0; ni < NI; ni++)
                    mma8(acc[mi][ni], af[mi], bf[ni]);
        }
    }

    if (gridDim.z == 1) {
#pragma unroll
        for (int mi = 0; mi < 2; mi++) {
            const long r0 = m0 + wm * 32 + mi * 16 + g;
            const long r1 = r0 + 8;
#pragma unroll
            for (int ni = 0; ni < NI; ni++) {
                const int c = n0 + wn * (BN / 2) + ni * 8 + 2 * tg;
                float v00 = scale * acc[mi][ni][0];
                float v01 = scale * acc[mi][ni][1];
                float v10 = scale * acc[mi][ni][2];
                float v11 = scale * acc[mi][ni][3];
                if (bias) {
                    float b0 = bias[c], b1 = bias[c + 1];
                    v00 += b0; v01 += b1; v10 += b0; v11 += b1;
                }
                if (round_out) {
                    v00 = __uint_as_float(f2tf(v00));
                    v01 = __uint_as_float(f2tf(v01));
                    v10 = __uint_as_float(f2tf(v10));
                    v11 = __uint_as_float(f2tf(v11));
                }
                *(float2*)(C + r0 * ldc + c) = make_float2(v00, v01);
                *(float2*)(C + r1 * ldc + c) = make_float2(v10, v11);
            }
        }
    } else {
        float* Pp = part + (long)blockIdx.z * M * ldc;
#pragma unroll
        for (int mi = 0; mi < 2; mi++) {
            const long r0 = m0 + wm * 32 + mi * 16 + g;
            const long r1 = r0 + 8;
#pragma unroll
            for (int ni = 0; ni < NI; ni++) {
                const int c = n0 + wn * (BN / 2) + ni * 8 + 2 * tg;
                *(float2*)(Pp + r0 * ldc + c) =
                    make_float2(acc[mi][ni][0], acc[mi][ni][1]);
                *(float2*)(Pp + r1 * ldc + c) =
                    make_float2(acc[mi][ni][2], acc[mi][ni][3]);
            }
        }
    }
}

// ---------------------------------------------------------------------------
// Fused conv split-K reduce + bias + LayerNorm -> xs (tf32-rounded).
// ---------------------------------------------------------------------------
__global__ void reduce_ln(const float* __restrict__ part,
                          const float* __restrict__ bias,
                          const float* __restrict__ gam,
                          const float* __restrict__ bet,
                          float* __restrict__ out)
{
    const int row = blockIdx.x;
    const int t   = threadIdx.x;
    float v[4];
#pragma unroll
    for (int j = 0; j < 4; j++) {
        const int col = t + j * 128;
        float s = bias[col];
        const long off = (long)row * 512 + col;
#pragma unroll
        for (int z = 0; z < 8; z++) s += part[z * 589824 + off];
        v[j] = s;
    }
    float s  = v[0] + v[1] + v[2] + v[3];
    float s2 = v[0]*v[0] + v[1]*v[1] + v[2]*v[2] + v[3]*v[3];
#pragma unroll
    for (int o = 16; o > 0; o >>= 1) {
        s  += __shfl_xor_sync(0xffffffffu, s,  o);
        s2 += __shfl_xor_sync(0xffffffffu, s2, o);
    }
    __shared__ float ss[4], ss2[4];
    if ((t & 31) == 0) { ss[t >> 5] = s; ss2[t >> 5] = s2; }
    __syncthreads();
    s  = ss[0]  + ss[1]  + ss[2]  + ss[3];
    s2 = ss2[0] + ss2[1] + ss2[2] + ss2[3];
    const float mean = s * (1.f / 512.f);
    const float var  = s2 * (1.f / 512.f) - mean * mean;
    const float inv  = rsqrtf(var + 1e-5f);
    float* o = out + (long)row * 512;
#pragma unroll
    for (int j = 0; j < 4; j++) {
        const int col = t + j * 128;
        o[col] = __uint_as_float(f2tf((v[j] - mean) * inv * gam[col] + bet[col]));
    }
}

// ---------------------------------------------------------------------------
// Fused kv split-K reduce + bias + head split + LoRA-v fixup.
// k: [bh][m][dd] tf32.  v: [bh][dd][m] TRANSPOSED, tf32.
// ---------------------------------------------------------------------------
__global__ void reduce_build_kv(const float* __restrict__ part,
                                const float* __restrict__ bias,
                                const float* __restrict__ lv,
                                float* __restrict__ k, float* __restrict__ vt)
{
    const int idx = blockIdx.x * 256 + threadIdx.x;
    const int dd = idx & 63;
    const int m  = (idx >> 6) % 576;
    const int bh = idx / 36864;
    const int h  = bh & 7, b = bh >> 3;
    const int ck = h * 64 + dd;
    const long mrow = (long)(b * 576 + m) * 1024;
    float sk = bias[ck], sv = bias[512 + ck];
#pragma unroll
    for (int z = 0; z < 4; z++) {
        sk += part[z * 1179648 + mrow + ck];
        sv += part[z * 1179648 + mrow + 512 + ck];
    }
    k[idx] = __uint_as_float(f2tf(sk));
    float vv = sv + lv[(long)b * 294912 + h * 36864 + m * 64 + dd];
    vt[(long)bh * 36864 + dd * 576 + m] = __uint_as_float(f2tf(vv));
}

// w2[co][(i*4+j)*512 + ci] = tf32(w_sr[co][ci][i][j])
__global__ void reorder_w_kernel(const float* __restrict__ w,
                                 float* __restrict__ w2)
{
    const int tid = blockIdx.x * 256 + threadIdx.x;
    const int ci = tid & 511;
    const int s  = (tid >> 9) & 15;
    const int co = tid >> 13;
    w2[tid] = __uint_as_float(f2tf(w[(long)co * 8192 + ci * 16 + s]));
}

// pad lora_A_q / lora_A_v to 64x512 (tf32); prescale lora_B_q (tf32), b_q
__global__ void prep_lora(const float* __restrict__ lAq,
                          const float* __restrict__ lBq,
                          const float* __restrict__ lAv,
                          const float* __restrict__ bq,
                          float* __restrict__ lAqp,
                          float* __restrict__ lAvp,
                          float* __restrict__ Bq2,
                          float* __restrict__ bq8)
{
    const int i = blockIdx.x * 256 + threadIdx.x;
    if (i < 64 * 512) {
        lAqp[i] = (i < 32 * 512) ? __uint_as_float(f2tf(lAq[i])) : 0.f;
        lAvp[i] = (i < 32 * 512) ? __uint_as_float(f2tf(lAv[i])) : 0.f;
    }
    if (i < 512 * 32) Bq2[i] = __uint_as_float(f2tf(lBq[i] * SCALING));
    if (i < 512) bq8[i] = bq[i] * 0.125f;
}

// ---------------------------------------------------------------------------
// FA2-style tf32 attention, cp.async + double-buffered K/V.
// ---------------------------------------------------------------------------
#define TPw 68
#define ATTN_SMEM (TPw * 384 * 4)

__global__ void __launch_bounds__(256, 2)
attn_flash(const float* __restrict__ qb,
           const float* __restrict__ kb,
           const float* __restrict__ vtb,
           float* __restrict__ ctx)
{
    extern __shared__ float sm[];
    float*    Sw = sm;
    unsigned* KV = (unsigned*)(sm + 128 * TPw);

    const int t    = threadIdx.x;
    const int lane = t & 31, w = t >> 5;
    const int g  = lane >> 2, tg = lane & 3;
    const int bh = blockIdx.y, b = bh >> 3, h = bh & 7;
    const int n0 = blockIdx.x * 128;

    const int tS = lane >> 3;
    const unsigned swB = (unsigned)__cvta_generic_to_shared(Sw);
    const unsigned kvB = (unsigned)__cvta_generic_to_shared(KV);
    const unsigned aOff = ((w * 16 + (tS & 1) * 8 + (lane & 7)) * TPw
                           + (tS >> 1) * 4) * 4;
    const unsigned bOff = (((tS >> 1) * 8 + (lane & 7)) * TPw
                           + (tS & 1) * 4) * 4;
    constexpr unsigned BUFB = 128 * TPw * 4;
    constexpr unsigned VOFF = 64 * TPw * 4;

    auto loadQ = [&]() {
#pragma unroll
        for (int i = 0; i < 8; i++) {
            int c = i * 256 + t;
            int row = c >> 4, off = (c & 15) * 4;
            cpa16(swB + (row * TPw + off) * 4,
                  qb + (long)(b * 9216 + n0 + row) * 512 + h * 64 + off);
        }
    };
    auto loadKV = [&](int ch, int buf) {
#pragma unroll
        for (int i = 0; i < 4; i++) {
            int c = i * 256 + t;
            int row = c >> 4, off = (c & 15) * 4;
            cpa16(kvB + buf * BUFB + (row * TPw + off) * 4,
                  kb + (long)(bh * 576 + ch * 64 + row) * 64 + off);
            cpa16(kvB + buf * BUFB + VOFF + (row * TPw + off) * 4,
                  vtb + (long)bh * 36864 + row * 576 + ch * 64 + off);
        }
    };

    loadQ();
    loadKV(0, 0);
    cpa_commit();
    cpa_wait0();
    __syncthreads();

    unsigned Qf[8][4];
#pragma unroll
    for (int kk = 0; kk < 8; kk++)
        ldsm4(Qf[kk], swB + aOff + kk * 32);

    float O[8][4];
#pragma unroll
    for (int nd = 0; nd < 8; nd++)
#pragma unroll
        for (int c = 0; c < 4; c++) O[nd][c] = 0.f;
    float m0 = -1e30f, l0 = 0.f, m1 = -1e30f, l1 = 0.f;

    int buf = 0;
    for (int ch = 0; ch < 9; ch++) {
        const bool more = (ch + 1 < 9);
        if (more) { loadKV(ch + 1, buf ^ 1); cpa_commit(); }

        const unsigned ksB = kvB + buf * BUFB + bOff;
        const unsigned vsB = kvB + buf * BUFB + VOFF + bOff;

        float acc[8][4];
#pragma unroll
        for (int ni = 0; ni < 8; ni++)
#pragma unroll
            for (int c = 0; c < 4; c++) acc[ni][c] = 0.f;
#pragma unroll
        for (int kk = 0; kk < 8; kk++) {
            unsigned bf[8][2];
#pragma unroll
            for (int p = 0; p < 4; p++) {
                unsigned q4[4];
                ldsm4(q4, ksB + p * (16 * TPw * 4) + kk * 32);
                bf[2 * p][0] = q4[0]; bf[2 * p][1] = q4[1];
                bf[2 * p + 1][0] = q4[2]; bf[2 * p + 1][1] = q4[3];
            }
#pragma unroll
            for (int ni = 0; ni < 8; ni++)
                mma8(acc[ni], Qf[kk], bf[ni]);
        }

        float cm0 = -1e30f, cm1 = -1e30f;
#pragma unroll
        for (int ni = 0; ni < 8; ni++) {
            cm0 = fmaxf(cm0, fmaxf(acc[ni][0], acc[ni][1]));
            cm1 = fmaxf(cm1, fmaxf(acc[ni][2], acc[ni][3]));
        }
        cm0 = fmaxf(cm0, __shfl_xor_sync(0xffffffffu, cm0, 1));
        cm0 = fmaxf(cm0, __shfl_xor_sync(0xffffffffu, cm0, 2));
        cm1 = fmaxf(cm1, __shfl_xor_sync(0xffffffffu, cm1, 1));
        cm1 = fmaxf(cm1, __shfl_xor_sync(0xffffffffu, cm1, 2));
        const float nm0 = fmaxf(m0, cm0), nm1 = fmaxf(m1, cm1);
        const float al0 = __expf(m0 - nm0), al1 = __expf(m1 - nm1);
        float sum0 = 0.f, sum1 = 0.f;
#pragma unroll
        for (int ni = 0; ni < 8; ni++) {
            float e0 = __uint_as_float(f2tf(__expf(acc[ni][0] - nm0)));
            float e1 = __uint_as_float(f2tf(__expf(acc[ni][1] - nm0)));
            float e2 = __uint_as_float(f2tf(__expf(acc[ni][2] - nm1)));
            float e3 = __uint_as_float(f2tf(__expf(acc[ni][3] - nm1)));
            acc[ni][0] = e0; acc[ni][1] = e1; acc[ni][2] = e2; acc[ni][3] = e3;
            sum0 += e0 + e1; sum1 += e2 + e3;
        }
        sum0 += __shfl_xor_sync(0xffffffffu, sum0, 1);
        sum0 += __shfl_xor_sync(0xffffffffu, sum0, 2);
        sum1 += __shfl_xor_sync(0xffffffffu, sum1, 1);
        sum1 += __shfl_xor_sync(0xffffffffu, sum1, 2);
        l0 = l0 * al0 + sum0; l1 = l1 * al1 + sum1;
        m0 = nm0; m1 = nm1;
#pragma unroll
        for (int nd = 0; nd < 8; nd++) {
            O[nd][0] *= al0; O[nd][1] *= al0;
            O[nd][2] *= al1; O[nd][3] *= al1;
        }

        float* SwW = Sw + w * 16 * TPw;
#pragma unroll
        for (int ni = 0; ni < 8; ni++) {
            *(float2*)&SwW[g * TPw + ni * 8 + 2 * tg] =
                make_float2(acc[ni][0], acc[ni][1]);
            *(float2*)&SwW[(g + 8) * TPw + ni * 8 + 2 * tg] =
                make_float2(acc[ni][2], acc[ni][3]);
        }
        __syncwarp();

#pragma unroll
        for (int kk = 0; kk < 8; kk++) {
            unsigned pa[4];
            ldsm4(pa, swB + aOff + kk * 32);
            unsigned bf[8][2];
#pragma unroll
            for (int p = 0; p < 4; p++) {
                unsigned q4[4];
                ldsm4(q4, vsB + p * (16 * TPw * 4) + kk * 32);
                bf[2 * p][0] = q4[0]; bf[2 * p][1] = q4[1];
                bf[2 * p + 1][0] = q4[2]; bf[2 * p + 1][1] = q4[3];
            }
#pragma unroll
            for (int nd = 0; nd < 8; nd++)
                mma8(O[nd], pa, bf[nd]);
        }

        if (more) {
            cpa_wait0();
            __syncthreads();
            buf ^= 1;
        }
    }

    const float inv0 = 1.f / l0, inv1 = 1.f / l1;
    const long row0 = (long)(b * 9216 + n0 + w * 16 + g) * 512 + h * 64;
    const long row1 = row0 + 8 * 512;
#pragma unroll
    for (int nd = 0; nd < 8; nd++) {
        const int c = nd * 8 + 2 * tg;
        *(float2*)(ctx + row0 + c) =
            make_float2(__uint_as_float(f2tf(O[nd][0] * inv0)),
                        __uint_as_float(f2tf(O[nd][1] * inv0)));
        *(float2*)(ctx + row1 + c) =
            make_float2(__uint_as_float(f2tf(O[nd][2] * inv1)),
                        __uint_as_float(f2tf(O[nd][3] * inv1)));
    }
}

// ---------------------------------------------------------------------------
// Launch pipeline
// ---------------------------------------------------------------------------
extern "C" void kernel_launch(void* const* d_in, const int* in_sizes, int n_in,
                              void* d_out, int out_size)
{
    (void)in_sizes; (void)n_in; (void)out_size;
    const float* x      = (const float*)d_in[0];
    const float* w_q    = (const float*)d_in[1];
    const float* b_q    = (const float*)d_in[2];
    const float* w_kv   = (const float*)d_in[3];
    const float* b_kv   = (const float*)d_in[4];
    const float* w_proj = (const float*)d_in[5];
    const float* b_proj = (const float*)d_in[6];
    const float* w_sr   = (const float*)d_in[7];
    const float* b_sr   = (const float*)d_in[8];
    const float* ln_g   = (const float*)d_in[9];
    const float* ln_b   = (const float*)d_in[10];
    const float* lAq    = (const float*)d_in[11];
    const float* lBq    = (const float*)d_in[12];
    const float* lAv    = (const float*)d_in[13];
    const float* lBv    = (const float*)d_in[14];

    float *q, *xtf, *xs, *t2p, *lv, *k, *v, *ctx, *t1p, *w2, *part;
    float *lAqp, *lAvp, *Bq2, *bq8, *wq2, *wkv2, *wp2, *lBv2;
    cudaGetSymbolAddress((void**)&q,     g_q);
    cudaGetSymbolAddress((void**)&xtf,   g_xtf);
    cudaGetSymbolAddress((void**)&xs,    g_xs);
    cudaGetSymbolAddress((void**)&t2p,   g_t2p);
    cudaGetSymbolAddress((void**)&lv,    g_lv);
    cudaGetSymbolAddress((void**)&k,     g_k);
    cudaGetSymbolAddress((void**)&v,     g_v);
    cudaGetSymbolAddress((void**)&ctx,   g_ctx);
    cudaGetSymbolAddress((void**)&t1p,   g_t1p);
    cudaGetSymbolAddress((void**)&w2,    g_w2);
    cudaGetSymbolAddress((void**)&part,  g_part);
    cudaGetSymbolAddress((void**)&lAqp,  g_lAqp);
    cudaGetSymbolAddress((void**)&lAvp,  g_lAvp);
    cudaGetSymbolAddress((void**)&Bq2,   g_Bq2);
    cudaGetSymbolAddress((void**)&bq8,   g_bq8);
    cudaGetSymbolAddress((void**)&wq2,   g_wq2);
    cudaGetSymbolAddress((void**)&wkv2,  g_wkv2);
    cudaGetSymbolAddress((void**)&wp2,   g_wp2);
    cudaGetSymbolAddress((void**)&lBv2,  g_lBv2);

    static cudaStream_t s2 = nullptr;
    static cudaEvent_t evF = nullptr, evX = nullptr, evJ = nullptr;
    if (!s2) {
        cudaStreamCreateWithFlags(&s2, cudaStreamNonBlocking);
        cudaEventCreateWithFlags(&evF, cudaEventDisableTiming);
        cudaEventCreateWithFlags(&evX, cudaEventDisableTiming);
        cudaEventCreateWithFlags(&evJ, cudaEventDisableTiming);
    }

    dim3 blk(256);
    const int smem128 = 2 * 256 * 36 * 4;   // 73728
    const int smem64  = 2 * 192 * 36 * 4;   // 55296
    cudaFuncSetAttribute(gemm_tf32<128, 0>,
                         cudaFuncAttributeMaxDynamicSharedMemorySize, smem128);
    cudaFuncSetAttribute(gemm_tf32<128, 1>,
                         cudaFuncAttributeMaxDynamicSharedMemorySize, smem128);
    cudaFuncSetAttribute(gemm_tf32<64, 0>,
                         cudaFuncAttributeMaxDynamicSharedMemorySize, smem64);
    cudaFuncSetAttribute(attn_flash,
                         cudaFuncAttributeMaxDynamicSharedMemorySize, ATTN_SMEM);

    // ---- prep on main (both chains depend on parts of it) ----
    prep_lora<<<128, blk>>>(lAq, lBq, lAv, b_q, lAqp, lAvp, Bq2, bq8);

    // ---- fork (side chain starts with x-independent work) ----
    cudaEventRecord(evF, 0);
    cudaStreamWaitEvent(s2, evF, 0);

    // main: convert x (+ weights for q path)
    cvt_tf32<<<9216, blk>>>(x, xtf);
    cudaEventRecord(evX, 0);
    cvt_tf32<<<256, blk>>>(w_q, wq2);
    cvt_tf32<<<256, blk>>>(w_proj, wp2);

    // side: conv-weight reorder + kv/lBv weight conversion, then wait for xtf
    reorder_w_kernel<<<16384, blk, 0, s2>>>(w_sr, w2);
    cvt_tf32<<<512, blk, 0, s2>>>(w_kv, wkv2);
    cvt_tf32<<<16, blk, 0, s2>>>(lBv, lBv2);
    cudaStreamWaitEvent(s2, evX, 0);

    // side chain: conv -> LN -> kv -> lora-v -> build k/v
    gemm_tf32<128, 1><<<dim3(4, 9, 8), blk, smem128, s2>>>(
        1152, 512, 8192, xtf, 512, w2, 8192, nullptr, 1.f, nullptr, 512,
        1024, part, nullptr, 0, nullptr, 0, 0, 0);
    reduce_ln<<<1152, 128, 0, s2>>>(part, b_sr, ln_g, ln_b, xs);
    gemm_tf32<128, 0><<<dim3(8, 9, 4), blk, smem128, s2>>>(
        1152, 1024, 512, xs, 512, wkv2, 512, nullptr, 1.f, nullptr, 1024,
        128, part, nullptr, 0, nullptr, 0, 0, 0);
    gemm_tf32<64, 0><<<dim3(1, 9, 1), blk, smem64, s2>>>(
        1152, 64, 512, xs, 512, lAvp, 512, nullptr, 1.f, t2p, 64,
        512, nullptr, nullptr, 0, nullptr, 0, 0, 1);
    gemm_tf32<128, 0><<<dim3(4, 9, 1), blk, smem128, s2>>>(
        1152, 512, 32, t2p, 64, lBv2, 32, nullptr, SCALING, lv, 512,
        32, nullptr, nullptr, 0, nullptr, 0, 0, 0);
    reduce_build_kv<<<2304, blk, 0, s2>>>(part, b_kv, lv, k, v);
    cudaEventRecord(evJ, s2);

    // main chain: t1p -> q (prescaled 0.125, tf32-rounded)
    gemm_tf32<64, 0><<<dim3(1, 144, 1), blk, smem64>>>(
        18432, 64, 512, xtf, 512, lAqp, 512, nullptr, 1.f, t1p, 64,
        512, nullptr, nullptr, 0, nullptr, 0, 0, 1);
    gemm_tf32<128, 0><<<dim3(4, 144, 1), blk, smem128>>>(
        18432, 512, 512, xtf, 512, wq2, 512, bq8, 0.125f, q, 512,
        512, nullptr, t1p, 64, Bq2, 32, 32, 1);

    // join
    cudaStreamWaitEvent(0, evJ, 0);

    attn_flash<<<dim3(72, 16), blk, ATTN_SMEM>>>(q, k, v, ctx);

    gemm_tf32<128, 0><<<dim3(4, 144, 1), blk, smem128>>>(
        18432, 512, 512, ctx, 512, wp2, 512, b_proj, 1.f, (float*)d_out,
        512, 512, nullptr, nullptr, 0, nullptr, 0, 0, 0);
}

// round 13
// speedup vs baseline: 5.5013x; 1.0134x over previous
#include <cuda_runtime.h>
#include <math.h>

// B=2, N=9216, C=512, HEAD=8, d=64, SR=4, H=W=96 -> Nkv=576, R=32
#define SCALING 0.125f

// ---------------------------------------------------------------------------
// Scratch (all GEMM operands stored tf32-rounded)
// ---------------------------------------------------------------------------
__device__ float g_q    [9437184];  // (B,N,C) prescaled*0.125, tf32
__device__ float g_xtf  [9437184];  // x tf32-rounded
__device__ float g_xs   [589824];   // (B*576,512) post-LN, tf32
__device__ float g_lv   [589824];
__device__ float g_k    [589824];   // (B*H,576,64) tf32
__device__ float g_v    [589824];   // (B*H,64,576) TRANSPOSED, tf32
__device__ float g_ctx  [9437184];  // tf32
__device__ float g_w2   [4194304];  // 512x8192 reordered conv weight, tf32
__device__ float g_part [4718592];  // split-K partials
__device__ float g_bq8  [512];      // b_q * 0.125
__device__ float g_weffq[262144];   // w_q + 0.125*lBq@lAq, tf32
__device__ float g_weffv[262144];   // 0.125*lBv@lAv, tf32
__device__ float g_wkv2 [524288];   // w_kv tf32
__device__ float g_wp2  [262144];   // w_proj tf32

// ---------------------------------------------------------------------------
// helpers
// ---------------------------------------------------------------------------
__device__ __forceinline__ unsigned f2tf(float x) {
    unsigned u;
    asm("cvt.rna.tf32.f32 %0, %1;" : "=r"(u) : "f"(x));
    return u;
}
__device__ __forceinline__ void mma8(float* c, const unsigned* a, const unsigned* b) {
    asm volatile(
        "mma.sync.aligned.m16n8k8.row.col.f32.tf32.tf32.f32 "
        "{%0,%1,%2,%3}, {%4,%5,%6,%7}, {%8,%9}, {%0,%1,%2,%3};"
        : "+f"(c[0]), "+f"(c[1]), "+f"(c[2]), "+f"(c[3])
        : "r"(a[0]), "r"(a[1]), "r"(a[2]), "r"(a[3]),
          "r"(b[0]), "r"(b[1]));
}
__device__ __forceinline__ void ldsm4(unsigned* r, unsigned addr) {
    asm volatile(
        "ldmatrix.sync.aligned.m8n8.x4.shared.b16 {%0,%1,%2,%3}, [%4];"
        : "=r"(r[0]), "=r"(r[1]), "=r"(r[2]), "=r"(r[3]) : "r"(addr));
}
__device__ __forceinline__ void cpa16(unsigned dst, const void* src) {
    asm volatile("cp.async.cg.shared.global [%0], [%1], 16;" :: "r"(dst), "l"(src));
}
__device__ __forceinline__ void cpa_commit() {
    asm volatile("cp.async.commit_group;" ::: "memory");
}
__device__ __forceinline__ void cpa_wait0() {
    asm volatile("cp.async.wait_group 0;" ::: "memory");
}

// elementwise tf32 round (n multiple of 1024)
__global__ void cvt_tf32(const float* __restrict__ in, float* __restrict__ out)
{
    const int i = (blockIdx.x * 256 + threadIdx.x) * 4;
    float4 v = *(const float4*)(in + i);
    uint4 u;
    u.x = f2tf(v.x); u.y = f2tf(v.y); u.z = f2tf(v.z); u.w = f2tf(v.w);
    *(uint4*)(out + i) = u;
}

// Weff[o][i] = tf32( (base? base[o][i]:0) + SCALING * sum_r lB[o][r]*lA[r][i] )
__global__ void make_weff(const float* __restrict__ wbase,
                          const float* __restrict__ lB,   // 512x32
                          const float* __restrict__ lA,   // 32x512
                          float* __restrict__ out)        // 512x512
{
    const int i = blockIdx.x * 256 + threadIdx.x;   // < 262144
    const int col = i & 511, row = i >> 9;
    float s = 0.f;
#pragma unroll 8
    for (int r = 0; r < 32; r++)
        s += lB[row * 32 + r] * lA[r * 512 + col];
    s *= SCALING;
    if (wbase) s += wbase[i];
    out[i] = __uint_as_float(f2tf(s));
}

__global__ void prep_bq(const float* __restrict__ bq, float* __restrict__ bq8)
{
    const int i = blockIdx.x * 256 + threadIdx.x;
    if (i < 512) bq8[i] = bq[i] * 0.125f;
}

// ---------------------------------------------------------------------------
// tf32 GEMM, BK=32, 2-stage cp.async pipeline, ldmatrix frags.
// All operands pre-tf32.  C = scale*(A@B^T) (+bias)  [round_out]
// BM=128, BN in {64,128}; 256 threads; warps 4(M)x2(N).
// REQUIRES kchunk%32==0.  CONV=1: A gathered with SR-conv im2col mapping.
// dyn smem: 2*(128+BN)*36*4 bytes.  Pitch 36 words (36 % 32 == 4).
// ---------------------------------------------------------------------------
template <int BN, int CONV>
__global__ void __launch_bounds__(256, 2)
gemm_tf32(int M, int N, int K,
          const float* __restrict__ A, int lda,
          const float* __restrict__ B, int ldb,
          const float* __restrict__ bias,
          float scale,
          float* __restrict__ C, int ldc,
          int kchunk, float* __restrict__ part,
          int round_out)
{
    constexpr int NI = BN / 16;
    constexpr int P  = 36;
    extern __shared__ unsigned gsm[];
    unsigned* AsU = gsm;                   // 2 x 128 x P
    unsigned* BsU = gsm + 2 * 128 * P;     // 2 x BN x P

    const int t    = threadIdx.x;
    const int lane = t & 31, w = t >> 5;
    const int g  = lane >> 2, tg = lane & 3;
    const int wm = w >> 1,  wn = w & 1;
    const long m0 = (long)blockIdx.y * 128;
    const int  n0 = blockIdx.x * BN;
    const int  kb = blockIdx.z * kchunk;

    const int lrow = t >> 3;
    const int lko  = (t & 7) * 4;

    const int tS = lane >> 3;
    const unsigned asB = (unsigned)__cvta_generic_to_shared(AsU);
    const unsigned bsB = (unsigned)__cvta_generic_to_shared(BsU);
    const unsigned aOff = ((wm * 32 + (tS & 1) * 8 + (lane & 7)) * P
                           + (tS >> 1) * 4) * 4;
    const unsigned bOff = ((wn * (BN / 2) + (tS >> 1) * 8 + (lane & 7)) * P
                           + (tS & 1) * 4) * 4;

    float acc[2][NI][4];
#pragma unroll
    for (int mi = 0; mi < 2; mi++)
#pragma unroll
        for (int ni = 0; ni < NI; ni++)
#pragma unroll
            for (int c = 0; c < 4; c++) acc[mi][ni][c] = 0.f;

    long cr[4];
    if (CONV) {
#pragma unroll
        for (int i = 0; i < 4; i++) {
            int m = (int)m0 + i * 32 + lrow;
            int b = m / 576, p = m % 576, py = p / 24, px = p % 24;
            cr[i] = (long)b * 9216 + (py * 4) * 96 + px * 4;
        }
    }

    const int nIter = kchunk >> 5;

    auto issueTile = [&](int idx, int s) {
        const unsigned aS = asB + s * (128 * P * 4);
        const unsigned bS = bsB + s * (BN * P * 4);
        const int k0 = kb + (idx << 5);
        if (CONV) {
            const int tap = k0 >> 9;
            const int ci  = (k0 & 511) + lko;
            const long toff = (long)((tap >> 2) * 96 + (tap & 3)) * 512 + ci;
#pragma unroll
            for (int i = 0; i < 4; i++)
                cpa16(aS + ((i * 32 + lrow) * P + lko) * 4,
                      A + cr[i] * 512 + toff);
        } else {
#pragma unroll
            for (int i = 0; i < 4; i++)
                cpa16(aS + ((i * 32 + lrow) * P + lko) * 4,
                      A + (m0 + i * 32 + lrow) * lda + k0 + lko);
        }
#pragma unroll
        for (int i = 0; i < BN / 32; i++)
            cpa16(bS + ((i * 32 + lrow) * P + lko) * 4,
                  B + (long)(n0 + i * 32 + lrow) * ldb + k0 + lko);
        cpa_commit();
    };

    issueTile(0, 0);

    for (int it = 0; it < nIter; it++) {
        cpa_wait0();
        __syncthreads();
        if (it + 1 < nIter) issueTile(it + 1, (it + 1) & 1);

        const int s = it & 1;
        const unsigned aB = asB + s * (128 * P * 4) + aOff;
        const unsigned bB = bsB + s * (BN * P * 4) + bOff;
#pragma unroll
        for (int kk = 0; kk < 32; kk += 8) {
            unsigned af[2][4], bf[NI][2];
#pragma unroll
            for (int mi = 0; mi < 2; mi++)
                ldsm4(af[mi], aB + mi * (16 * P * 4) + kk * 4);
#pragma unroll
            for (int p = 0; p < NI / 2; p++) {
                unsigned q4[4];
                ldsm4(q4, bB + p * (16 * P * 4) + kk * 4);
                bf[2 * p][0] = q4[0]; bf[2 * p][1] = q4[1];
                bf[2 * p + 1][0] = q4[2]; bf[2 * p + 1][1] = q4[3];
            }
#pragma unroll
            for (int mi = 0; mi < 2; mi++)
#pragma unroll
                for (int ni = 0; ni < NI; ni++)
                    mma8(acc[mi][ni], af[mi], bf[ni]);
        }
    }

    if (gridDim.z == 1) {
#pragma unroll
        for (int mi = 0; mi < 2; mi++) {
            const long r0 = m0 + wm * 32 + mi * 16 + g;
            const long r1 = r0 + 8;
#pragma unroll
            for (int ni = 0; ni < NI; ni++) {
                const int c = n0 + wn * (BN / 2) + ni * 8 + 2 * tg;
                float v00 = scale * acc[mi][ni][0];
                float v01 = scale * acc[mi][ni][1];
                float v10 = scale * acc[mi][ni][2];
                float v11 = scale * acc[mi][ni][3];
                if (bias) {
                    float b0 = bias[c], b1 = bias[c + 1];
                    v00 += b0; v01 += b1; v10 += b0; v11 += b1;
                }
                if (round_out) {
                    v00 = __uint_as_float(f2tf(v00));
                    v01 = __uint_as_float(f2tf(v01));
                    v10 = __uint_as_float(f2tf(v10));
                    v11 = __uint_as_float(f2tf(v11));
                }
                *(float2*)(C + r0 * ldc + c) = make_float2(v00, v01);
                *(float2*)(C + r1 * ldc + c) = make_float2(v10, v11);
            }
        }
    } else {
        float* Pp = part + (long)blockIdx.z * M * ldc;
#pragma unroll
        for (int mi = 0; mi < 2; mi++) {
            const long r0 = m0 + wm * 32 + mi * 16 + g;
            const long r1 = r0 + 8;
#pragma unroll
            for (int ni = 0; ni < NI; ni++) {
                const int c = n0 + wn * (BN / 2) + ni * 8 + 2 * tg;
                *(float2*)(Pp + r0 * ldc + c) =
                    make_float2(acc[mi][ni][0], acc[mi][ni][1]);
                *(float2*)(Pp + r1 * ldc + c) =
                    make_float2(acc[mi][ni][2], acc[mi][ni][3]);
            }
        }
    }
}

// ---------------------------------------------------------------------------
// Fused conv split-K reduce + bias + LayerNorm -> xs (tf32-rounded).
// ---------------------------------------------------------------------------
__global__ void reduce_ln(const float* __restrict__ part,
                          const float* __restrict__ bias,
                          const float* __restrict__ gam,
                          const float* __restrict__ bet,
                          float* __restrict__ out)
{
    const int row = blockIdx.x;
    const int t   = threadIdx.x;
    float v[4];
#pragma unroll
    for (int j = 0; j < 4; j++) {
        const int col = t + j * 128;
        float s = bias[col];
        const long off = (long)row * 512 + col;
#pragma unroll
        for (int z = 0; z < 8; z++) s += part[z * 589824 + off];
        v[j] = s;
    }
    float s  = v[0] + v[1] + v[2] + v[3];
    float s2 = v[0]*v[0] + v[1]*v[1] + v[2]*v[2] + v[3]*v[3];
#pragma unroll
    for (int o = 16; o > 0; o >>= 1) {
        s  += __shfl_xor_sync(0xffffffffu, s,  o);
        s2 += __shfl_xor_sync(0xffffffffu, s2, o);
    }
    __shared__ float ss[4], ss2[4];
    if ((t & 31) == 0) { ss[t >> 5] = s; ss2[t >> 5] = s2; }
    __syncthreads();
    s  = ss[0]  + ss[1]  + ss[2]  + ss[3];
    s2 = ss2[0] + ss2[1] + ss2[2] + ss2[3];
    const float mean = s * (1.f / 512.f);
    const float var  = s2 * (1.f / 512.f) - mean * mean;
    const float inv  = rsqrtf(var + 1e-5f);
    float* o = out + (long)row * 512;
#pragma unroll
    for (int j = 0; j < 4; j++) {
        const int col = t + j * 128;
        o[col] = __uint_as_float(f2tf((v[j] - mean) * inv * gam[col] + bet[col]));
    }
}

// ---------------------------------------------------------------------------
// Fused kv split-K reduce + bias + head split + LoRA-v fixup.
// k: [bh][m][dd] tf32.  v: [bh][dd][m] TRANSPOSED, tf32.
// ---------------------------------------------------------------------------
__global__ void reduce_build_kv(const float* __restrict__ part,
                                const float* __restrict__ bias,
                                const float* __restrict__ lv,
                                float* __restrict__ k, float* __restrict__ vt)
{
    const int idx = blockIdx.x * 256 + threadIdx.x;
    const int dd = idx & 63;
    const int m  = (idx >> 6) % 576;
    const int bh = idx / 36864;
    const int h  = bh & 7, b = bh >> 3;
    const int ck = h * 64 + dd;
    const long mrow = (long)(b * 576 + m) * 1024;
    float sk = bias[ck], sv = bias[512 + ck];
#pragma unroll
    for (int z = 0; z < 4; z++) {
        sk += part[z * 1179648 + mrow + ck];
        sv += part[z * 1179648 + mrow + 512 + ck];
    }
    k[idx] = __uint_as_float(f2tf(sk));
    float vv = sv + lv[(long)b * 294912 + h * 36864 + m * 64 + dd];
    vt[(long)bh * 36864 + dd * 576 + m] = __uint_as_float(f2tf(vv));
}

// w2[co][(i*4+j)*512 + ci] = tf32(w_sr[co][ci][i][j])
__global__ void reorder_w_kernel(const float* __restrict__ w,
                                 float* __restrict__ w2)
{
    const int tid = blockIdx.x * 256 + threadIdx.x;
    const int ci = tid & 511;
    const int s  = (tid >> 9) & 15;
    const int co = tid >> 13;
    w2[tid] = __uint_as_float(f2tf(w[(long)co * 8192 + ci * 16 + s]));
}

// ---------------------------------------------------------------------------
// FA2-style tf32 attention, cp.async + double-buffered K/V.
// Softmax exps are NOT pre-rounded (mma rounds the A operand internally;
// the l-sum uses unrounded e -> ~1e-5 relative shift, negligible).
// ---------------------------------------------------------------------------
#define TPw 68
#define ATTN_SMEM (TPw * 384 * 4)

__global__ void __launch_bounds__(256, 2)
attn_flash(const float* __restrict__ qb,
           const float* __restrict__ kb,
           const float* __restrict__ vtb,
           float* __restrict__ ctx)
{
    extern __shared__ float sm[];
    float*    Sw = sm;
    unsigned* KV = (unsigned*)(sm + 128 * TPw);

    const int t    = threadIdx.x;
    const int lane = t & 31, w = t >> 5;
    const int g  = lane >> 2, tg = lane & 3;
    const int bh = blockIdx.y, b = bh >> 3, h = bh & 7;
    const int n0 = blockIdx.x * 128;

    const int tS = lane >> 3;
    const unsigned swB = (unsigned)__cvta_generic_to_shared(Sw);
    const unsigned kvB = (unsigned)__cvta_generic_to_shared(KV);
    const unsigned aOff = ((w * 16 + (tS & 1) * 8 + (lane & 7)) * TPw
                           + (tS >> 1) * 4) * 4;
    const unsigned bOff = (((tS >> 1) * 8 + (lane & 7)) * TPw
                           + (tS & 1) * 4) * 4;
    constexpr unsigned BUFB = 128 * TPw * 4;
    constexpr unsigned VOFF = 64 * TPw * 4;

    auto loadQ = [&]() {
#pragma unroll
        for (int i = 0; i < 8; i++) {
            int c = i * 256 + t;
            int row = c >> 4, off = (c & 15) * 4;
            cpa16(swB + (row * TPw + off) * 4,
                  qb + (long)(b * 9216 + n0 + row) * 512 + h * 64 + off);
        }
    };
    auto loadKV = [&](int ch, int buf) {
#pragma unroll
        for (int i = 0; i < 4; i++) {
            int c = i * 256 + t;
            int row = c >> 4, off = (c & 15) * 4;
            cpa16(kvB + buf * BUFB + (row * TPw + off) * 4,
                  kb + (long)(bh * 576 + ch * 64 + row) * 64 + off);
            cpa16(kvB + buf * BUFB + VOFF + (row * TPw + off) * 4,
                  vtb + (long)bh * 36864 + row * 576 + ch * 64 + off);
        }
    };

    loadQ();
    loadKV(0, 0);
    cpa_commit();
    cpa_wait0();
    __syncthreads();

    unsigned Qf[8][4];
#pragma unroll
    for (int kk = 0; kk < 8; kk++)
        ldsm4(Qf[kk], swB + aOff + kk * 32);

    float O[8][4];
#pragma unroll
    for (int nd = 0; nd < 8; nd++)
#pragma unroll
        for (int c = 0; c < 4; c++) O[nd][c] = 0.f;
    float m0 = -1e30f, l0 = 0.f, m1 = -1e30f, l1 = 0.f;

    int buf = 0;
    for (int ch = 0; ch < 9; ch++) {
        const bool more = (ch + 1 < 9);
        if (more) { loadKV(ch + 1, buf ^ 1); cpa_commit(); }

        const unsigned ksB = kvB + buf * BUFB + bOff;
        const unsigned vsB = kvB + buf * BUFB + VOFF + bOff;

        float acc[8][4];
#pragma unroll
        for (int ni = 0; ni < 8; ni++)
#pragma unroll
            for (int c = 0; c < 4; c++) acc[ni][c] = 0.f;
#pragma unroll
        for (int kk = 0; kk < 8; kk++) {
            unsigned bf[8][2];
#pragma unroll
            for (int p = 0; p < 4; p++) {
                unsigned q4[4];
                ldsm4(q4, ksB + p * (16 * TPw * 4) + kk * 32);
                bf[2 * p][0] = q4[0]; bf[2 * p][1] = q4[1];
                bf[2 * p + 1][0] = q4[2]; bf[2 * p + 1][1] = q4[3];
            }
#pragma unroll
            for (int ni = 0; ni < 8; ni++)
                mma8(acc[ni], Qf[kk], bf[ni]);
        }

        float cm0 = -1e30f, cm1 = -1e30f;
#pragma unroll
        for (int ni = 0; ni < 8; ni++) {
            cm0 = fmaxf(cm0, fmaxf(acc[ni][0], acc[ni][1]));
            cm1 = fmaxf(cm1, fmaxf(acc[ni][2], acc[ni][3]));
        }
        cm0 = fmaxf(cm0, __shfl_xor_sync(0xffffffffu, cm0, 1));
        cm0 = fmaxf(cm0, __shfl_xor_sync(0xffffffffu, cm0, 2));
        cm1 = fmaxf(cm1, __shfl_xor_sync(0xffffffffu, cm1, 1));
        cm1 = fmaxf(cm1, __shfl_xor_sync(0xffffffffu, cm1, 2));
        const float nm0 = fmaxf(m0, cm0), nm1 = fmaxf(m1, cm1);
        const float al0 = __expf(m0 - nm0), al1 = __expf(m1 - nm1);
        float sum0 = 0.f, sum1 = 0.f;
#pragma unroll
        for (int ni = 0; ni < 8; ni++) {
            float e0 = __expf(acc[ni][0] - nm0);
            float e1 = __expf(acc[ni][1] - nm0);
            float e2 = __expf(acc[ni][2] - nm1);
            float e3 = __expf(acc[ni][3] - nm1);
            acc[ni][0] = e0; acc[ni][1] = e1; acc[ni][2] = e2; acc[ni][3] = e3;
            sum0 += e0 + e1; sum1 += e2 + e3;
        }
        sum0 += __shfl_xor_sync(0xffffffffu, sum0, 1);
        sum0 += __shfl_xor_sync(0xffffffffu, sum0, 2);
        sum1 += __shfl_xor_sync(0xffffffffu, sum1, 1);
        sum1 += __shfl_xor_sync(0xffffffffu, sum1, 2);
        l0 = l0 * al0 + sum0; l1 = l1 * al1 + sum1;
        m0 = nm0; m1 = nm1;
#pragma unroll
        for (int nd = 0; nd < 8; nd++) {
            O[nd][0] *= al0; O[nd][1] *= al0;
            O[nd][2] *= al1; O[nd][3] *= al1;
        }

        float* SwW = Sw + w * 16 * TPw;
#pragma unroll
        for (int ni = 0; ni < 8; ni++) {
            *(float2*)&SwW[g * TPw + ni * 8 + 2 * tg] =
                make_float2(acc[ni][0], acc[ni][1]);
            *(float2*)&SwW[(g + 8) * TPw + ni * 8 + 2 * tg] =
                make_float2(acc[ni][2], acc[ni][3]);
        }
        __syncwarp();

#pragma unroll
        for (int kk = 0; kk < 8; kk++) {
            unsigned pa[4];
            ldsm4(pa, swB + aOff + kk * 32);
            unsigned bf[8][2];
#pragma unroll
            for (int p = 0; p < 4; p++) {
                unsigned q4[4];
                ldsm4(q4, vsB + p * (16 * TPw * 4) + kk * 32);
                bf[2 * p][0] = q4[0]; bf[2 * p][1] = q4[1];
                bf[2 * p + 1][0] = q4[2]; bf[2 * p + 1][1] = q4[3];
            }
#pragma unroll
            for (int nd = 0; nd < 8; nd++)
                mma8(O[nd], pa, bf[nd]);
        }

        if (more) {
            cpa_wait0();
            __syncthreads();
            buf ^= 1;
        }
    }

    const float inv0 = 1.f / l0, inv1 = 1.f / l1;
    const long row0 = (long)(b * 9216 + n0 + w * 16 + g) * 512 + h * 64;
    const long row1 = row0 + 8 * 512;
#pragma unroll
    for (int nd = 0; nd < 8; nd++) {
        const int c = nd * 8 + 2 * tg;
        *(float2*)(ctx + row0 + c) =
            make_float2(__uint_as_float(f2tf(O[nd][0] * inv0)),
                        __uint_as_float(f2tf(O[nd][1] * inv0)));
        *(float2*)(ctx + row1 + c) =
            make_float2(__uint_as_float(f2tf(O[nd][2] * inv1)),
                        __uint_as_float(f2tf(O[nd][3] * inv1)));
    }
}

// ---------------------------------------------------------------------------
// Launch pipeline
// ---------------------------------------------------------------------------
extern "C" void kernel_launch(void* const* d_in, const int* in_sizes, int n_in,
                              void* d_out, int out_size)
{
    (void)in_sizes; (void)n_in; (void)out_size;
    const float* x      = (const float*)d_in[0];
    const float* w_q    = (const float*)d_in[1];
    const float* b_q    = (const float*)d_in[2];
    const float* w_kv   = (const float*)d_in[3];
    const float* b_kv   = (const float*)d_in[4];
    const float* w_proj = (const float*)d_in[5];
    const float* b_proj = (const float*)d_in[6];
    const float* w_sr   = (const float*)d_in[7];
    const float* b_sr   = (const float*)d_in[8];
    const float* ln_g   = (const float*)d_in[9];
    const float* ln_b   = (const float*)d_in[10];
    const float* lAq    = (const float*)d_in[11];
    const float* lBq    = (const float*)d_in[12];
    const float* lAv    = (const float*)d_in[13];
    const float* lBv    = (const float*)d_in[14];

    float *q, *xtf, *xs, *lv, *k, *v, *ctx, *w2, *part;
    float *bq8, *weffq, *weffv, *wkv2, *wp2;
    cudaGetSymbolAddress((void**)&q,     g_q);
    cudaGetSymbolAddress((void**)&xtf,   g_xtf);
    cudaGetSymbolAddress((void**)&xs,    g_xs);
    cudaGetSymbolAddress((void**)&lv,    g_lv);
    cudaGetSymbolAddress((void**)&k,     g_k);
    cudaGetSymbolAddress((void**)&v,     g_v);
    cudaGetSymbolAddress((void**)&ctx,   g_ctx);
    cudaGetSymbolAddress((void**)&w2,    g_w2);
    cudaGetSymbolAddress((void**)&part,  g_part);
    cudaGetSymbolAddress((void**)&bq8,   g_bq8);
    cudaGetSymbolAddress((void**)&weffq, g_weffq);
    cudaGetSymbolAddress((void**)&weffv, g_weffv);
    cudaGetSymbolAddress((void**)&wkv2,  g_wkv2);
    cudaGetSymbolAddress((void**)&wp2,   g_wp2);

    static cudaStream_t s2 = nullptr;
    static cudaEvent_t evF = nullptr, evX = nullptr, evJ = nullptr;
    if (!s2) {
        cudaStreamCreateWithFlags(&s2, cudaStreamNonBlocking);
        cudaEventCreateWithFlags(&evF, cudaEventDisableTiming);
        cudaEventCreateWithFlags(&evX, cudaEventDisableTiming);
        cudaEventCreateWithFlags(&evJ, cudaEventDisableTiming);
    }

    dim3 blk(256);
    const int smem128 = 2 * 256 * 36 * 4;   // 73728
    cudaFuncSetAttribute(gemm_tf32<128, 0>,
                         cudaFuncAttributeMaxDynamicSharedMemorySize, smem128);
    cudaFuncSetAttribute(gemm_tf32<128, 1>,
                         cudaFuncAttributeMaxDynamicSharedMemorySize, smem128);
    cudaFuncSetAttribute(attn_flash,
                         cudaFuncAttributeMaxDynamicSharedMemorySize, ATTN_SMEM);

    // ---- fork ----
    cudaEventRecord(evF, 0);
    cudaStreamWaitEvent(s2, evF, 0);

    // main: q-path weights + x conversion
    prep_bq<<<2, blk>>>(b_q, bq8);
    make_weff<<<1024, blk>>>(w_q, lBq, lAq, weffq);
    cvt_tf32<<<9216, blk>>>(x, xtf);
    cudaEventRecord(evX, 0);
    cvt_tf32<<<256, blk>>>(w_proj, wp2);

    // side: conv-weight reorder + kv weight + v-lora weight, then wait for xtf
    reorder_w_kernel<<<16384, blk, 0, s2>>>(w_sr, w2);
    cvt_tf32<<<512, blk, 0, s2>>>(w_kv, wkv2);
    make_weff<<<1024, blk, 0, s2>>>(nullptr, lBv, lAv, weffv);
    cudaStreamWaitEvent(s2, evX, 0);

    // side chain: conv -> LN -> kv -> lv -> build k/v
    gemm_tf32<128, 1><<<dim3(4, 9, 8), blk, smem128, s2>>>(
        1152, 512, 8192, xtf, 512, w2, 8192, nullptr, 1.f, nullptr, 512,
        1024, part, 0);
    reduce_ln<<<1152, 128, 0, s2>>>(part, b_sr, ln_g, ln_b, xs);
    gemm_tf32<128, 0><<<dim3(8, 9, 4), blk, smem128, s2>>>(
        1152, 1024, 512, xs, 512, wkv2, 512, nullptr, 1.f, nullptr, 1024,
        128, part, 0);
    gemm_tf32<128, 0><<<dim3(4, 9, 1), blk, smem128, s2>>>(
        1152, 512, 512, xs, 512, weffv, 512, nullptr, 1.f, lv, 512,
        512, nullptr, 0);
    reduce_build_kv<<<2304, blk, 0, s2>>>(part, b_kv, lv, k, v);
    cudaEventRecord(evJ, s2);

    // main chain: q = (X @ Weff_q^T) * 0.125 + bq8, tf32-rounded
    gemm_tf32<128, 0><<<dim3(4, 144, 1), blk, smem128>>>(
        18432, 512, 512, xtf, 512, weffq, 512, bq8, 0.125f, q, 512,
        512, nullptr, 1);

    // join
    cudaStreamWaitEvent(0, evJ, 0);

    attn_flash<<<dim3(72, 16), blk, ATTN_SMEM>>>(q, k, v, ctx);

    gemm_tf32<128, 0><<<dim3(4, 144, 1), blk, smem128>>>(
        18432, 512, 512, ctx, 512, wp2, 512, b_proj, 1.f, (float*)d_out,
        512, 512, nullptr, 0);
}